// round 1
// baseline (speedup 1.0000x reference)
#include <cuda_runtime.h>
#include <math_constants.h>

#define BB 4
#define CC 256
#define AA 4096

// ---- device scratch (no allocs allowed) ----
__device__ float g_S[(long)BB * AA * AA];          // 256 MB: S[b][a][n]
__device__ float g_VbW[(long)BB * CC * AA];        // 16 MB : (W^T Vb)[b][c][n]
__device__ float g_rowmax[BB * AA];
__device__ float g_rowsum[BB * AA];
__device__ float g_colmax[BB * AA];
__device__ float g_colsum[BB * AA];
__device__ float g_cpm[BB * 8 * AA];               // column-stat partials
__device__ float g_cps[BB * 8 * AA];

// ============================================================
// Generic 128x128 fp32 GEMM body, 256 threads, 8x8 micro-tiles.
// AKM:  A stored [K x M] (k-major)   else [M x K]
// BKM:  B stored [K x N] (k-major)   else [N x K]
// SMAX: B element -> exp(B - mx[n]); epilogue: * 1/sm[n]
// ============================================================
template<bool AKM, bool BKM, bool SMAX>
__device__ __forceinline__ void gemm_body(
    const float* __restrict__ A, int lda,
    const float* __restrict__ B, int ldb,
    float* __restrict__ C, int ldc,
    int K,
    const float* __restrict__ mx, const float* __restrict__ sm)
{
    __shared__ __align__(16) float As[16][132];
    __shared__ __align__(16) float Bs[16][132];
    __shared__ float mxs[128];

    const int m0 = blockIdx.y * 128;
    const int n0 = blockIdx.x * 128;
    const int tid = threadIdx.x;

    if (SMAX) {
        if (tid < 128) mxs[tid] = mx[n0 + tid];
        __syncthreads();
    }

    float acc[8][8];
#pragma unroll
    for (int i = 0; i < 8; i++)
#pragma unroll
        for (int j = 0; j < 8; j++) acc[i][j] = 0.f;

    const int tx = tid & 15, ty = tid >> 4;

    for (int k0 = 0; k0 < K; k0 += 16) {
        // ---- load A tile ----
#pragma unroll
        for (int r = 0; r < 8; r++) {
            int i = tid + r * 256;
            if (AKM) {
                int k = i >> 7, m = i & 127;
                As[k][m] = A[(long)(k0 + k) * lda + (m0 + m)];
            } else {
                int m = i >> 4, k = i & 15;
                As[k][m] = A[(long)(m0 + m) * lda + (k0 + k)];
            }
        }
        // ---- load B tile (optionally exponentiated) ----
#pragma unroll
        for (int r = 0; r < 8; r++) {
            int i = tid + r * 256;
            int k, n;
            float v;
            if (BKM) {
                k = i >> 7; n = i & 127;
                v = B[(long)(k0 + k) * ldb + (n0 + n)];
            } else {
                n = i >> 4; k = i & 15;
                v = B[(long)(n0 + n) * ldb + (k0 + k)];
            }
            if (SMAX) v = __expf(v - mxs[n]);
            Bs[k][n] = v;
        }
        __syncthreads();
#pragma unroll
        for (int kk = 0; kk < 16; kk++) {
            float4 a0 = *(const float4*)&As[kk][ty * 8];
            float4 a1 = *(const float4*)&As[kk][ty * 8 + 4];
            float4 b0 = *(const float4*)&Bs[kk][tx * 8];
            float4 b1 = *(const float4*)&Bs[kk][tx * 8 + 4];
            float a8[8] = {a0.x,a0.y,a0.z,a0.w,a1.x,a1.y,a1.z,a1.w};
            float b8[8] = {b0.x,b0.y,b0.z,b0.w,b1.x,b1.y,b1.z,b1.w};
#pragma unroll
            for (int i = 0; i < 8; i++)
#pragma unroll
                for (int j = 0; j < 8; j++)
                    acc[i][j] = fmaf(a8[i], b8[j], acc[i][j]);
        }
        __syncthreads();
    }

    float inv[8];
#pragma unroll
    for (int j = 0; j < 8; j++)
        inv[j] = SMAX ? 1.f / sm[n0 + tx * 8 + j] : 1.f;

#pragma unroll
    for (int i = 0; i < 8; i++)
#pragma unroll
        for (int j = 0; j < 8; j++)
            C[(long)(m0 + ty * 8 + i) * ldc + (n0 + tx * 8 + j)] = acc[i][j] * inv[j];
}

// ---- GEMM 1: VbW[b][c][n] = sum_d W[d][c] * Vb[b][d][n]   (M=256,N=4096,K=256)
__global__ void __launch_bounds__(256) k_gemm_vbw(const float* __restrict__ Wl,
                                                  const float* __restrict__ Vb) {
    long b = blockIdx.z;
    gemm_body<true, true, false>(Wl, CC,
                                 Vb + b * CC * AA, AA,
                                 g_VbW + b * CC * AA, AA,
                                 CC, nullptr, nullptr);
}

// ---- GEMM 2: S[b][a][n] = sum_c Va[b][c][a] * VbW[b][c][n]  (M=N=4096,K=256)
__global__ void __launch_bounds__(256) k_gemm_s(const float* __restrict__ Va) {
    long b = blockIdx.z;
    gemm_body<true, true, false>(Va + b * CC * AA, AA,
                                 g_VbW + b * CC * AA, AA,
                                 g_S + b * (long)AA * AA, AA,
                                 CC, nullptr, nullptr);
}

// ---- GEMM 3: Va_att[b][c][n] = sum_a Vb[b][c][a] * exp(S[b][a][n]-cm[b][n])/cs[b][n]
__global__ void __launch_bounds__(256) k_gemm_va_att(const float* __restrict__ Vb,
                                                     float* __restrict__ out) {
    long b = blockIdx.z;
    gemm_body<false, true, true>(Vb + b * CC * AA, AA,
                                 g_S + b * (long)AA * AA, AA,
                                 out + b * (2L * CC * AA), AA,
                                 AA, g_colmax + b * AA, g_colsum + b * AA);
}

// ---- GEMM 4: Vb_att[b][c][n] = sum_a Va[b][c][a] * exp(S[b][n][a]-rm[b][n])/rs[b][n]
__global__ void __launch_bounds__(256) k_gemm_vb_att(const float* __restrict__ Va,
                                                     float* __restrict__ out) {
    long b = blockIdx.z;
    gemm_body<false, false, true>(Va + b * CC * AA, AA,
                                  g_S + b * (long)AA * AA, AA,
                                  out + (long)(BB + b) * (2L * CC * AA), AA,
                                  AA, g_rowmax + b * AA, g_rowsum + b * AA);
}

// ---- row stats: max/sum-exp over n for each (b,a). one warp per row.
__global__ void __launch_bounds__(256) k_row_stats() {
    int row = blockIdx.x * 8 + (threadIdx.x >> 5);   // row in [0, BB*AA)
    int lane = threadIdx.x & 31;
    const float* p = g_S + (long)row * AA;
    float m = -CUDART_INF_F;
    for (int i = lane; i < AA; i += 32) m = fmaxf(m, p[i]);
#pragma unroll
    for (int o = 16; o; o >>= 1) m = fmaxf(m, __shfl_xor_sync(0xffffffffu, m, o));
    float s = 0.f;
    for (int i = lane; i < AA; i += 32) s += __expf(p[i] - m);
#pragma unroll
    for (int o = 16; o; o >>= 1) s += __shfl_xor_sync(0xffffffffu, s, o);
    if (lane == 0) { g_rowmax[row] = m; g_rowsum[row] = s; }
}

// ---- column stats, partial over 512-row chunks. grid (AA/128, 8, BB), 128 thr.
__global__ void __launch_bounds__(128) k_col_stats_part() {
    int b = blockIdx.z, ch = blockIdx.y;
    int n = blockIdx.x * 128 + threadIdx.x;
    const float* p = g_S + ((long)b * AA + ch * 512) * AA + n;
    float m = -CUDART_INF_F, s = 0.f;
    for (int i = 0; i < 512; i++) {
        float x = p[(long)i * AA];
        if (x > m) { s *= __expf(m - x); m = x; }
        s += __expf(x - m);
    }
    g_cpm[(b * 8 + ch) * AA + n] = m;
    g_cps[(b * 8 + ch) * AA + n] = s;
}

// ---- combine 8 column partials
__global__ void __launch_bounds__(256) k_col_stats_combine() {
    int idx = blockIdx.x * 256 + threadIdx.x;   // idx in [0, BB*AA)
    int b = idx / AA, n = idx % AA;
    float m = -CUDART_INF_F;
#pragma unroll
    for (int ch = 0; ch < 8; ch++) m = fmaxf(m, g_cpm[(b * 8 + ch) * AA + n]);
    float s = 0.f;
#pragma unroll
    for (int ch = 0; ch < 8; ch++)
        s += g_cps[(b * 8 + ch) * AA + n] * __expf(g_cpm[(b * 8 + ch) * AA + n] - m);
    g_colmax[idx] = m;
    g_colsum[idx] = s;
}

// ---- gate + in-place scale + concat-copy. grid (AA/256, BB, 2), 256 thr.
__global__ void __launch_bounds__(256) k_gate_concat(const float* __restrict__ Wg,
                                                     const float* __restrict__ Va,
                                                     const float* __restrict__ Vb,
                                                     float* __restrict__ out) {
    int side = blockIdx.z;
    int b = blockIdx.y;
    int n = blockIdx.x * 256 + threadIdx.x;
    const float* orig = (side ? Vb : Va) + (long)b * CC * AA + n;
    float* att = out + ((long)(side * BB + b)) * (2L * CC * AA) + n;
    float dot = 0.f;
#pragma unroll 4
    for (int c = 0; c < CC; c++) dot = fmaf(att[(long)c * AA], Wg[c], dot);
    float mask = 1.f / (1.f + __expf(-dot));
#pragma unroll 4
    for (int c = 0; c < CC; c++) {
        att[(long)c * AA] *= mask;
        att[(long)(c + CC) * AA] = orig[(long)c * AA];
    }
}

// ---- tail fill (for a possible trailing input_size element in d_out)
__global__ void k_tail(float* __restrict__ out, long start, long total,
                       const int* __restrict__ isz) {
    long i = start + blockIdx.x * 256L + threadIdx.x;
    if (i < total) out[i] = (float)(*isz);
}

extern "C" void kernel_launch(void* const* d_in, const int* in_sizes, int n_in,
                              void* d_out, int out_size) {
    const float* Va = (const float*)d_in[0];
    const float* Vb = (const float*)d_in[1];
    const float* Wl = (const float*)d_in[2];
    const float* Wg = (const float*)d_in[3];
    const int* isz = (const int*)d_in[4];
    float* out = (float*)d_out;

    // 1) VbW = W^T @ Vb
    k_gemm_vbw<<<dim3(AA / 128, CC / 128, BB), 256>>>(Wl, Vb);
    // 2) S = Va^T @ VbW
    k_gemm_s<<<dim3(AA / 128, AA / 128, BB), 256>>>(Va);
    // 3) softmax stats
    k_row_stats<<<BB * AA / 8, 256>>>();
    k_col_stats_part<<<dim3(AA / 128, 8, BB), 128>>>();
    k_col_stats_combine<<<BB * AA / 256, 256>>>();
    // 4) attention GEMMs straight into d_out
    k_gemm_va_att<<<dim3(AA / 128, CC / 128, BB), 256>>>(Vb, out);
    k_gemm_vb_att<<<dim3(AA / 128, CC / 128, BB), 256>>>(Va, out);
    // 5) gate + concat
    k_gate_concat<<<dim3(AA / 256, BB, 2), 256>>>(Wg, Va, Vb, out);
    // 6) optional tail element(s) = input_size
    long main_elems = 2L * BB * 2 * CC * AA;   // 16,777,216
    if ((long)out_size > main_elems) {
        long rem = (long)out_size - main_elems;
        k_tail<<<(unsigned)((rem + 255) / 256), 256>>>(out, main_elems, out_size, isz);
    }
}

// round 2
// speedup vs baseline: 1.0039x; 1.0039x over previous
#include <cuda_runtime.h>
#include <math_constants.h>

#define BB 4
#define CC 256
#define AA 4096

// ---- device scratch (no allocs allowed) ----
__device__ float g_S[(long)BB * AA * AA];          // 256 MB: S[b][a][n]
__device__ float g_VbW[(long)BB * CC * AA];        // 16 MB : (W^T Vb)[b][c][n]
__device__ float g_rowmax[BB * AA];
__device__ float g_rowsum[BB * AA];
__device__ float g_colmax[BB * AA];
__device__ float g_colsum[BB * AA];
__device__ float g_cpm[BB * 8 * AA];               // column-stat partials
__device__ float g_cps[BB * 8 * AA];

// ============================================================
// Generic 128x128 fp32 GEMM body, 256 threads, 8x8 micro-tiles.
// AKM:  A stored [K x M] (k-major)   else [M x K]
// BKM:  B stored [K x N] (k-major)   else [N x K]
// SMAX: B element -> exp(B - mx[n]); epilogue: * 1/sm[n]
// ============================================================
template<bool AKM, bool BKM, bool SMAX>
__device__ __forceinline__ void gemm_body(
    const float* __restrict__ A, int lda,
    const float* __restrict__ B, int ldb,
    float* __restrict__ C, int ldc,
    int K,
    const float* __restrict__ mx, const float* __restrict__ sm)
{
    __shared__ __align__(16) float As[16][132];
    __shared__ __align__(16) float Bs[16][132];
    __shared__ float mxs[128];

    const int m0 = blockIdx.y * 128;
    const int n0 = blockIdx.x * 128;
    const int tid = threadIdx.x;

    if (SMAX) {
        if (tid < 128) mxs[tid] = mx[n0 + tid];
        __syncthreads();
    }

    float acc[8][8];
#pragma unroll
    for (int i = 0; i < 8; i++)
#pragma unroll
        for (int j = 0; j < 8; j++) acc[i][j] = 0.f;

    const int tx = tid & 15, ty = tid >> 4;

    for (int k0 = 0; k0 < K; k0 += 16) {
        // ---- load A tile ----
#pragma unroll
        for (int r = 0; r < 8; r++) {
            int i = tid + r * 256;
            if (AKM) {
                int k = i >> 7, m = i & 127;
                As[k][m] = A[(long)(k0 + k) * lda + (m0 + m)];
            } else {
                int m = i >> 4, k = i & 15;
                As[k][m] = A[(long)(m0 + m) * lda + (k0 + k)];
            }
        }
        // ---- load B tile (optionally exponentiated) ----
#pragma unroll
        for (int r = 0; r < 8; r++) {
            int i = tid + r * 256;
            int k, n;
            float v;
            if (BKM) {
                k = i >> 7; n = i & 127;
                v = B[(long)(k0 + k) * ldb + (n0 + n)];
            } else {
                n = i >> 4; k = i & 15;
                v = B[(long)(n0 + n) * ldb + (k0 + k)];
            }
            if (SMAX) v = __expf(v - mxs[n]);
            Bs[k][n] = v;
        }
        __syncthreads();
#pragma unroll
        for (int kk = 0; kk < 16; kk++) {
            float4 a0 = *(const float4*)&As[kk][ty * 8];
            float4 a1 = *(const float4*)&As[kk][ty * 8 + 4];
            float4 b0 = *(const float4*)&Bs[kk][tx * 8];
            float4 b1 = *(const float4*)&Bs[kk][tx * 8 + 4];
            float a8[8] = {a0.x,a0.y,a0.z,a0.w,a1.x,a1.y,a1.z,a1.w};
            float b8[8] = {b0.x,b0.y,b0.z,b0.w,b1.x,b1.y,b1.z,b1.w};
#pragma unroll
            for (int i = 0; i < 8; i++)
#pragma unroll
                for (int j = 0; j < 8; j++)
                    acc[i][j] = fmaf(a8[i], b8[j], acc[i][j]);
        }
        __syncthreads();
    }

    float inv[8];
#pragma unroll
    for (int j = 0; j < 8; j++)
        inv[j] = SMAX ? 1.f / sm[n0 + tx * 8 + j] : 1.f;

#pragma unroll
    for (int i = 0; i < 8; i++)
#pragma unroll
        for (int j = 0; j < 8; j++)
            C[(long)(m0 + ty * 8 + i) * ldc + (n0 + tx * 8 + j)] = acc[i][j] * inv[j];
}

// ---- GEMM 1: VbW[b][c][n] = sum_d W[d][c] * Vb[b][d][n]   (M=256,N=4096,K=256)
__global__ void __launch_bounds__(256) k_gemm_vbw(const float* __restrict__ Wl,
                                                  const float* __restrict__ Vb) {
    long b = blockIdx.z;
    gemm_body<true, true, false>(Wl, CC,
                                 Vb + b * CC * AA, AA,
                                 g_VbW + b * CC * AA, AA,
                                 CC, nullptr, nullptr);
}

// ---- GEMM 2: S[b][a][n] = sum_c Va[b][c][a] * VbW[b][c][n]  (M=N=4096,K=256)
__global__ void __launch_bounds__(256) k_gemm_s(const float* __restrict__ Va) {
    long b = blockIdx.z;
    gemm_body<true, true, false>(Va + b * CC * AA, AA,
                                 g_VbW + b * CC * AA, AA,
                                 g_S + b * (long)AA * AA, AA,
                                 CC, nullptr, nullptr);
}

// ---- GEMM 3: Va_att[b][c][n] = sum_a Vb[b][c][a] * exp(S[b][a][n]-cm[b][n])/cs[b][n]
__global__ void __launch_bounds__(256) k_gemm_va_att(const float* __restrict__ Vb,
                                                     float* __restrict__ out) {
    long b = blockIdx.z;
    gemm_body<false, true, true>(Vb + b * CC * AA, AA,
                                 g_S + b * (long)AA * AA, AA,
                                 out + b * (2L * CC * AA), AA,
                                 AA, g_colmax + b * AA, g_colsum + b * AA);
}

// ---- GEMM 4: Vb_att[b][c][n] = sum_a Va[b][c][a] * exp(S[b][n][a]-rm[b][n])/rs[b][n]
__global__ void __launch_bounds__(256) k_gemm_vb_att(const float* __restrict__ Va,
                                                     float* __restrict__ out) {
    long b = blockIdx.z;
    gemm_body<false, false, true>(Va + b * CC * AA, AA,
                                  g_S + b * (long)AA * AA, AA,
                                  out + (long)(BB + b) * (2L * CC * AA), AA,
                                  AA, g_rowmax + b * AA, g_rowsum + b * AA);
}

// ---- row stats: max/sum-exp over n for each (b,a). one warp per row.
__global__ void __launch_bounds__(256) k_row_stats() {
    int row = blockIdx.x * 8 + (threadIdx.x >> 5);   // row in [0, BB*AA)
    int lane = threadIdx.x & 31;
    const float* p = g_S + (long)row * AA;
    float m = -CUDART_INF_F;
    for (int i = lane; i < AA; i += 32) m = fmaxf(m, p[i]);
#pragma unroll
    for (int o = 16; o; o >>= 1) m = fmaxf(m, __shfl_xor_sync(0xffffffffu, m, o));
    float s = 0.f;
    for (int i = lane; i < AA; i += 32) s += __expf(p[i] - m);
#pragma unroll
    for (int o = 16; o; o >>= 1) s += __shfl_xor_sync(0xffffffffu, s, o);
    if (lane == 0) { g_rowmax[row] = m; g_rowsum[row] = s; }
}

// ---- column stats, partial over 512-row chunks. grid (AA/128, 8, BB), 128 thr.
__global__ void __launch_bounds__(128) k_col_stats_part() {
    int b = blockIdx.z, ch = blockIdx.y;
    int n = blockIdx.x * 128 + threadIdx.x;
    const float* p = g_S + ((long)b * AA + ch * 512) * AA + n;
    float m = -CUDART_INF_F, s = 0.f;
    for (int i = 0; i < 512; i++) {
        float x = p[(long)i * AA];
        if (x > m) { s *= __expf(m - x); m = x; }
        s += __expf(x - m);
    }
    g_cpm[(b * 8 + ch) * AA + n] = m;
    g_cps[(b * 8 + ch) * AA + n] = s;
}

// ---- combine 8 column partials
__global__ void __launch_bounds__(256) k_col_stats_combine() {
    int idx = blockIdx.x * 256 + threadIdx.x;   // idx in [0, BB*AA)
    int b = idx / AA, n = idx % AA;
    float m = -CUDART_INF_F;
#pragma unroll
    for (int ch = 0; ch < 8; ch++) m = fmaxf(m, g_cpm[(b * 8 + ch) * AA + n]);
    float s = 0.f;
#pragma unroll
    for (int ch = 0; ch < 8; ch++)
        s += g_cps[(b * 8 + ch) * AA + n] * __expf(g_cpm[(b * 8 + ch) * AA + n] - m);
    g_colmax[idx] = m;
    g_colsum[idx] = s;
}

// ---- gate + in-place scale + concat-copy. grid (AA/256, BB, 2), 256 thr.
__global__ void __launch_bounds__(256) k_gate_concat(const float* __restrict__ Wg,
                                                     const float* __restrict__ Va,
                                                     const float* __restrict__ Vb,
                                                     float* __restrict__ out) {
    int side = blockIdx.z;
    int b = blockIdx.y;
    int n = blockIdx.x * 256 + threadIdx.x;
    const float* orig = (side ? Vb : Va) + (long)b * CC * AA + n;
    float* att = out + ((long)(side * BB + b)) * (2L * CC * AA) + n;
    float dot = 0.f;
#pragma unroll 4
    for (int c = 0; c < CC; c++) dot = fmaf(att[(long)c * AA], Wg[c], dot);
    float mask = 1.f / (1.f + __expf(-dot));
#pragma unroll 4
    for (int c = 0; c < CC; c++) {
        att[(long)c * AA] *= mask;
        att[(long)(c + CC) * AA] = orig[(long)c * AA];
    }
}

// ---- tail fill (for a possible trailing input_size element in d_out)
__global__ void k_tail(float* __restrict__ out, long start, long total,
                       const int* __restrict__ isz) {
    long i = start + blockIdx.x * 256L + threadIdx.x;
    if (i < total) out[i] = (float)(*isz);
}

extern "C" void kernel_launch(void* const* d_in, const int* in_sizes, int n_in,
                              void* d_out, int out_size) {
    const float* Va = (const float*)d_in[0];
    const float* Vb = (const float*)d_in[1];
    const float* Wl = (const float*)d_in[2];
    const float* Wg = (const float*)d_in[3];
    const int* isz = (const int*)d_in[4];
    float* out = (float*)d_out;

    // 1) VbW = W^T @ Vb
    k_gemm_vbw<<<dim3(AA / 128, CC / 128, BB), 256>>>(Wl, Vb);
    // 2) S = Va^T @ VbW
    k_gemm_s<<<dim3(AA / 128, AA / 128, BB), 256>>>(Va);
    // 3) softmax stats
    k_row_stats<<<BB * AA / 8, 256>>>();
    k_col_stats_part<<<dim3(AA / 128, 8, BB), 128>>>();
    k_col_stats_combine<<<BB * AA / 256, 256>>>();
    // 4) attention GEMMs straight into d_out
    k_gemm_va_att<<<dim3(AA / 128, CC / 128, BB), 256>>>(Vb, out);
    k_gemm_vb_att<<<dim3(AA / 128, CC / 128, BB), 256>>>(Va, out);
    // 5) gate + concat
    k_gate_concat<<<dim3(AA / 256, BB, 2), 256>>>(Wg, Va, Vb, out);
    // 6) optional tail element(s) = input_size
    long main_elems = 2L * BB * 2 * CC * AA;   // 16,777,216
    if ((long)out_size > main_elems) {
        long rem = (long)out_size - main_elems;
        k_tail<<<(unsigned)((rem + 255) / 256), 256>>>(out, main_elems, out_size, isz);
    }
}

// round 3
// speedup vs baseline: 1.5721x; 1.5661x over previous
#include <cuda_runtime.h>
#include <cuda_bf16.h>
#include <mma.h>
#include <math_constants.h>
#include <type_traits>

using namespace nvcuda;
typedef __nv_bfloat16 bf16;

#define BB 4
#define CC 256
#define AA 4096

// ---- device scratch (no allocs allowed) ----
__device__ float g_S[(long)BB * AA * AA];          // 256 MB: S[b][a][n]
__device__ float g_VbW[(long)BB * CC * AA];        // 16 MB
__device__ float g_rowmax[BB * AA];
__device__ float g_rowsum[BB * AA];
__device__ float g_colmax[BB * AA];
__device__ float g_colsum[BB * AA];
__device__ float g_cpm[BB * 8 * AA];
__device__ float g_cps[BB * 8 * AA];

__device__ __forceinline__ void split_bf16(float v, bf16& h, bf16& l) {
    h = __float2bfloat16(v);
    l = __float2bfloat16(v - __bfloat162float(h));
}

// ============================================================
// wmma bf16-split GEMM, 128x128 block tile, 256 threads (8 warps),
// warp tile 32x64 (2x4 fragments), K-step 32.
//
// MODE 0:  C[m][n] = sum_k A[k][m] * B[k][n]            (A k-major)
// MODE 1:  C[m][n] = sum_k A[m][k] * exp(B[k][n]-cm[n]) / cs[n]
// MODE 2:  C[m][n] = sum_k (A[m][k]*e^{cm[k]}) * (exp(B[n][k]-cm[k]) * e^{-rm[n]}/rs[n])
// ============================================================
template<int MODE>
__global__ void __launch_bounds__(256) k_wmma(
    const float* __restrict__ Ag, long sA, int lda,
    const float* __restrict__ Bg, long sB, int ldb,
    float* __restrict__ Cg, long sC, int ldc,
    int K,
    const float* __restrict__ cmax, const float* __restrict__ csum,
    const float* __restrict__ rmax, const float* __restrict__ rsum)
{
    using LA = typename std::conditional<MODE == 0, wmma::col_major, wmma::row_major>::type;
    using LB = typename std::conditional<MODE == 2, wmma::col_major, wmma::row_major>::type;
    constexpr int LDA = (MODE == 0) ? 136 : 40;   // smem leading dims
    constexpr int LDB = (MODE == 2) ? 40 : 136;

    __shared__ bf16 Ash[5120], Asl[5120], Bsh[5120], Bsl[5120];
    __shared__ float s_cmn[128], s_scn[128];

    const int tid = threadIdx.x;
    const int b = blockIdx.z;
    const int m0 = blockIdx.y * 128, n0 = blockIdx.x * 128;
    const float* A = Ag + (long)b * sA;
    const float* B = Bg + (long)b * sB;
    float* C = Cg + (long)b * sC;
    const float* cm = cmax + (long)b * AA;

    if (MODE == 1 && tid < 128) {
        s_cmn[tid] = cm[n0 + tid];
        s_scn[tid] = 1.f / csum[(long)b * AA + n0 + tid];
    }
    if (MODE == 2 && tid < 128) {
        s_scn[tid] = __expf(-rmax[(long)b * AA + n0 + tid]) / rsum[(long)b * AA + n0 + tid];
    }

    wmma::fragment<wmma::accumulator, 16, 16, 16, float> acc[2][4];
#pragma unroll
    for (int i = 0; i < 2; i++)
#pragma unroll
        for (int j = 0; j < 4; j++) wmma::fill_fragment(acc[i][j], 0.f);

    const int wid = tid >> 5;
    const int wm = wid >> 1, wn = wid & 1;    // 4 x 2 warp grid

    for (int k0 = 0; k0 < K; k0 += 32) {
        __syncthreads();
        // ---- A tile (hi/lo split) ----
        if (MODE == 0) {
#pragma unroll
            for (int r = 0; r < 16; r++) {
                int idx = tid + r * 256;
                int k = idx >> 7, m = idx & 127;
                float v = A[(long)(k0 + k) * lda + m0 + m];
                bf16 h, l; split_bf16(v, h, l);
                Ash[k * 136 + m] = h; Asl[k * 136 + m] = l;
            }
        } else {
            float mul = 1.f;
            if (MODE == 2) mul = __expf(cm[k0 + (tid & 31)]);
#pragma unroll
            for (int r = 0; r < 16; r++) {
                int idx = tid + r * 256;
                int m = idx >> 5, k = idx & 31;      // k == tid&31 for all r
                float v = A[(long)(m0 + m) * lda + k0 + k] * mul;
                bf16 h, l; split_bf16(v, h, l);
                Ash[m * 40 + k] = h; Asl[m * 40 + k] = l;
            }
        }
        // ---- B tile (hi/lo split, optional fused exp/scale) ----
        if (MODE == 2) {
            float cmv = cm[k0 + (tid & 31)];
#pragma unroll
            for (int r = 0; r < 16; r++) {
                int idx = tid + r * 256;
                int n = idx >> 5, k = idx & 31;
                float s = B[(long)(n0 + n) * ldb + k0 + k];
                float v = __expf(s - cmv) * s_scn[n];
                bf16 h, l; split_bf16(v, h, l);
                Bsh[n * 40 + k] = h; Bsl[n * 40 + k] = l;
            }
        } else {
#pragma unroll
            for (int r = 0; r < 16; r++) {
                int idx = tid + r * 256;
                int k = idx >> 7, n = idx & 127;
                float v = B[(long)(k0 + k) * ldb + n0 + n];
                if (MODE == 1) v = __expf(v - s_cmn[n]) * s_scn[n];
                bf16 h, l; split_bf16(v, h, l);
                Bsh[k * 136 + n] = h; Bsl[k * 136 + n] = l;
            }
        }
        __syncthreads();
        // ---- 3-product split mma ----
#pragma unroll
        for (int kk = 0; kk < 32; kk += 16) {
            wmma::fragment<wmma::matrix_a, 16, 16, 16, bf16, LA> ah[2], al[2];
            wmma::fragment<wmma::matrix_b, 16, 16, 16, bf16, LB> bh[4], bl[4];
#pragma unroll
            for (int i = 0; i < 2; i++) {
                int off = (MODE == 0) ? (kk * 136 + wm * 32 + i * 16)
                                      : ((wm * 32 + i * 16) * 40 + kk);
                wmma::load_matrix_sync(ah[i], Ash + off, LDA);
                wmma::load_matrix_sync(al[i], Asl + off, LDA);
            }
#pragma unroll
            for (int j = 0; j < 4; j++) {
                int off = (MODE == 2) ? ((wn * 64 + j * 16) * 40 + kk)
                                      : (kk * 136 + wn * 64 + j * 16);
                wmma::load_matrix_sync(bh[j], Bsh + off, LDB);
                wmma::load_matrix_sync(bl[j], Bsl + off, LDB);
            }
#pragma unroll
            for (int i = 0; i < 2; i++)
#pragma unroll
                for (int j = 0; j < 4; j++) {
                    wmma::mma_sync(acc[i][j], ah[i], bh[j], acc[i][j]);
                    wmma::mma_sync(acc[i][j], ah[i], bl[j], acc[i][j]);
                    wmma::mma_sync(acc[i][j], al[i], bh[j], acc[i][j]);
                }
        }
    }
    // ---- direct store (scales already folded into B) ----
#pragma unroll
    for (int i = 0; i < 2; i++)
#pragma unroll
        for (int j = 0; j < 4; j++)
            wmma::store_matrix_sync(C + (long)(m0 + wm * 32 + i * 16) * ldc
                                      + n0 + wn * 64 + j * 16,
                                    acc[i][j], ldc, wmma::mem_row_major);
}

// ---- row stats: max/sum-exp over n for each (b,a). one warp per row.
__global__ void __launch_bounds__(256) k_row_stats() {
    int row = blockIdx.x * 8 + (threadIdx.x >> 5);
    int lane = threadIdx.x & 31;
    const float* p = g_S + (long)row * AA;
    float m = -CUDART_INF_F;
    for (int i = lane; i < AA; i += 32) m = fmaxf(m, p[i]);
#pragma unroll
    for (int o = 16; o; o >>= 1) m = fmaxf(m, __shfl_xor_sync(0xffffffffu, m, o));
    float s = 0.f;
    for (int i = lane; i < AA; i += 32) s += __expf(p[i] - m);
#pragma unroll
    for (int o = 16; o; o >>= 1) s += __shfl_xor_sync(0xffffffffu, s, o);
    if (lane == 0) { g_rowmax[row] = m; g_rowsum[row] = s; }
}

// ---- column stats, partial over 512-row chunks.
__global__ void __launch_bounds__(128) k_col_stats_part() {
    int b = blockIdx.z, ch = blockIdx.y;
    int n = blockIdx.x * 128 + threadIdx.x;
    const float* p = g_S + ((long)b * AA + ch * 512) * AA + n;
    float m = -CUDART_INF_F, s = 0.f;
    for (int i = 0; i < 512; i++) {
        float x = p[(long)i * AA];
        if (x > m) { s *= __expf(m - x); m = x; }
        s += __expf(x - m);
    }
    g_cpm[(b * 8 + ch) * AA + n] = m;
    g_cps[(b * 8 + ch) * AA + n] = s;
}

__global__ void __launch_bounds__(256) k_col_stats_combine() {
    int idx = blockIdx.x * 256 + threadIdx.x;
    int b = idx / AA, n = idx % AA;
    float m = -CUDART_INF_F;
#pragma unroll
    for (int ch = 0; ch < 8; ch++) m = fmaxf(m, g_cpm[(b * 8 + ch) * AA + n]);
    float s = 0.f;
#pragma unroll
    for (int ch = 0; ch < 8; ch++)
        s += g_cps[(b * 8 + ch) * AA + n] * __expf(g_cpm[(b * 8 + ch) * AA + n] - m);
    g_colmax[idx] = m;
    g_colsum[idx] = s;
}

// ---- gate + in-place scale + concat-copy.
__global__ void __launch_bounds__(256) k_gate_concat(const float* __restrict__ Wg,
                                                     const float* __restrict__ Va,
                                                     const float* __restrict__ Vb,
                                                     float* __restrict__ out) {
    int side = blockIdx.z;
    int b = blockIdx.y;
    int n = blockIdx.x * 256 + threadIdx.x;
    const float* orig = (side ? Vb : Va) + (long)b * CC * AA + n;
    float* att = out + ((long)(side * BB + b)) * (2L * CC * AA) + n;
    float dot = 0.f;
#pragma unroll 4
    for (int c = 0; c < CC; c++) dot = fmaf(att[(long)c * AA], Wg[c], dot);
    float mask = 1.f / (1.f + __expf(-dot));
#pragma unroll 4
    for (int c = 0; c < CC; c++) {
        att[(long)c * AA] *= mask;
        att[(long)(c + CC) * AA] = orig[(long)c * AA];
    }
}

__global__ void k_tail(float* __restrict__ out, long start, long total,
                       const int* __restrict__ isz) {
    long i = start + blockIdx.x * 256L + threadIdx.x;
    if (i < total) out[i] = (float)(*isz);
}

extern "C" void kernel_launch(void* const* d_in, const int* in_sizes, int n_in,
                              void* d_out, int out_size) {
    const float* Va = (const float*)d_in[0];
    const float* Vb = (const float*)d_in[1];
    const float* Wl = (const float*)d_in[2];
    const float* Wg = (const float*)d_in[3];
    const int* isz = (const int*)d_in[4];
    float* out = (float*)d_out;

    float* S = nullptr;  cudaGetSymbolAddress((void**)&S, g_S);
    float* VbWp = nullptr; cudaGetSymbolAddress((void**)&VbWp, g_VbW);
    float* cmx = nullptr; cudaGetSymbolAddress((void**)&cmx, g_colmax);
    float* csm = nullptr; cudaGetSymbolAddress((void**)&csm, g_colsum);
    float* rmx = nullptr; cudaGetSymbolAddress((void**)&rmx, g_rowmax);
    float* rsm = nullptr; cudaGetSymbolAddress((void**)&rsm, g_rowsum);

    // 1) VbW[b][c][n] = sum_d W[d][c] * Vb[b][d][n]   (M=256, N=4096, K=256)
    k_wmma<0><<<dim3(AA / 128, CC / 128, BB), 256>>>(
        Wl, 0, CC, Vb, (long)CC * AA, AA, VbWp, (long)CC * AA, AA, CC,
        nullptr, nullptr, nullptr, nullptr);
    // 2) S[b][a][n] = sum_c Va[b][c][a] * VbW[b][c][n]  (M=N=4096, K=256)
    k_wmma<0><<<dim3(AA / 128, AA / 128, BB), 256>>>(
        Va, (long)CC * AA, AA, VbWp, (long)CC * AA, AA, S, (long)AA * AA, AA, CC,
        nullptr, nullptr, nullptr, nullptr);
    // 3) softmax stats
    k_row_stats<<<BB * AA / 8, 256>>>();
    k_col_stats_part<<<dim3(AA / 128, 8, BB), 128>>>();
    k_col_stats_combine<<<BB * AA / 256, 256>>>();
    // 4) Va_att = Vb @ softmax_col(S)   -> out[0:B]
    k_wmma<1><<<dim3(AA / 128, CC / 128, BB), 256>>>(
        Vb, (long)CC * AA, AA, S, (long)AA * AA, AA, out, 2L * CC * AA, AA, AA,
        cmx, csm, nullptr, nullptr);
    // 5) Vb_att = Va @ softmax_row(S)^T -> out[B:2B]
    k_wmma<2><<<dim3(AA / 128, CC / 128, BB), 256>>>(
        Va, (long)CC * AA, AA, S, (long)AA * AA, AA,
        out + (long)BB * 2 * CC * AA, 2L * CC * AA, AA, AA,
        cmx, nullptr, rmx, rsm);
    // 6) gate + concat
    k_gate_concat<<<dim3(AA / 256, BB, 2), 256>>>(Wg, Va, Vb, out);
    // 7) optional tail
    long main_elems = 2L * BB * 2 * CC * AA;
    if ((long)out_size > main_elems) {
        long rem = (long)out_size - main_elems;
        k_tail<<<(unsigned)((rem + 255) / 256), 256>>>(out, main_elems, out_size, isz);
    }
}

// round 5
// speedup vs baseline: 1.9158x; 1.2186x over previous
#include <cuda_runtime.h>
#include <cuda_bf16.h>
#include <mma.h>
#include <math_constants.h>
#include <cstdint>

using namespace nvcuda;
typedef __nv_bfloat16 bf16;

#define BB 4
#define CC 256
#define AA 4096

// tcgen05 is only legal on the arch-specific ('a') targets.
#if defined(__CUDA_ARCH_FEAT_SM103_ALL) || defined(__CUDA_ARCH_FEAT_SM100_ALL) || \
    defined(__CUDA_ARCH_FEAT_SM101_ALL) || defined(__CUDA_ARCH_FEAT_SM110_ALL)
#define HAS_TC 1
#else
#define HAS_TC 0
#endif

// ---- device scratch ----
__device__ float g_S [(long)BB * AA * AA];    // S [b][a][n]
__device__ float g_ST[(long)BB * AA * AA];    // S^T [b][n][a]
__device__ float g_VaT [(long)BB * AA * CC];  // Va^T [b][a][c]
__device__ float g_VbWT[(long)BB * AA * CC];  // (W^T Vb)^T [b][n][c]
__device__ float g_rm[BB * AA], g_rs[BB * AA];
__device__ float g_cm[BB * AA], g_cs[BB * AA];

// ============================================================
// PTX helpers
// ============================================================
__device__ __forceinline__ uint32_t smem_u32(const void* p) {
    uint32_t a;
    asm("{ .reg .u64 t; cvta.to.shared.u64 t, %1; cvt.u32.u64 %0, t; }" : "=r"(a) : "l"(p));
    return a;
}
#if HAS_TC
__device__ __forceinline__ uint32_t elect_one() {
    uint32_t p;
    asm volatile("{ .reg .pred p; elect.sync _|p, 0xFFFFFFFF; selp.b32 %0, 1, 0, p; }" : "=r"(p));
    return p;
}
__device__ __forceinline__ void mbar_init(uint32_t m, uint32_t cnt) {
    asm volatile("mbarrier.init.shared.b64 [%0], %1;" :: "r"(m), "r"(cnt) : "memory");
}
__device__ __forceinline__ void mbar_wait(uint32_t m, uint32_t par) {
    asm volatile(
        "{\n\t.reg .pred P;\n\t"
        "W_%=:\n\t"
        "mbarrier.try_wait.parity.acquire.cta.shared::cta.b64 P, [%0], %1, 0x989680;\n\t"
        "@P bra.uni D_%=;\n\t"
        "bra.uni W_%=;\n\t"
        "D_%=:\n\t}"
        :: "r"(m), "r"(par) : "memory");
}
__device__ __forceinline__ void tmem_alloc(uint32_t dst, uint32_t ncols) {
    asm volatile("tcgen05.alloc.cta_group::1.sync.aligned.shared::cta.b32 [%0], %1;"
                 :: "r"(dst), "r"(ncols) : "memory");
}
__device__ __forceinline__ void tmem_dealloc(uint32_t t, uint32_t ncols) {
    asm volatile("tcgen05.relinquish_alloc_permit.cta_group::1.sync.aligned;");
    asm volatile("tcgen05.dealloc.cta_group::1.sync.aligned.b32 %0, %1;" :: "r"(t), "r"(ncols));
}
__device__ __forceinline__ void tc_commit(uint32_t mbar) {
    asm volatile("tcgen05.commit.cta_group::1.mbarrier::arrive::one.shared::cluster.b64 [%0];"
                 :: "r"(mbar) : "memory");
}
__device__ __forceinline__ void mma_f16_ss(uint32_t d, uint64_t ad, uint64_t bd,
                                           uint32_t idesc, bool accum) {
    uint32_t en = accum ? 1u : 0u;
    asm volatile(
        "{\n\t.reg .pred p;\n\tsetp.ne.u32 p, %4, 0;\n\t"
        "tcgen05.mma.cta_group::1.kind::f16 [%0], %1, %2, %3, {%5, %5, %5, %5}, p;\n\t}"
        :: "r"(d), "l"(ad), "l"(bd), "r"(idesc), "r"(en), "r"(0u) : "memory");
}
#define TC_FENCE_AFTER()  asm volatile("tcgen05.fence::after_thread_sync;" ::: "memory")
#define TC_FENCE_BEFORE() asm volatile("tcgen05.fence::before_thread_sync;" ::: "memory")
#define PROXY_FENCE()     asm volatile("fence.proxy.async.shared::cta;" ::: "memory")
#define TC_WAIT_LD()      asm volatile("tcgen05.wait::ld.sync.aligned;" ::: "memory")

#define TC_LD_X32(r, addr) \
    asm volatile("tcgen05.ld.sync.aligned.32x32b.x32.b32 " \
        "{%0,%1,%2,%3,%4,%5,%6,%7,%8,%9,%10,%11,%12,%13,%14,%15," \
        "%16,%17,%18,%19,%20,%21,%22,%23,%24,%25,%26,%27,%28,%29,%30,%31}, [%32];" \
        : "=r"((r)[0]),"=r"((r)[1]),"=r"((r)[2]),"=r"((r)[3]), \
          "=r"((r)[4]),"=r"((r)[5]),"=r"((r)[6]),"=r"((r)[7]), \
          "=r"((r)[8]),"=r"((r)[9]),"=r"((r)[10]),"=r"((r)[11]), \
          "=r"((r)[12]),"=r"((r)[13]),"=r"((r)[14]),"=r"((r)[15]), \
          "=r"((r)[16]),"=r"((r)[17]),"=r"((r)[18]),"=r"((r)[19]), \
          "=r"((r)[20]),"=r"((r)[21]),"=r"((r)[22]),"=r"((r)[23]), \
          "=r"((r)[24]),"=r"((r)[25]),"=r"((r)[26]),"=r"((r)[27]), \
          "=r"((r)[28]),"=r"((r)[29]),"=r"((r)[30]),"=r"((r)[31]) \
        : "r"(addr))
#endif  // HAS_TC

static constexpr uint64_t DESC_BASE_SW128 =
    (uint64_t(2) << 61) | (uint64_t(1) << 46) | (uint64_t(64) << 32) | (uint64_t(1) << 16);
__device__ __forceinline__ uint64_t mk_desc(uint32_t addr) {
    return DESC_BASE_SW128 | ((uint64_t)(addr >> 4) & 0x3FFF);
}
__device__ __forceinline__ int sw128(int off) { return off ^ ((off >> 3) & 0x70); }

__device__ __forceinline__ void split_bf16(float v, bf16& h, bf16& l) {
    h = __float2bfloat16(v);
    l = __float2bfloat16(v - __bfloat162float(h));
}
__device__ __forceinline__ uint32_t pack2(bf16 a, bf16 b) {
    return ((uint32_t)__bfloat16_as_ushort(b) << 16) | __bfloat16_as_ushort(a);
}

// ============================================================
// SS bf16-split GEMM. CTA tile M=128 x N=256, 256 threads.
// C[m][n] = sum_k A[m][k] * f(B[n][k]),  f = EXP ? exp(x-m[n])/s[n] : x
// A, B K-major fp32. tcgen05 path: K-stage 64, double-buffered SMEM.
// Fallback path (non-'a' target): wmma, two 128x128 halves, K-step 32.
// ============================================================
#define OFF_MBAR 0
#define OFF_TMEM 32
#define STG_B (96 * 1024)
#define OFF_AH(s) (1024 + (s) * STG_B)
#define OFF_AL(s) (OFF_AH(s) + 16 * 1024)
#define OFF_BH(s) (OFF_AH(s) + 32 * 1024)
#define OFF_BL(s) (OFF_AH(s) + 64 * 1024)
#define OFF_STATS (1024 + 2 * STG_B)
#define SMEM_NEED (OFF_STATS + 2048 + 1024)

static constexpr uint32_t IDESC =
    (1u << 4) | (1u << 7) | (1u << 10) | ((256 / 8) << 17) | ((128 / 16) << 24);

template<bool EXP>
__global__ void __launch_bounds__(256) k_tc(
    const float* __restrict__ Ag, long sA, int lda,
    const float* __restrict__ Bg, long sB, int ldb,
    float* __restrict__ Cg, long sC,
    int K,
    const float* __restrict__ mv, const float* __restrict__ sv)
{
    extern __shared__ char smraw[];
    char* sm = (char*)(((uintptr_t)smraw + 1023) & ~(uintptr_t)1023);
    const int tid = threadIdx.x, wid = tid >> 5, lid = tid & 31;
    const int b = blockIdx.z;
    const int m0 = blockIdx.y * 128, n0 = blockIdx.x * 256;
    const float* A = Ag + (long)b * sA;
    const float* B = Bg + (long)b * sB;
    float* C = Cg + (long)b * sC;
    float* s_m  = (float*)(sm + OFF_STATS);
    float* s_is = s_m + 256;

#if HAS_TC
    const uint32_t sb = smem_u32(sm);
    if (tid == 0) { mbar_init(sb + OFF_MBAR, 1); mbar_init(sb + OFF_MBAR + 8, 1); }
    if (wid == 0) tmem_alloc(sb + OFF_TMEM, 256);
    if (EXP) {
        s_m[tid]  = mv[(long)b * AA + n0 + tid];
        s_is[tid] = 1.f / sv[(long)b * AA + n0 + tid];
    }
    __syncthreads();
    uint32_t tmem;
    asm volatile("ld.shared.b32 %0, [%1];" : "=r"(tmem) : "r"(sb + OFF_TMEM));

    int ph0 = 0, ph1 = 0;
    const int nst = K / 64;
    for (int s = 0; s < nst; s++) {
        const int buf = s & 1;
        if (s >= 2) {
            if (buf) { mbar_wait(sb + OFF_MBAR + 8, ph1); ph1 ^= 1; }
            else     { mbar_wait(sb + OFF_MBAR,     ph0); ph0 ^= 1; }
        }
        const int k0 = s * 64;
        // ---- B tile: thread t -> row n0+t, 64 k-elements ----
        {
            const float4* src = (const float4*)(B + (long)(n0 + tid) * ldb + k0);
            char* bhb = sm + OFF_BH(buf);
            char* blb = sm + OFF_BL(buf);
            float mn = 0.f, isn = 0.f;
            if (EXP) { mn = s_m[tid]; isn = s_is[tid]; }
#pragma unroll
            for (int q = 0; q < 16; q++) {
                float4 v = __ldg(src + q);
                if (EXP) {
                    v.x = __expf(v.x - mn) * isn; v.y = __expf(v.y - mn) * isn;
                    v.z = __expf(v.z - mn) * isn; v.w = __expf(v.w - mn) * isn;
                }
                bf16 h0,l0,h1,l1,h2,l2,h3,l3;
                split_bf16(v.x,h0,l0); split_bf16(v.y,h1,l1);
                split_bf16(v.z,h2,l2); split_bf16(v.w,h3,l3);
                int off = tid * 128 + q * 8;
                *(uint32_t*)(bhb + sw128(off))     = pack2(h0, h1);
                *(uint32_t*)(bhb + sw128(off + 4)) = pack2(h2, h3);
                *(uint32_t*)(blb + sw128(off))     = pack2(l0, l1);
                *(uint32_t*)(blb + sw128(off + 4)) = pack2(l2, l3);
            }
        }
        // ---- A tile: thread t -> row t>>1, half t&1 ----
        {
            const int m = tid >> 1, hf = tid & 1;
            const float4* src = (const float4*)(A + (long)(m0 + m) * lda + k0 + hf * 32);
            char* ahb = sm + OFF_AH(buf);
            char* alb = sm + OFF_AL(buf);
            const int base = m * 128 + hf * 64;
#pragma unroll
            for (int q = 0; q < 8; q++) {
                float4 v = __ldg(src + q);
                bf16 h0,l0,h1,l1,h2,l2,h3,l3;
                split_bf16(v.x,h0,l0); split_bf16(v.y,h1,l1);
                split_bf16(v.z,h2,l2); split_bf16(v.w,h3,l3);
                int off = base + q * 8;
                *(uint32_t*)(ahb + sw128(off))     = pack2(h0, h1);
                *(uint32_t*)(ahb + sw128(off + 4)) = pack2(h2, h3);
                *(uint32_t*)(alb + sw128(off))     = pack2(l0, l1);
                *(uint32_t*)(alb + sw128(off + 4)) = pack2(l2, l3);
            }
        }
        PROXY_FENCE();
        __syncthreads();
        if (wid == 0 && elect_one()) {
            uint64_t adh = mk_desc(sb + OFF_AH(buf));
            uint64_t adl = mk_desc(sb + OFF_AL(buf));
            uint64_t bdh = mk_desc(sb + OFF_BH(buf));
            uint64_t bdl = mk_desc(sb + OFF_BL(buf));
#pragma unroll
            for (int k = 0; k < 4; k++) {
                mma_f16_ss(tmem, adh + k * 2, bdh + k * 2, IDESC, !(s == 0 && k == 0));
                mma_f16_ss(tmem, adh + k * 2, bdl + k * 2, IDESC, true);
                mma_f16_ss(tmem, adl + k * 2, bdh + k * 2, IDESC, true);
            }
            tc_commit(sb + OFF_MBAR + buf * 8);
        }
    }
    mbar_wait(sb + OFF_MBAR,     ph0);
    mbar_wait(sb + OFF_MBAR + 8, ph1);
    TC_FENCE_AFTER();
    if (wid < 4) {
        const int row = wid * 32 + lid;
        float* dst = C + (long)(m0 + row) * AA + n0;
#pragma unroll
        for (int ch = 0; ch < 8; ch++) {
            uint32_t r[32];
            TC_LD_X32(r, tmem + ch * 32);
            TC_WAIT_LD();
#pragma unroll
            for (int j = 0; j < 32; j += 4) {
                float4 o = make_float4(__uint_as_float(r[j]),   __uint_as_float(r[j+1]),
                                       __uint_as_float(r[j+2]), __uint_as_float(r[j+3]));
                *(float4*)(dst + ch * 32 + j) = o;
            }
        }
        TC_FENCE_BEFORE();
    }
    __syncthreads();
    if (wid == 0) tmem_dealloc(tmem, 256);

#else  // ================= wmma fallback (non-'a' target) =================
    bf16* Ash = (bf16*)(sm + 1024);      // 128 x 40
    bf16* Asl = Ash + 5120;
    bf16* Bsh = Asl + 5120;              // 128 x 40
    bf16* Bsl = Bsh + 5120;

    if (EXP) {
        s_m[tid]  = mv[(long)b * AA + n0 + tid];
        s_is[tid] = 1.f / sv[(long)b * AA + n0 + tid];
    }
    const int wm = wid >> 1, wn = wid & 1;

    for (int nh = 0; nh < 2; nh++) {
        const int n0h = n0 + nh * 128;
        wmma::fragment<wmma::accumulator, 16, 16, 16, float> acc[2][4];
#pragma unroll
        for (int i = 0; i < 2; i++)
#pragma unroll
            for (int j = 0; j < 4; j++) wmma::fill_fragment(acc[i][j], 0.f);

        for (int k0 = 0; k0 < K; k0 += 32) {
            __syncthreads();
#pragma unroll
            for (int r = 0; r < 16; r++) {
                int idx = tid + r * 256;
                int m = idx >> 5, k = idx & 31;
                float v = A[(long)(m0 + m) * lda + k0 + k];
                bf16 h, l; split_bf16(v, h, l);
                Ash[m * 40 + k] = h; Asl[m * 40 + k] = l;
            }
#pragma unroll
            for (int r = 0; r < 16; r++) {
                int idx = tid + r * 256;
                int n = idx >> 5, k = idx & 31;
                float v = B[(long)(n0h + n) * ldb + k0 + k];
                if (EXP) v = __expf(v - s_m[nh * 128 + n]) * s_is[nh * 128 + n];
                bf16 h, l; split_bf16(v, h, l);
                Bsh[n * 40 + k] = h; Bsl[n * 40 + k] = l;
            }
            __syncthreads();
#pragma unroll
            for (int kk = 0; kk < 32; kk += 16) {
                wmma::fragment<wmma::matrix_a, 16, 16, 16, bf16, wmma::row_major> ah[2], al[2];
                wmma::fragment<wmma::matrix_b, 16, 16, 16, bf16, wmma::col_major> bh[4], bl[4];
#pragma unroll
                for (int i = 0; i < 2; i++) {
                    int off = (wm * 32 + i * 16) * 40 + kk;
                    wmma::load_matrix_sync(ah[i], Ash + off, 40);
                    wmma::load_matrix_sync(al[i], Asl + off, 40);
                }
#pragma unroll
                for (int j = 0; j < 4; j++) {
                    int off = (wn * 64 + j * 16) * 40 + kk;
                    wmma::load_matrix_sync(bh[j], Bsh + off, 40);
                    wmma::load_matrix_sync(bl[j], Bsl + off, 40);
                }
#pragma unroll
                for (int i = 0; i < 2; i++)
#pragma unroll
                    for (int j = 0; j < 4; j++) {
                        wmma::mma_sync(acc[i][j], ah[i], bh[j], acc[i][j]);
                        wmma::mma_sync(acc[i][j], ah[i], bl[j], acc[i][j]);
                        wmma::mma_sync(acc[i][j], al[i], bh[j], acc[i][j]);
                    }
            }
        }
#pragma unroll
        for (int i = 0; i < 2; i++)
#pragma unroll
            for (int j = 0; j < 4; j++)
                wmma::store_matrix_sync(C + (long)(m0 + wm * 32 + i * 16) * AA
                                          + n0h + wn * 64 + j * 16,
                                        acc[i][j], AA, wmma::mem_row_major);
        __syncthreads();
    }
#endif
}

// ============================================================
// small wmma split GEMM: VbWT[b][n][c] = sum_d W[d][c] * Vb[b][d][n]
// ============================================================
__global__ void __launch_bounds__(256) k_vbwt(const float* __restrict__ Wl,
                                              const float* __restrict__ Vbg) {
    __shared__ bf16 Ash[5120], Asl[5120], Bsh[5120], Bsl[5120];
    const int tid = threadIdx.x;
    const long b = blockIdx.z;
    const int m0 = blockIdx.y * 128, n0 = blockIdx.x * 128;
    const float* Vb = Vbg + b * CC * AA;
    float* CT = g_VbWT + b * (long)AA * CC;

    wmma::fragment<wmma::accumulator, 16, 16, 16, float> acc[2][4];
#pragma unroll
    for (int i = 0; i < 2; i++)
#pragma unroll
        for (int j = 0; j < 4; j++) wmma::fill_fragment(acc[i][j], 0.f);

    const int wid = tid >> 5, wm = wid >> 1, wn = wid & 1;

    for (int k0 = 0; k0 < CC; k0 += 32) {
        __syncthreads();
#pragma unroll
        for (int r = 0; r < 16; r++) {
            int idx = tid + r * 256;
            int k = idx >> 7, m = idx & 127;
            float v = Wl[(long)(k0 + k) * CC + m0 + m];
            bf16 h, l; split_bf16(v, h, l);
            Ash[k * 136 + m] = h; Asl[k * 136 + m] = l;
        }
#pragma unroll
        for (int r = 0; r < 16; r++) {
            int idx = tid + r * 256;
            int k = idx >> 7, n = idx & 127;
            float v = Vb[(long)(k0 + k) * AA + n0 + n];
            bf16 h, l; split_bf16(v, h, l);
            Bsh[k * 136 + n] = h; Bsl[k * 136 + n] = l;
        }
        __syncthreads();
#pragma unroll
        for (int kk = 0; kk < 32; kk += 16) {
            wmma::fragment<wmma::matrix_a, 16, 16, 16, bf16, wmma::col_major> ah[2], al[2];
            wmma::fragment<wmma::matrix_b, 16, 16, 16, bf16, wmma::row_major> bh[4], bl[4];
#pragma unroll
            for (int i = 0; i < 2; i++) {
                int off = kk * 136 + wm * 32 + i * 16;
                wmma::load_matrix_sync(ah[i], Ash + off, 136);
                wmma::load_matrix_sync(al[i], Asl + off, 136);
            }
#pragma unroll
            for (int j = 0; j < 4; j++) {
                int off = kk * 136 + wn * 64 + j * 16;
                wmma::load_matrix_sync(bh[j], Bsh + off, 136);
                wmma::load_matrix_sync(bl[j], Bsl + off, 136);
            }
#pragma unroll
            for (int i = 0; i < 2; i++)
#pragma unroll
                for (int j = 0; j < 4; j++) {
                    wmma::mma_sync(acc[i][j], ah[i], bh[j], acc[i][j]);
                    wmma::mma_sync(acc[i][j], ah[i], bl[j], acc[i][j]);
                    wmma::mma_sync(acc[i][j], al[i], bh[j], acc[i][j]);
                }
        }
    }
#pragma unroll
    for (int i = 0; i < 2; i++)
#pragma unroll
        for (int j = 0; j < 4; j++) {
            long n_g = n0 + wn * 64 + j * 16;
            long m_g = m0 + wm * 32 + i * 16;
            wmma::store_matrix_sync(CT + n_g * CC + m_g, acc[i][j], CC, wmma::mem_col_major);
        }
}

// ---- 32x32 tiled transpose: dst[b][a][c] = src[b][c][a] ----
__global__ void k_transpose(const float* __restrict__ src, float* __restrict__ dst) {
    __shared__ float t[32][33];
    const long b = blockIdx.z;
    const int a0 = blockIdx.x * 32, c0 = blockIdx.y * 32;
    const float* s = src + b * CC * AA;
    float* d = dst + b * (long)AA * CC;
    const int x = threadIdx.x, y = threadIdx.y;
#pragma unroll
    for (int i = 0; i < 32; i += 8)
        t[y + i][x] = s[(long)(c0 + y + i) * AA + a0 + x];
    __syncthreads();
#pragma unroll
    for (int i = 0; i < 32; i += 8)
        d[(long)(a0 + y + i) * CC + c0 + x] = t[x][y + i];
}

// ---- row stats (max & sum-exp over last dim), one warp per row ----
__global__ void __launch_bounds__(256) k_row_stats(const float* __restrict__ Sp,
                                                   float* __restrict__ om,
                                                   float* __restrict__ os) {
    const int row = blockIdx.x * 8 + (threadIdx.x >> 5);
    const int lane = threadIdx.x & 31;
    const float4* p = (const float4*)(Sp + (long)row * AA);
    float m = -CUDART_INF_F;
    for (int i = lane; i < AA / 4; i += 32) {
        float4 v = __ldg(p + i);
        m = fmaxf(m, fmaxf(fmaxf(v.x, v.y), fmaxf(v.z, v.w)));
    }
#pragma unroll
    for (int o = 16; o; o >>= 1) m = fmaxf(m, __shfl_xor_sync(0xffffffffu, m, o));
    float s = 0.f;
    for (int i = lane; i < AA / 4; i += 32) {
        float4 v = __ldg(p + i);
        s += __expf(v.x - m) + __expf(v.y - m) + __expf(v.z - m) + __expf(v.w - m);
    }
#pragma unroll
    for (int o = 16; o; o >>= 1) s += __shfl_xor_sync(0xffffffffu, s, o);
    if (lane == 0) { om[row] = m; os[row] = s; }
}

// ---- gate + in-place scale + concat-copy ----
__global__ void __launch_bounds__(256) k_gate_concat(const float* __restrict__ Wg,
                                                     const float* __restrict__ Va,
                                                     const float* __restrict__ Vb,
                                                     float* __restrict__ out) {
    const int side = blockIdx.z, b = blockIdx.y;
    const int n = blockIdx.x * 256 + threadIdx.x;
    const float* orig = (side ? Vb : Va) + (long)b * CC * AA + n;
    float* att = out + ((long)(side * BB + b)) * (2L * CC * AA) + n;
    float dot = 0.f;
#pragma unroll 4
    for (int c = 0; c < CC; c++) dot = fmaf(att[(long)c * AA], Wg[c], dot);
    float mask = 1.f / (1.f + __expf(-dot));
#pragma unroll 4
    for (int c = 0; c < CC; c++) {
        att[(long)c * AA] *= mask;
        att[(long)(c + CC) * AA] = orig[(long)c * AA];
    }
}

__global__ void k_tail(float* __restrict__ out, long start, long total,
                       const int* __restrict__ isz) {
    long i = start + blockIdx.x * 256L + threadIdx.x;
    if (i < total) out[i] = (float)(*isz);
}

extern "C" void kernel_launch(void* const* d_in, const int* in_sizes, int n_in,
                              void* d_out, int out_size) {
    const float* Va = (const float*)d_in[0];
    const float* Vb = (const float*)d_in[1];
    const float* Wl = (const float*)d_in[2];
    const float* Wg = (const float*)d_in[3];
    const int* isz = (const int*)d_in[4];
    float* out = (float*)d_out;

    float *S, *ST, *VaT, *VbWT, *rm, *rs, *cm, *cs;
    cudaGetSymbolAddress((void**)&S, g_S);
    cudaGetSymbolAddress((void**)&ST, g_ST);
    cudaGetSymbolAddress((void**)&VaT, g_VaT);
    cudaGetSymbolAddress((void**)&VbWT, g_VbWT);
    cudaGetSymbolAddress((void**)&rm, g_rm);
    cudaGetSymbolAddress((void**)&rs, g_rs);
    cudaGetSymbolAddress((void**)&cm, g_cm);
    cudaGetSymbolAddress((void**)&cs, g_cs);

    cudaFuncSetAttribute(k_tc<false>, cudaFuncAttributeMaxDynamicSharedMemorySize, SMEM_NEED);
    cudaFuncSetAttribute(k_tc<true>,  cudaFuncAttributeMaxDynamicSharedMemorySize, SMEM_NEED);

    // 1) VaT = transpose(Va)
    k_transpose<<<dim3(AA / 32, CC / 32, BB), dim3(32, 8)>>>(Va, VaT);
    // 2) VbWT[n][c] = sum_d W[d][c] Vb[d][n]
    k_vbwt<<<dim3(AA / 128, CC / 128, BB), 256>>>(Wl, Vb);
    // 3) S[a][n]  = sum_c VaT[a][c] * VbWT[n][c]
    k_tc<false><<<dim3(AA / 256, AA / 128, BB), 256, SMEM_NEED>>>(
        VaT, (long)AA * CC, CC, VbWT, (long)AA * CC, CC,
        S, (long)AA * AA, CC, nullptr, nullptr);
    // 4) ST[n][a] = sum_c VbWT[n][c] * VaT[a][c]
    k_tc<false><<<dim3(AA / 256, AA / 128, BB), 256, SMEM_NEED>>>(
        VbWT, (long)AA * CC, CC, VaT, (long)AA * CC, CC,
        ST, (long)AA * AA, CC, nullptr, nullptr);
    // 5) stats: rows of S -> rm/rs, rows of ST -> cm/cs
    k_row_stats<<<BB * AA / 8, 256>>>(S, rm, rs);
    k_row_stats<<<BB * AA / 8, 256>>>(ST, cm, cs);
    // 6) Va_att[c][n] = sum_a Vb[c][a] * exp(ST[n][a]-cm[n])/cs[n]  -> out[0:B]
    k_tc<true><<<dim3(AA / 256, CC / 128, BB), 256, SMEM_NEED>>>(
        Vb, (long)CC * AA, AA, ST, (long)AA * AA, AA,
        out, 2L * CC * AA, AA, cm, cs);
    // 7) Vb_att[c][n] = sum_a Va[c][a] * exp(S[n][a]-rm[n])/rs[n]   -> out[B:2B]
    k_tc<true><<<dim3(AA / 256, CC / 128, BB), 256, SMEM_NEED>>>(
        Va, (long)CC * AA, AA, S, (long)AA * AA, AA,
        out + (long)BB * 2 * CC * AA, 2L * CC * AA, AA, rm, rs);
    // 8) gate + concat
    k_gate_concat<<<dim3(AA / 256, BB, 2), 256>>>(Wg, Va, Vb, out);
    // 9) optional tail
    long main_elems = 2L * BB * 2 * CC * AA;
    if ((long)out_size > main_elems) {
        long rem = (long)out_size - main_elems;
        k_tail<<<(unsigned)((rem + 255) / 256), 256>>>(out, main_elems, out_size, isz);
    }
}

// round 6
// speedup vs baseline: 4.6442x; 2.4242x over previous
#include <cuda_runtime.h>
#include <cuda_bf16.h>
#include <mma.h>
#include <math_constants.h>
#include <cstdint>

using namespace nvcuda;
typedef __nv_bfloat16 bf16;

#define BB 4
#define CC 256
#define AA 4096

#if defined(__CUDA_ARCH_FEAT_SM103_ALL) || defined(__CUDA_ARCH_FEAT_SM100_ALL) || \
    defined(__CUDA_ARCH_FEAT_SM101_ALL) || defined(__CUDA_ARCH_FEAT_SM110_ALL)
#define HAS_TC 1
#else
#define HAS_TC 0
#endif

// ---- device scratch ----
__device__ __align__(1024) float g_S [(long)BB * AA * AA];     // S fp32
__device__ __align__(1024) bf16  g_Eh [(long)BB * AA * AA];    // exp(S-60) hi
__device__ __align__(1024) bf16  g_El [(long)BB * AA * AA];
__device__ __align__(1024) bf16  g_ETh[(long)BB * AA * AA];    // transposed
__device__ __align__(1024) bf16  g_ETl[(long)BB * AA * AA];
__device__ __align__(1024) bf16  g_VaH[(long)BB * CC * AA], g_VaL[(long)BB * CC * AA];
__device__ __align__(1024) bf16  g_VbH[(long)BB * CC * AA], g_VbL[(long)BB * CC * AA];
__device__ __align__(1024) bf16  g_VaTh[(long)BB * AA * CC], g_VaTl[(long)BB * AA * CC];
__device__ __align__(1024) bf16  g_VbWTh[(long)BB * AA * CC], g_VbWTl[(long)BB * AA * CC];
__device__ __align__(1024) float g_VbWf[(long)BB * AA * CC];
__device__ float g_rp[(long)BB * 32 * AA], g_cp[(long)BB * 32 * AA];
__device__ float g_irs[BB * AA], g_ics[BB * AA];

// ============================================================
// helpers
// ============================================================
__device__ __forceinline__ uint32_t smem_u32(const void* p) {
    uint32_t a;
    asm("{ .reg .u64 t; cvta.to.shared.u64 t, %1; cvt.u32.u64 %0, t; }" : "=r"(a) : "l"(p));
    return a;
}
__device__ __forceinline__ uint32_t cvt2(float lo, float hi) {
    uint32_t r;
    asm("cvt.rn.bf16x2.f32 %0, %1, %2;" : "=r"(r) : "f"(hi), "f"(lo));
    return r;
}
// split 8 fp32 -> 8 bf16 hi (uint4) + 8 bf16 lo (uint4)
__device__ __forceinline__ void split8(const float* v, uint4& H, uint4& L) {
    uint32_t h[4], l[4];
#pragma unroll
    for (int i = 0; i < 4; i++) {
        float a = v[2 * i], b = v[2 * i + 1];
        h[i] = cvt2(a, b);
        float ar = a - __uint_as_float(h[i] << 16);
        float br = b - __uint_as_float(h[i] & 0xFFFF0000u);
        l[i] = cvt2(ar, br);
    }
    H = make_uint4(h[0], h[1], h[2], h[3]);
    L = make_uint4(l[0], l[1], l[2], l[3]);
}
__device__ __forceinline__ int sw128(int off) { return off ^ ((off >> 3) & 0x70); }

#if HAS_TC
__device__ __forceinline__ uint32_t elect_one() {
    uint32_t p;
    asm volatile("{ .reg .pred p; elect.sync _|p, 0xFFFFFFFF; selp.b32 %0, 1, 0, p; }" : "=r"(p));
    return p;
}
__device__ __forceinline__ void mbar_init(uint32_t m, uint32_t cnt) {
    asm volatile("mbarrier.init.shared.b64 [%0], %1;" :: "r"(m), "r"(cnt) : "memory");
}
__device__ __forceinline__ void mbar_wait(uint32_t m, uint32_t par) {
    asm volatile(
        "{\n\t.reg .pred P;\n\t"
        "W_%=:\n\t"
        "mbarrier.try_wait.parity.acquire.cta.shared::cta.b64 P, [%0], %1, 0x989680;\n\t"
        "@P bra.uni D_%=;\n\t"
        "bra.uni W_%=;\n\t"
        "D_%=:\n\t}"
        :: "r"(m), "r"(par) : "memory");
}
__device__ __forceinline__ void tmem_alloc(uint32_t dst, uint32_t ncols) {
    asm volatile("tcgen05.alloc.cta_group::1.sync.aligned.shared::cta.b32 [%0], %1;"
                 :: "r"(dst), "r"(ncols) : "memory");
}
__device__ __forceinline__ void tmem_dealloc(uint32_t t, uint32_t ncols) {
    asm volatile("tcgen05.relinquish_alloc_permit.cta_group::1.sync.aligned;");
    asm volatile("tcgen05.dealloc.cta_group::1.sync.aligned.b32 %0, %1;" :: "r"(t), "r"(ncols));
}
__device__ __forceinline__ void tc_commit(uint32_t mbar) {
    asm volatile("tcgen05.commit.cta_group::1.mbarrier::arrive::one.shared::cluster.b64 [%0];"
                 :: "r"(mbar) : "memory");
}
__device__ __forceinline__ void mma_f16_ss(uint32_t d, uint64_t ad, uint64_t bd,
                                           uint32_t idesc, bool accum) {
    uint32_t en = accum ? 1u : 0u;
    asm volatile(
        "{\n\t.reg .pred p;\n\tsetp.ne.u32 p, %4, 0;\n\t"
        "tcgen05.mma.cta_group::1.kind::f16 [%0], %1, %2, %3, {%5, %5, %5, %5}, p;\n\t}"
        :: "r"(d), "l"(ad), "l"(bd), "r"(idesc), "r"(en), "r"(0u) : "memory");
}
__device__ __forceinline__ void cp16(uint32_t dst, const void* src) {
    asm volatile("cp.async.cg.shared.global [%0], [%1], 16;" :: "r"(dst), "l"(src));
}
#define CP_COMMIT() asm volatile("cp.async.commit_group;" ::: "memory")
#define CP_WAIT1()  asm volatile("cp.async.wait_group 1;" ::: "memory")
#define CP_WAIT0()  asm volatile("cp.async.wait_group 0;" ::: "memory")
#define TC_FENCE_AFTER()  asm volatile("tcgen05.fence::after_thread_sync;" ::: "memory")
#define TC_FENCE_BEFORE() asm volatile("tcgen05.fence::before_thread_sync;" ::: "memory")
#define PROXY_FENCE()     asm volatile("fence.proxy.async.shared::cta;" ::: "memory")
#define TC_WAIT_LD()      asm volatile("tcgen05.wait::ld.sync.aligned;" ::: "memory")

#define TC_LD_X32(r, addr) \
    asm volatile("tcgen05.ld.sync.aligned.32x32b.x32.b32 " \
        "{%0,%1,%2,%3,%4,%5,%6,%7,%8,%9,%10,%11,%12,%13,%14,%15," \
        "%16,%17,%18,%19,%20,%21,%22,%23,%24,%25,%26,%27,%28,%29,%30,%31}, [%32];" \
        : "=r"((r)[0]),"=r"((r)[1]),"=r"((r)[2]),"=r"((r)[3]), \
          "=r"((r)[4]),"=r"((r)[5]),"=r"((r)[6]),"=r"((r)[7]), \
          "=r"((r)[8]),"=r"((r)[9]),"=r"((r)[10]),"=r"((r)[11]), \
          "=r"((r)[12]),"=r"((r)[13]),"=r"((r)[14]),"=r"((r)[15]), \
          "=r"((r)[16]),"=r"((r)[17]),"=r"((r)[18]),"=r"((r)[19]), \
          "=r"((r)[20]),"=r"((r)[21]),"=r"((r)[22]),"=r"((r)[23]), \
          "=r"((r)[24]),"=r"((r)[25]),"=r"((r)[26]),"=r"((r)[27]), \
          "=r"((r)[28]),"=r"((r)[29]),"=r"((r)[30]),"=r"((r)[31]) \
        : "r"(addr))
#endif

static constexpr uint64_t DESC_BASE_SW128 =
    (uint64_t(2) << 61) | (uint64_t(1) << 46) | (uint64_t(64) << 32) | (uint64_t(1) << 16);
__device__ __forceinline__ uint64_t mk_desc(uint32_t addr) {
    return DESC_BASE_SW128 | ((uint64_t)(addr >> 4) & 0x3FFF);
}

// ============================================================
// main GEMM: CTA tile 128m x 256n, K-stage 64, pure cp.async producers.
// C[m][n] = sum_k A[m][k]*B[n][k], A/B pre-split bf16 hi/lo, fp32 out (UNSCALED).
// ============================================================
#define OFF_MBAR 0
#define OFF_TMEM 32
#define STG_B (96 * 1024)
#define OFF_BUF(s) (1024 + (s) * STG_B)
#define SMEM_NEED (1024 + 2 * STG_B + 1024)

static constexpr uint32_t IDESC =
    (1u << 4) | (1u << 7) | (1u << 10) | ((256 / 8) << 17) | ((128 / 16) << 24);

__global__ void __launch_bounds__(256) k_gemm(
    const bf16* __restrict__ Agh, const bf16* __restrict__ Agl, long sA, int lda,
    const bf16* __restrict__ Bgh, const bf16* __restrict__ Bgl, long sB, int ldb,
    float* __restrict__ Cg, long sC, int K)
{
    extern __shared__ char smraw[];
    char* sm = (char*)(((uintptr_t)smraw + 1023) & ~(uintptr_t)1023);
    const int tid = threadIdx.x, wid = tid >> 5, lid = tid & 31;
    const int b = blockIdx.z;
    const int m0 = blockIdx.y * 128, n0 = blockIdx.x * 256;
    const bf16* Ah = Agh + (long)b * sA + (long)m0 * lda;
    const bf16* Al = Agl + (long)b * sA + (long)m0 * lda;
    const bf16* Bh = Bgh + (long)b * sB + (long)n0 * ldb;
    const bf16* Bl = Bgl + (long)b * sB + (long)n0 * ldb;
    float* C = Cg + (long)b * sC;

#if HAS_TC
    const uint32_t sb = smem_u32(sm);
    if (tid == 0) { mbar_init(sb + OFF_MBAR, 1); mbar_init(sb + OFF_MBAR + 8, 1); }
    if (wid == 0) tmem_alloc(sb + OFF_TMEM, 256);
    __syncthreads();
    uint32_t tmem;
    asm volatile("ld.shared.b32 %0, [%1];" : "=r"(tmem) : "r"(sb + OFF_TMEM));

    const int nst = K / 64;
    // stage issue lambda
    auto issue = [&](int s) {
        const uint32_t bufb = sb + OFF_BUF(s & 1);
        const int k0 = s * 64;
#pragma unroll
        for (int i = 0; i < 4; i++) {           // A: 128 rows x 8 chunks
            int idx = tid + i * 256;
            int r = idx >> 3, ch = idx & 7;
            uint32_t d = bufb + (uint32_t)sw128(r * 128 + ch * 16);
            const long so = (long)r * lda + k0 + ch * 8;
            cp16(d, Ah + so);
            cp16(d + 16 * 1024, Al + so);
        }
#pragma unroll
        for (int i = 0; i < 8; i++) {           // B: 256 rows x 8 chunks
            int idx = tid + i * 256;
            int r = idx >> 3, ch = idx & 7;
            uint32_t d = bufb + 32 * 1024 + (uint32_t)sw128(r * 128 + ch * 16);
            const long so = (long)r * ldb + k0 + ch * 8;
            cp16(d, Bh + so);
            cp16(d + 32 * 1024, Bl + so);
        }
        CP_COMMIT();
    };

    issue(0);
    issue(1);
    int ph0 = 0, ph1 = 0;
    for (int s = 0; s < nst; s++) {
        const int buf = s & 1;
        if (s + 1 < nst) CP_WAIT1(); else CP_WAIT0();
        PROXY_FENCE();
        __syncthreads();
        if (wid == 0 && elect_one()) {
            const uint32_t bufb = sb + OFF_BUF(buf);
            uint64_t adh = mk_desc(bufb);
            uint64_t adl = mk_desc(bufb + 16 * 1024);
            uint64_t bdh = mk_desc(bufb + 32 * 1024);
            uint64_t bdl = mk_desc(bufb + 64 * 1024);
#pragma unroll
            for (int k = 0; k < 4; k++) {
                mma_f16_ss(tmem, adh + k * 2, bdh + k * 2, IDESC, !(s == 0 && k == 0));
                mma_f16_ss(tmem, adh + k * 2, bdl + k * 2, IDESC, true);
                mma_f16_ss(tmem, adl + k * 2, bdh + k * 2, IDESC, true);
            }
            tc_commit(sb + OFF_MBAR + buf * 8);
        }
        if (s + 2 < nst) {
            if (buf == 0) { mbar_wait(sb + OFF_MBAR, ph0); ph0 ^= 1; }
            else          { mbar_wait(sb + OFF_MBAR + 8, ph1); ph1 ^= 1; }
            issue(s + 2);
        }
    }
    mbar_wait(sb + OFF_MBAR, ph0);
    mbar_wait(sb + OFF_MBAR + 8, ph1);
    TC_FENCE_AFTER();
    // epilogue: 8 warps, warp w: rows=(w&3)*32+lane, col half=(w>>2)*128
    {
        const int row = (wid & 3) * 32 + lid;
        const int half = wid >> 2;
        float* dst = C + (long)(m0 + row) * AA + n0 + half * 128;
#pragma unroll
        for (int ch = 0; ch < 4; ch++) {
            uint32_t r[32];
            TC_LD_X32(r, tmem + half * 128 + ch * 32);
            TC_WAIT_LD();
#pragma unroll
            for (int j = 0; j < 32; j += 4) {
                float4 o = make_float4(__uint_as_float(r[j]),   __uint_as_float(r[j+1]),
                                       __uint_as_float(r[j+2]), __uint_as_float(r[j+3]));
                *(float4*)(dst + ch * 32 + j) = o;
            }
        }
        TC_FENCE_BEFORE();
    }
    __syncthreads();
    if (wid == 0) tmem_dealloc(tmem, 256);

#else  // ---------- wmma-from-global fallback (insurance only) ----------
    (void)sm;
    const int wm = wid >> 1, wn = wid & 1;   // 4x2 warps, warp tile 32x128
    for (int nc = 0; nc < 2; nc++) {
        wmma::fragment<wmma::accumulator, 16, 16, 16, float> acc[2][4];
#pragma unroll
        for (int i = 0; i < 2; i++)
#pragma unroll
            for (int j = 0; j < 4; j++) wmma::fill_fragment(acc[i][j], 0.f);
        for (int k0 = 0; k0 < K; k0 += 16) {
            wmma::fragment<wmma::matrix_a, 16, 16, 16, bf16, wmma::row_major> ah[2], al[2];
            wmma::fragment<wmma::matrix_b, 16, 16, 16, bf16, wmma::col_major> bh[4], bl[4];
#pragma unroll
            for (int i = 0; i < 2; i++) {
                long off = (long)(wm * 32 + i * 16) * lda + k0;
                wmma::load_matrix_sync(ah[i], Ah + off, lda);
                wmma::load_matrix_sync(al[i], Al + off, lda);
            }
#pragma unroll
            for (int j = 0; j < 4; j++) {
                long off = (long)(nc * 128 + wn * 64 + j * 16) * ldb + k0;
                wmma::load_matrix_sync(bh[j], Bh + off, ldb);
                wmma::load_matrix_sync(bl[j], Bl + off, ldb);
            }
#pragma unroll
            for (int i = 0; i < 2; i++)
#pragma unroll
                for (int j = 0; j < 4; j++) {
                    wmma::mma_sync(acc[i][j], ah[i], bh[j], acc[i][j]);
                    wmma::mma_sync(acc[i][j], ah[i], bl[j], acc[i][j]);
                    wmma::mma_sync(acc[i][j], al[i], bh[j], acc[i][j]);
                }
        }
#pragma unroll
        for (int i = 0; i < 2; i++)
#pragma unroll
            for (int j = 0; j < 4; j++)
                wmma::store_matrix_sync(C + (long)(m0 + wm * 32 + i * 16) * AA
                                          + n0 + nc * 128 + wn * 64 + j * 16,
                                        acc[i][j], AA, wmma::mem_row_major);
    }
#endif
}

// ============================================================
// exp + transpose + partial sums: reads S tile 128x128, writes
// E (straight) and ET (transposed) bf16 hi/lo, row/col partial sums.
// ============================================================
__global__ void __launch_bounds__(256) k_exp_trans() {
    extern __shared__ float tile[];   // [128][133]
    const int b = blockIdx.z;
    const int n0 = blockIdx.x * 128, a0 = blockIdx.y * 128;
    const int tid = threadIdx.x;
    const int r = tid >> 1, h = tid & 1;
    const long eoff = ((long)b * AA + a0 + r) * AA + n0 + h * 64;
    const float4* src = (const float4*)(g_S + eoff);
    float rsum = 0.f;
#pragma unroll
    for (int g = 0; g < 8; g++) {
        float4 v0 = __ldg(src + g * 2);
        float4 v1 = __ldg(src + g * 2 + 1);
        float e[8];
        e[0] = __expf(v0.x - 60.f); e[1] = __expf(v0.y - 60.f);
        e[2] = __expf(v0.z - 60.f); e[3] = __expf(v0.w - 60.f);
        e[4] = __expf(v1.x - 60.f); e[5] = __expf(v1.y - 60.f);
        e[6] = __expf(v1.z - 60.f); e[7] = __expf(v1.w - 60.f);
#pragma unroll
        for (int i = 0; i < 8; i++) {
            rsum += e[i];
            tile[r * 133 + h * 64 + g * 8 + i] = e[i];
        }
        uint4 H, L; split8(e, H, L);
        *(uint4*)(g_Eh + eoff + g * 8) = H;
        *(uint4*)(g_El + eoff + g * 8) = L;
    }
    rsum += __shfl_xor_sync(0xffffffffu, rsum, 1);
    if (h == 0) g_rp[((long)b * 32 + blockIdx.x) * AA + a0 + r] = rsum;
    __syncthreads();
    const int c = tid >> 1, hv = tid & 1;
    const long toff = ((long)b * AA + n0 + c) * AA + a0 + hv * 64;
    float csum = 0.f;
#pragma unroll
    for (int g = 0; g < 8; g++) {
        float e[8];
#pragma unroll
        for (int i = 0; i < 8; i++) {
            e[i] = tile[(hv * 64 + g * 8 + i) * 133 + c];
            csum += e[i];
        }
        uint4 H, L; split8(e, H, L);
        *(uint4*)(g_ETh + toff + g * 8) = H;
        *(uint4*)(g_ETl + toff + g * 8) = L;
    }
    csum += __shfl_xor_sync(0xffffffffu, csum, 1);
    if (hv == 0) g_cp[((long)b * 32 + blockIdx.y) * AA + n0 + c] = csum;
}

// ---- combine partial sums -> inverse sums ----
__global__ void __launch_bounds__(256) k_combine() {
    const int idx = blockIdx.x * 256 + threadIdx.x;   // [0, BB*AA)
    const int b = idx / AA, x = idx % AA;
    float rs = 0.f, cs = 0.f;
#pragma unroll
    for (int j = 0; j < 32; j++) {
        rs += g_rp[((long)b * 32 + j) * AA + x];
        cs += g_cp[((long)b * 32 + j) * AA + x];
    }
    g_irs[idx] = 1.f / rs;
    g_ics[idx] = 1.f / cs;
}

// ---- elementwise fp32 -> bf16 hi/lo split (8 vals/thread) ----
__global__ void __launch_bounds__(256) k_split(const float* __restrict__ in,
                                               bf16* __restrict__ oh,
                                               bf16* __restrict__ ol) {
    const long i8 = (long)blockIdx.x * 256 + threadIdx.x;
    float v[8];
    *(float4*)(v)     = __ldg((const float4*)in + i8 * 2);
    *(float4*)(v + 4) = __ldg((const float4*)in + i8 * 2 + 1);
    uint4 H, L; split8(v, H, L);
    *(uint4*)(oh + i8 * 8) = H;
    *(uint4*)(ol + i8 * 8) = L;
}

// ---- transpose + split: VaT h/l [b][a][c] from Va [b][c][a] ----
__global__ void __launch_bounds__(256) k_trans_split(const float* __restrict__ src) {
    __shared__ float t[32][33];
    const long b = blockIdx.z;
    const int a0 = blockIdx.x * 32, c0 = blockIdx.y * 32;
    const int x = threadIdx.x & 31, y = threadIdx.x >> 5;   // 32 x 8
#pragma unroll
    for (int i = 0; i < 32; i += 8)
        t[y + i][x] = src[(b * CC + c0 + y + i) * (long)AA + a0 + x];
    __syncthreads();
#pragma unroll
    for (int p = 0; p < 2; p++) {
        int idx = threadIdx.x + p * 256;
        int r = idx >> 4, cp = idx & 15;         // out row a, col pair
        float v0 = t[cp * 2][r], v1 = t[cp * 2 + 1][r];
        uint32_t hp = cvt2(v0, v1);
        float r0 = v0 - __uint_as_float(hp << 16);
        float r1 = v1 - __uint_as_float(hp & 0xFFFF0000u);
        uint32_t lp = cvt2(r0, r1);
        long o = (b * AA + a0 + r) * (long)CC + c0 + cp * 2;
        *(uint32_t*)(g_VaTh + o) = hp;
        *(uint32_t*)(g_VaTl + o) = lp;
    }
}

// ============================================================
// small wmma split GEMM: VbWf[b][n][c] = sum_d W[d][c] * Vb[b][d][n]
// ============================================================
__global__ void __launch_bounds__(256) k_vbwt(const float* __restrict__ Wl,
                                              const float* __restrict__ Vbg) {
    __shared__ bf16 Ash[5120], Asl[5120], Bsh[5120], Bsl[5120];
    const int tid = threadIdx.x;
    const long b = blockIdx.z;
    const int m0 = blockIdx.y * 128, n0 = blockIdx.x * 128;
    const float* Vb = Vbg + b * CC * AA;
    float* CT = g_VbWf + b * (long)AA * CC;

    wmma::fragment<wmma::accumulator, 16, 16, 16, float> acc[2][4];
#pragma unroll
    for (int i = 0; i < 2; i++)
#pragma unroll
        for (int j = 0; j < 4; j++) wmma::fill_fragment(acc[i][j], 0.f);
    const int wid = tid >> 5, wm = wid >> 1, wn = wid & 1;

    for (int k0 = 0; k0 < CC; k0 += 32) {
        __syncthreads();
#pragma unroll
        for (int r = 0; r < 16; r++) {
            int idx = tid + r * 256;
            int k = idx >> 7, m = idx & 127;
            float v = Wl[(long)(k0 + k) * CC + m0 + m];
            uint32_t hp = cvt2(v, 0.f);
            Ash[k * 136 + m] = __ushort_as_bfloat16((unsigned short)(hp & 0xFFFF));
            float rr = v - __uint_as_float(hp << 16);
            Asl[k * 136 + m] = __float2bfloat16(rr);
        }
#pragma unroll
        for (int r = 0; r < 16; r++) {
            int idx = tid + r * 256;
            int k = idx >> 7, n = idx & 127;
            float v = Vb[(long)(k0 + k) * AA + n0 + n];
            uint32_t hp = cvt2(v, 0.f);
            Bsh[k * 136 + n] = __ushort_as_bfloat16((unsigned short)(hp & 0xFFFF));
            float rr = v - __uint_as_float(hp << 16);
            Bsl[k * 136 + n] = __float2bfloat16(rr);
        }
        __syncthreads();
#pragma unroll
        for (int kk = 0; kk < 32; kk += 16) {
            wmma::fragment<wmma::matrix_a, 16, 16, 16, bf16, wmma::col_major> ah[2], al[2];
            wmma::fragment<wmma::matrix_b, 16, 16, 16, bf16, wmma::row_major> bh[4], bl[4];
#pragma unroll
            for (int i = 0; i < 2; i++) {
                int off = kk * 136 + wm * 32 + i * 16;
                wmma::load_matrix_sync(ah[i], Ash + off, 136);
                wmma::load_matrix_sync(al[i], Asl + off, 136);
            }
#pragma unroll
            for (int j = 0; j < 4; j++) {
                int off = kk * 136 + wn * 64 + j * 16;
                wmma::load_matrix_sync(bh[j], Bsh + off, 136);
                wmma::load_matrix_sync(bl[j], Bsl + off, 136);
            }
#pragma unroll
            for (int i = 0; i < 2; i++)
#pragma unroll
                for (int j = 0; j < 4; j++) {
                    wmma::mma_sync(acc[i][j], ah[i], bh[j], acc[i][j]);
                    wmma::mma_sync(acc[i][j], ah[i], bl[j], acc[i][j]);
                    wmma::mma_sync(acc[i][j], al[i], bh[j], acc[i][j]);
                }
        }
    }
#pragma unroll
    for (int i = 0; i < 2; i++)
#pragma unroll
        for (int j = 0; j < 4; j++) {
            long n_g = n0 + wn * 64 + j * 16;
            long m_g = m0 + wm * 32 + i * 16;
            wmma::store_matrix_sync(CT + n_g * CC + m_g, acc[i][j], CC, wmma::mem_col_major);
        }
}

// ---- gate + normalize + in-place scale + concat-copy ----
__global__ void __launch_bounds__(256) k_gate_concat(const float* __restrict__ Wg,
                                                     const float* __restrict__ Va,
                                                     const float* __restrict__ Vb) {
    extern __shared__ float smo[];   // unused; keep static
    const int side = blockIdx.z, b = blockIdx.y;
    const int n = blockIdx.x * 256 + threadIdx.x;
    const float* orig = (side ? Vb : Va) + (long)b * CC * AA + n;
    const float isn = (side ? g_irs : g_ics)[b * AA + n];
    float* att;
    {
        extern __device__ float g_out_dummy[];  // placeholder (not used)
    }
    // out pointer passed via constant below
    att = nullptr;
    (void)att; (void)orig; (void)isn; (void)smo;
}

// real gate kernel (out passed as arg)
__global__ void __launch_bounds__(256) k_gate(const float* __restrict__ Wg,
                                              const float* __restrict__ Va,
                                              const float* __restrict__ Vb,
                                              float* __restrict__ out) {
    const int side = blockIdx.z, b = blockIdx.y;
    const int n = blockIdx.x * 256 + threadIdx.x;
    const float* orig = (side ? Vb : Va) + (long)b * CC * AA + n;
    const float isn = (side ? g_irs : g_ics)[b * AA + n];
    float* att = out + ((long)(side * BB + b)) * (2L * CC * AA) + n;
    float dot = 0.f;
    float vals[8];
    // first pass: normalize + dot, cache nothing (stream twice)
#pragma unroll 4
    for (int c = 0; c < CC; c++) dot = fmaf(att[(long)c * AA] * isn, Wg[c], dot);
    float mask = isn / (1.f + __expf(-dot));   // fold isn into mask
#pragma unroll 4
    for (int c = 0; c < CC; c++) {
        att[(long)c * AA] *= mask;
        att[(long)(c + CC) * AA] = orig[(long)c * AA];
    }
    (void)vals;
}

__global__ void k_tail(float* __restrict__ out, long start, long total,
                       const int* __restrict__ isz) {
    long i = start + blockIdx.x * 256L + threadIdx.x;
    if (i < total) out[i] = (float)(*isz);
}

extern "C" void kernel_launch(void* const* d_in, const int* in_sizes, int n_in,
                              void* d_out, int out_size) {
    const float* Va = (const float*)d_in[0];
    const float* Vb = (const float*)d_in[1];
    const float* Wl = (const float*)d_in[2];
    const float* Wg = (const float*)d_in[3];
    const int* isz = (const int*)d_in[4];
    float* out = (float*)d_out;

    float *S, *VbWf;
    bf16 *VaH, *VaL, *VbH, *VbL, *VaTh, *VaTl, *VbWTh, *VbWTl, *Eh, *El, *ETh, *ETl;
    cudaGetSymbolAddress((void**)&S, g_S);
    cudaGetSymbolAddress((void**)&VbWf, g_VbWf);
    cudaGetSymbolAddress((void**)&VaH, g_VaH);  cudaGetSymbolAddress((void**)&VaL, g_VaL);
    cudaGetSymbolAddress((void**)&VbH, g_VbH);  cudaGetSymbolAddress((void**)&VbL, g_VbL);
    cudaGetSymbolAddress((void**)&VaTh, g_VaTh); cudaGetSymbolAddress((void**)&VaTl, g_VaTl);
    cudaGetSymbolAddress((void**)&VbWTh, g_VbWTh); cudaGetSymbolAddress((void**)&VbWTl, g_VbWTl);
    cudaGetSymbolAddress((void**)&Eh, g_Eh);   cudaGetSymbolAddress((void**)&El, g_El);
    cudaGetSymbolAddress((void**)&ETh, g_ETh); cudaGetSymbolAddress((void**)&ETl, g_ETl);

    cudaFuncSetAttribute(k_gemm, cudaFuncAttributeMaxDynamicSharedMemorySize, SMEM_NEED);
    cudaFuncSetAttribute(k_exp_trans, cudaFuncAttributeMaxDynamicSharedMemorySize,
                         128 * 133 * 4);

    const long NCA = (long)BB * CC * AA;

    // 1) pre-split operands
    k_split<<<(unsigned)(NCA / 2048), 256>>>(Va, VaH, VaL);
    k_split<<<(unsigned)(NCA / 2048), 256>>>(Vb, VbH, VbL);
    k_trans_split<<<dim3(AA / 32, CC / 32, BB), 256>>>(Va);
    // 2) VbWf[n][c] then split
    k_vbwt<<<dim3(AA / 128, CC / 128, BB), 256>>>(Wl, Vb);
    k_split<<<(unsigned)(NCA / 2048), 256>>>(VbWf, VbWTh, VbWTl);
    // 3) S[a][n] = sum_c VaT[a][c] * VbWT[n][c]
    k_gemm<<<dim3(AA / 256, AA / 128, BB), 256, SMEM_NEED>>>(
        VaTh, VaTl, (long)AA * CC, CC,
        VbWTh, VbWTl, (long)AA * CC, CC,
        S, (long)AA * AA, CC);
    // 4) E = exp(S-60), ET = E^T, partial sums
    k_exp_trans<<<dim3(AA / 128, AA / 128, BB), 256, 128 * 133 * 4>>>();
    k_combine<<<BB * AA / 256, 256>>>();
    // 5) Va_att_unscaled[c][n] = sum_a Vb[c][a] * ET[n][a]   -> out[0:B]
    k_gemm<<<dim3(AA / 256, CC / 128, BB), 256, SMEM_NEED>>>(
        VbH, VbL, (long)CC * AA, AA,
        ETh, ETl, (long)AA * AA, AA,
        out, 2L * CC * AA, AA);
    // 6) Vb_att_unscaled[c][n] = sum_a Va[c][a] * E[n][a]    -> out[B:2B]
    k_gemm<<<dim3(AA / 256, CC / 128, BB), 256, SMEM_NEED>>>(
        VaH, VaL, (long)CC * AA, AA,
        Eh, El, (long)AA * AA, AA,
        out + (long)BB * 2 * CC * AA, 2L * CC * AA, AA);
    // 7) gate: normalize + mask + concat
    k_gate<<<dim3(AA / 256, BB, 2), 256>>>(Wg, Va, Vb, out);
    // 8) optional tail
    long main_elems = 2L * BB * 2 * CC * AA;
    if ((long)out_size > main_elems) {
        long rem = (long)out_size - main_elems;
        k_tail<<<(unsigned)((rem + 255) / 256), 256>>>(out, main_elems, out_size, isz);
    }
}

// round 7
// speedup vs baseline: 5.4701x; 1.1778x over previous
#include <cuda_runtime.h>
#include <cuda_bf16.h>
#include <mma.h>
#include <math_constants.h>
#include <cstdint>

using namespace nvcuda;
typedef __nv_bfloat16 bf16;

#define BB 4
#define CC 256
#define AA 4096

#if defined(__CUDA_ARCH_FEAT_SM103_ALL) || defined(__CUDA_ARCH_FEAT_SM100_ALL) || \
    defined(__CUDA_ARCH_FEAT_SM101_ALL) || defined(__CUDA_ARCH_FEAT_SM110_ALL)
#define HAS_TC 1
#else
#define HAS_TC 0
#endif

// ---- device scratch ----
__device__ __align__(1024) bf16  g_Eh [(long)BB * AA * AA];    // exp(S-60) hi
__device__ __align__(1024) bf16  g_El [(long)BB * AA * AA];
__device__ __align__(1024) bf16  g_ETh[(long)BB * AA * AA];    // transposed
__device__ __align__(1024) bf16  g_ETl[(long)BB * AA * AA];
__device__ __align__(1024) bf16  g_VaH[(long)BB * CC * AA], g_VaL[(long)BB * CC * AA];
__device__ __align__(1024) bf16  g_VbH[(long)BB * CC * AA], g_VbL[(long)BB * CC * AA];
__device__ __align__(1024) bf16  g_VaTh[(long)BB * AA * CC], g_VaTl[(long)BB * AA * CC];
__device__ __align__(1024) bf16  g_VbTh[(long)BB * AA * CC], g_VbTl[(long)BB * AA * CC];
__device__ __align__(1024) bf16  g_VbWTh[(long)BB * AA * CC], g_VbWTl[(long)BB * AA * CC];
__device__ __align__(1024) bf16  g_WTh[CC * CC], g_WTl[CC * CC];
__device__ float g_rp[(long)BB * 16 * AA], g_cp[(long)BB * 32 * AA];
__device__ float g_irs[BB * AA], g_ics[BB * AA];

// ============================================================
// helpers
// ============================================================
__device__ __forceinline__ uint32_t smem_u32(const void* p) {
    uint32_t a;
    asm("{ .reg .u64 t; cvta.to.shared.u64 t, %1; cvt.u32.u64 %0, t; }" : "=r"(a) : "l"(p));
    return a;
}
__device__ __forceinline__ uint32_t cvt2(float lo, float hi) {
    uint32_t r;
    asm("cvt.rn.bf16x2.f32 %0, %1, %2;" : "=r"(r) : "f"(hi), "f"(lo));
    return r;
}
__device__ __forceinline__ void split8(const float* v, uint4& H, uint4& L) {
    uint32_t h[4], l[4];
#pragma unroll
    for (int i = 0; i < 4; i++) {
        float a = v[2 * i], b = v[2 * i + 1];
        h[i] = cvt2(a, b);
        float ar = a - __uint_as_float(h[i] << 16);
        float br = b - __uint_as_float(h[i] & 0xFFFF0000u);
        l[i] = cvt2(ar, br);
    }
    H = make_uint4(h[0], h[1], h[2], h[3]);
    L = make_uint4(l[0], l[1], l[2], l[3]);
}
__device__ __forceinline__ int sw128(int off) { return off ^ ((off >> 3) & 0x70); }

#if HAS_TC
__device__ __forceinline__ uint32_t elect_one() {
    uint32_t p;
    asm volatile("{ .reg .pred p; elect.sync _|p, 0xFFFFFFFF; selp.b32 %0, 1, 0, p; }" : "=r"(p));
    return p;
}
__device__ __forceinline__ void mbar_init(uint32_t m, uint32_t cnt) {
    asm volatile("mbarrier.init.shared.b64 [%0], %1;" :: "r"(m), "r"(cnt) : "memory");
}
__device__ __forceinline__ void mbar_wait(uint32_t m, uint32_t par) {
    asm volatile(
        "{\n\t.reg .pred P;\n\t"
        "W_%=:\n\t"
        "mbarrier.try_wait.parity.acquire.cta.shared::cta.b64 P, [%0], %1, 0x989680;\n\t"
        "@P bra.uni D_%=;\n\t"
        "bra.uni W_%=;\n\t"
        "D_%=:\n\t}"
        :: "r"(m), "r"(par) : "memory");
}
__device__ __forceinline__ void tmem_alloc(uint32_t dst, uint32_t ncols) {
    asm volatile("tcgen05.alloc.cta_group::1.sync.aligned.shared::cta.b32 [%0], %1;"
                 :: "r"(dst), "r"(ncols) : "memory");
}
__device__ __forceinline__ void tmem_dealloc(uint32_t t, uint32_t ncols) {
    asm volatile("tcgen05.relinquish_alloc_permit.cta_group::1.sync.aligned;");
    asm volatile("tcgen05.dealloc.cta_group::1.sync.aligned.b32 %0, %1;" :: "r"(t), "r"(ncols));
}
__device__ __forceinline__ void tc_commit(uint32_t mbar) {
    asm volatile("tcgen05.commit.cta_group::1.mbarrier::arrive::one.shared::cluster.b64 [%0];"
                 :: "r"(mbar) : "memory");
}
__device__ __forceinline__ void mma_f16_ss(uint32_t d, uint64_t ad, uint64_t bd,
                                           uint32_t idesc, bool accum) {
    uint32_t en = accum ? 1u : 0u;
    asm volatile(
        "{\n\t.reg .pred p;\n\tsetp.ne.u32 p, %4, 0;\n\t"
        "tcgen05.mma.cta_group::1.kind::f16 [%0], %1, %2, %3, {%5, %5, %5, %5}, p;\n\t}"
        :: "r"(d), "l"(ad), "l"(bd), "r"(idesc), "r"(en), "r"(0u) : "memory");
}
__device__ __forceinline__ void cp16(uint32_t dst, const void* src) {
    asm volatile("cp.async.cg.shared.global [%0], [%1], 16;" :: "r"(dst), "l"(src));
}
#define CP_COMMIT() asm volatile("cp.async.commit_group;" ::: "memory")
#define CP_WAIT1()  asm volatile("cp.async.wait_group 1;" ::: "memory")
#define CP_WAIT0()  asm volatile("cp.async.wait_group 0;" ::: "memory")
#define TC_FENCE_AFTER()  asm volatile("tcgen05.fence::after_thread_sync;" ::: "memory")
#define TC_FENCE_BEFORE() asm volatile("tcgen05.fence::before_thread_sync;" ::: "memory")
#define PROXY_FENCE()     asm volatile("fence.proxy.async.shared::cta;" ::: "memory")
#define TC_WAIT_LD()      asm volatile("tcgen05.wait::ld.sync.aligned;" ::: "memory")

#define TC_LD_X32(r, addr) \
    asm volatile("tcgen05.ld.sync.aligned.32x32b.x32.b32 " \
        "{%0,%1,%2,%3,%4,%5,%6,%7,%8,%9,%10,%11,%12,%13,%14,%15," \
        "%16,%17,%18,%19,%20,%21,%22,%23,%24,%25,%26,%27,%28,%29,%30,%31}, [%32];" \
        : "=r"((r)[0]),"=r"((r)[1]),"=r"((r)[2]),"=r"((r)[3]), \
          "=r"((r)[4]),"=r"((r)[5]),"=r"((r)[6]),"=r"((r)[7]), \
          "=r"((r)[8]),"=r"((r)[9]),"=r"((r)[10]),"=r"((r)[11]), \
          "=r"((r)[12]),"=r"((r)[13]),"=r"((r)[14]),"=r"((r)[15]), \
          "=r"((r)[16]),"=r"((r)[17]),"=r"((r)[18]),"=r"((r)[19]), \
          "=r"((r)[20]),"=r"((r)[21]),"=r"((r)[22]),"=r"((r)[23]), \
          "=r"((r)[24]),"=r"((r)[25]),"=r"((r)[26]),"=r"((r)[27]), \
          "=r"((r)[28]),"=r"((r)[29]),"=r"((r)[30]),"=r"((r)[31]) \
        : "r"(addr))
#endif

static constexpr uint64_t DESC_BASE_SW128 =
    (uint64_t(2) << 61) | (uint64_t(1) << 46) | (uint64_t(64) << 32) | (uint64_t(1) << 16);
__device__ __forceinline__ uint64_t mk_desc(uint32_t addr) {
    return DESC_BASE_SW128 | ((uint64_t)(addr >> 4) & 0x3FFF);
}

// ============================================================
// main GEMM: CTA tile 128m x 256n, K-stage 64, pure cp.async producers.
// C[m][n] = sum_k A[m][k]*B[n][k], A/B pre-split bf16 hi/lo.
// EPI 0: fp32 store to Cf (ldc)
// EPI 1: bf16 hi/lo split store to Coh/Col (ldc)
// EPI 2: exp(x-60) -> E/ET bf16 hi/lo + row/col partial sums
// ============================================================
#define OFF_MBAR 0
#define OFF_TMEM 32
#define STG_B (96 * 1024)
#define OFF_BUF(s) (1024 + (s) * STG_B)
#define SMEM_NEED (1024 + 2 * STG_B + 1024)
#define TLD 257

static constexpr uint32_t IDESC =
    (1u << 4) | (1u << 7) | (1u << 10) | ((256 / 8) << 17) | ((128 / 16) << 24);

// common EPI-2 tile epilogue: tile holds fp32 S values [128][TLD]
__device__ __forceinline__ void epi_exp(float* tile, int b, int m0, int n0,
                                        int bx, int by, int tid) {
    // phase a: exp + E store + row sums (thread t: row r=t>>1, half h=t&1)
    {
        const int r = tid >> 1, h = tid & 1;
        float* trow = tile + r * TLD + h * 128;
        float rsum = 0.f;
#pragma unroll
        for (int g = 0; g < 16; g++) {
            float e[8];
#pragma unroll
            for (int i = 0; i < 8; i++) {
                e[i] = __expf(trow[g * 8 + i] - 60.f);
                rsum += e[i];
                trow[g * 8 + i] = e[i];
            }
            uint4 H, L; split8(e, H, L);
            const long off = ((long)b * AA + m0 + r) * AA + n0 + h * 128 + g * 8;
            *(uint4*)(g_Eh + off) = H;
            *(uint4*)(g_El + off) = L;
        }
        rsum += __shfl_xor_sync(0xffffffffu, rsum, 1);
        if (h == 0) g_rp[((long)b * 16 + bx) * AA + m0 + r] = rsum;
    }
    __syncthreads();
    // phase b: ET store + col sums (thread t: column n=t)
    {
        const int n = tid;
        float csum = 0.f;
#pragma unroll
        for (int g = 0; g < 16; g++) {
            float e[8];
#pragma unroll
            for (int i = 0; i < 8; i++) {
                e[i] = tile[(g * 8 + i) * TLD + n];
                csum += e[i];
            }
            uint4 H, L; split8(e, H, L);
            const long off = ((long)b * AA + n0 + n) * AA + m0 + g * 8;
            *(uint4*)(g_ETh + off) = H;
            *(uint4*)(g_ETl + off) = L;
        }
        g_cp[((long)b * 32 + by) * AA + n0 + n] = csum;
    }
}

template<int EPI>
__global__ void __launch_bounds__(256) k_gemm(
    const bf16* __restrict__ Agh, const bf16* __restrict__ Agl, long sA, int lda,
    const bf16* __restrict__ Bgh, const bf16* __restrict__ Bgl, long sB, int ldb,
    float* __restrict__ Cf, bf16* __restrict__ Coh, bf16* __restrict__ Col,
    long sC, int ldc, int K)
{
    extern __shared__ char smraw[];
    char* sm = (char*)(((uintptr_t)smraw + 1023) & ~(uintptr_t)1023);
    float* tile = (float*)(sm + 1024);    // reuses pipeline buffers post-mainloop
    const int tid = threadIdx.x, wid = tid >> 5, lid = tid & 31;
    const int b = blockIdx.z;
    const int m0 = blockIdx.y * 128, n0 = blockIdx.x * 256;
    const bf16* Ah = Agh + (long)b * sA + (long)m0 * lda;
    const bf16* Al = Agl + (long)b * sA + (long)m0 * lda;
    const bf16* Bh = Bgh + (long)b * sB + (long)n0 * ldb;
    const bf16* Bl = Bgl + (long)b * sB + (long)n0 * ldb;

#if HAS_TC
    const uint32_t sb = smem_u32(sm);
    if (tid == 0) { mbar_init(sb + OFF_MBAR, 1); mbar_init(sb + OFF_MBAR + 8, 1); }
    if (wid == 0) tmem_alloc(sb + OFF_TMEM, 256);
    __syncthreads();
    uint32_t tmem;
    asm volatile("ld.shared.b32 %0, [%1];" : "=r"(tmem) : "r"(sb + OFF_TMEM));

    const int nst = K / 64;
    auto issue = [&](int s) {
        const uint32_t bufb = sb + OFF_BUF(s & 1);
        const int k0 = s * 64;
#pragma unroll
        for (int i = 0; i < 4; i++) {           // A: 128 rows x 8 chunks
            int idx = tid + i * 256;
            int r = idx >> 3, ch = idx & 7;
            uint32_t d = bufb + (uint32_t)sw128(r * 128 + ch * 16);
            const long so = (long)r * lda + k0 + ch * 8;
            cp16(d, Ah + so);
            cp16(d + 16 * 1024, Al + so);
        }
#pragma unroll
        for (int i = 0; i < 8; i++) {           // B: 256 rows x 8 chunks
            int idx = tid + i * 256;
            int r = idx >> 3, ch = idx & 7;
            uint32_t d = bufb + 32 * 1024 + (uint32_t)sw128(r * 128 + ch * 16);
            const long so = (long)r * ldb + k0 + ch * 8;
            cp16(d, Bh + so);
            cp16(d + 32 * 1024, Bl + so);
        }
        CP_COMMIT();
    };

    issue(0);
    issue(1);
    int ph0 = 0, ph1 = 0;
    for (int s = 0; s < nst; s++) {
        const int buf = s & 1;
        if (s + 1 < nst) CP_WAIT1(); else CP_WAIT0();
        PROXY_FENCE();
        __syncthreads();
        if (wid == 0 && elect_one()) {
            const uint32_t bufb = sb + OFF_BUF(buf);
            uint64_t adh = mk_desc(bufb);
            uint64_t adl = mk_desc(bufb + 16 * 1024);
            uint64_t bdh = mk_desc(bufb + 32 * 1024);
            uint64_t bdl = mk_desc(bufb + 64 * 1024);
#pragma unroll
            for (int k = 0; k < 4; k++) {
                mma_f16_ss(tmem, adh + k * 2, bdh + k * 2, IDESC, !(s == 0 && k == 0));
                mma_f16_ss(tmem, adh + k * 2, bdl + k * 2, IDESC, true);
                mma_f16_ss(tmem, adl + k * 2, bdh + k * 2, IDESC, true);
            }
            tc_commit(sb + OFF_MBAR + buf * 8);
        }
        if (s + 2 < nst) {
            if (buf == 0) { mbar_wait(sb + OFF_MBAR, ph0); ph0 ^= 1; }
            else          { mbar_wait(sb + OFF_MBAR + 8, ph1); ph1 ^= 1; }
            issue(s + 2);
        }
    }
    mbar_wait(sb + OFF_MBAR, ph0);
    mbar_wait(sb + OFF_MBAR + 8, ph1);
    TC_FENCE_AFTER();

    // ---- epilogue: 8 warps, warp w: rows=(w&3)*32+lid, col half=(w>>2)*128 ----
    {
        const int row = (wid & 3) * 32 + lid;
        const int half = wid >> 2;
#pragma unroll
        for (int ch = 0; ch < 4; ch++) {
            uint32_t r[32];
            TC_LD_X32(r, tmem + half * 128 + ch * 32);
            TC_WAIT_LD();
            if (EPI == 0) {
                float* dst = Cf + (long)b * sC + (long)(m0 + row) * ldc
                             + n0 + half * 128 + ch * 32;
#pragma unroll
                for (int j = 0; j < 32; j += 4) {
                    float4 o = make_float4(__uint_as_float(r[j]),   __uint_as_float(r[j+1]),
                                           __uint_as_float(r[j+2]), __uint_as_float(r[j+3]));
                    *(float4*)(dst + j) = o;
                }
            } else if (EPI == 1) {
                const long off = (long)b * sC + (long)(m0 + row) * ldc
                                 + n0 + half * 128 + ch * 32;
#pragma unroll
                for (int g = 0; g < 4; g++) {
                    float e[8];
#pragma unroll
                    for (int i = 0; i < 8; i++) e[i] = __uint_as_float(r[g * 8 + i]);
                    uint4 H, L; split8(e, H, L);
                    *(uint4*)(Coh + off + g * 8) = H;
                    *(uint4*)(Col + off + g * 8) = L;
                }
            } else {
                float* trow = tile + row * TLD + half * 128 + ch * 32;
#pragma unroll
                for (int j = 0; j < 32; j++) trow[j] = __uint_as_float(r[j]);
            }
        }
        TC_FENCE_BEFORE();
    }
    __syncthreads();
    if (wid == 0) tmem_dealloc(tmem, 256);
    if (EPI == 2) {
        __syncthreads();
        epi_exp(tile, b, m0, n0, blockIdx.x, blockIdx.y, tid);
    }

#else  // ---------- wmma fallback (insurance only) ----------
    float* scratch = tile + 128 * TLD;   // 8 warps x 256 floats
    const int wm = wid >> 1, wn = wid & 1;
    for (int nc = 0; nc < 2; nc++) {
        wmma::fragment<wmma::accumulator, 16, 16, 16, float> acc[2][4];
#pragma unroll
        for (int i = 0; i < 2; i++)
#pragma unroll
            for (int j = 0; j < 4; j++) wmma::fill_fragment(acc[i][j], 0.f);
        for (int k0 = 0; k0 < K; k0 += 16) {
            wmma::fragment<wmma::matrix_a, 16, 16, 16, bf16, wmma::row_major> ah, al;
            wmma::fragment<wmma::matrix_b, 16, 16, 16, bf16, wmma::col_major> bh, bl;
#pragma unroll
            for (int i = 0; i < 2; i++) {
                long offA = (long)(wm * 32 + i * 16) * lda + k0;
                wmma::load_matrix_sync(ah, Ah + offA, lda);
                wmma::load_matrix_sync(al, Al + offA, lda);
#pragma unroll
                for (int j = 0; j < 4; j++) {
                    long offB = (long)(nc * 128 + wn * 64 + j * 16) * ldb + k0;
                    wmma::load_matrix_sync(bh, Bh + offB, ldb);
                    wmma::load_matrix_sync(bl, Bl + offB, ldb);
                    wmma::mma_sync(acc[i][j], ah, bh, acc[i][j]);
                    wmma::mma_sync(acc[i][j], ah, bl, acc[i][j]);
                    wmma::mma_sync(acc[i][j], al, bh, acc[i][j]);
                }
            }
        }
        if (EPI == 0) {
#pragma unroll
            for (int i = 0; i < 2; i++)
#pragma unroll
                for (int j = 0; j < 4; j++)
                    wmma::store_matrix_sync(Cf + (long)b * sC
                                            + (long)(m0 + wm * 32 + i * 16) * ldc
                                            + n0 + nc * 128 + wn * 64 + j * 16,
                                            acc[i][j], ldc, wmma::mem_row_major);
        } else {
            // stage via per-warp scratch into tile
#pragma unroll
            for (int i = 0; i < 2; i++)
#pragma unroll
                for (int j = 0; j < 4; j++) {
                    wmma::store_matrix_sync(scratch + wid * 256, acc[i][j], 16,
                                            wmma::mem_row_major);
                    __syncwarp();
#pragma unroll
                    for (int e = 0; e < 8; e++) {
                        int idx = lid + e * 32;
                        int rr = idx >> 4, cc = idx & 15;
                        tile[(wm * 32 + i * 16 + rr) * TLD
                             + nc * 128 + wn * 64 + j * 16 + cc] =
                            scratch[wid * 256 + rr * 16 + cc];
                    }
                    __syncwarp();
                }
        }
    }
    if (EPI == 1) {
        __syncthreads();
        const int r = tid >> 1, h = tid & 1;
        const long off0 = (long)b * sC + (long)(m0 + r) * ldc + n0 + h * 128;
#pragma unroll
        for (int g = 0; g < 16; g++) {
            float e[8];
#pragma unroll
            for (int i = 0; i < 8; i++) e[i] = tile[r * TLD + h * 128 + g * 8 + i];
            uint4 H, L; split8(e, H, L);
            *(uint4*)(Coh + off0 + g * 8) = H;
            *(uint4*)(Col + off0 + g * 8) = L;
        }
    } else if (EPI == 2) {
        __syncthreads();
        epi_exp(tile, b, m0, n0, blockIdx.x, blockIdx.y, tid);
    }
#endif
}

// ---- combine partial sums -> inverse sums ----
__global__ void __launch_bounds__(256) k_combine() {
    const int idx = blockIdx.x * 256 + threadIdx.x;
    const int b = idx / AA, x = idx % AA;
    float rs = 0.f, cs = 0.f;
#pragma unroll
    for (int j = 0; j < 16; j++) rs += g_rp[((long)b * 16 + j) * AA + x];
#pragma unroll
    for (int j = 0; j < 32; j++) cs += g_cp[((long)b * 32 + j) * AA + x];
    g_irs[idx] = 1.f / rs;
    g_ics[idx] = 1.f / cs;
}

// ---- elementwise fp32 -> bf16 hi/lo split ----
__global__ void __launch_bounds__(256) k_split(const float* __restrict__ in,
                                               bf16* __restrict__ oh,
                                               bf16* __restrict__ ol) {
    const long i8 = (long)blockIdx.x * 256 + threadIdx.x;
    float v[8];
    *(float4*)(v)     = __ldg((const float4*)in + i8 * 2);
    *(float4*)(v + 4) = __ldg((const float4*)in + i8 * 2 + 1);
    uint4 H, L; split8(v, H, L);
    *(uint4*)(oh + i8 * 8) = H;
    *(uint4*)(ol + i8 * 8) = L;
}

// ---- generic transpose + split: src[b][r][c] ([R][Cc]) -> out[b][c][r] ----
__global__ void __launch_bounds__(256) k_tsplit(const float* __restrict__ src,
                                                bf16* __restrict__ oh,
                                                bf16* __restrict__ ol,
                                                int R, int Cc, long sbatch) {
    __shared__ float t[32][33];
    const long b = blockIdx.z;
    const int c0 = blockIdx.x * 32, r0 = blockIdx.y * 32;
    const float* s = src + b * sbatch;
    bf16* doh = oh + b * sbatch;
    bf16* dol = ol + b * sbatch;
    const int x = threadIdx.x & 31, y = threadIdx.x >> 5;
#pragma unroll
    for (int i = 0; i < 32; i += 8)
        t[y + i][x] = s[(long)(r0 + y + i) * Cc + c0 + x];
    __syncthreads();
#pragma unroll
    for (int p = 0; p < 2; p++) {
        int idx = threadIdx.x + p * 256;
        int orow = idx >> 4, cp = idx & 15;
        float v0 = t[cp * 2][orow], v1 = t[cp * 2 + 1][orow];
        uint32_t hp = cvt2(v0, v1);
        float q0 = v0 - __uint_as_float(hp << 16);
        float q1 = v1 - __uint_as_float(hp & 0xFFFF0000u);
        uint32_t lp = cvt2(q0, q1);
        long o = (long)(c0 + orow) * R + r0 + cp * 2;
        *(uint32_t*)(doh + o) = hp;
        *(uint32_t*)(dol + o) = lp;
    }
}

// ---- gate + normalize + in-place scale + concat-copy ----
__global__ void __launch_bounds__(256) k_gate(const float* __restrict__ Wg,
                                              const float* __restrict__ Va,
                                              const float* __restrict__ Vb,
                                              float* __restrict__ out) {
    const int side = blockIdx.z, b = blockIdx.y;
    const int n = blockIdx.x * 256 + threadIdx.x;
    const float* orig = (side ? Vb : Va) + (long)b * CC * AA + n;
    const float isn = (side ? g_irs : g_ics)[b * AA + n];
    float* att = out + ((long)(side * BB + b)) * (2L * CC * AA) + n;
    float dot = 0.f;
#pragma unroll 4
    for (int c = 0; c < CC; c++) dot = fmaf(att[(long)c * AA] * isn, Wg[c], dot);
    float mask = isn / (1.f + __expf(-dot));
#pragma unroll 4
    for (int c = 0; c < CC; c++) {
        att[(long)c * AA] *= mask;
        att[(long)(c + CC) * AA] = orig[(long)c * AA];
    }
}

__global__ void k_tail(float* __restrict__ out, long start, long total,
                       const int* __restrict__ isz) {
    long i = start + blockIdx.x * 256L + threadIdx.x;
    if (i < total) out[i] = (float)(*isz);
}

extern "C" void kernel_launch(void* const* d_in, const int* in_sizes, int n_in,
                              void* d_out, int out_size) {
    const float* Va = (const float*)d_in[0];
    const float* Vb = (const float*)d_in[1];
    const float* Wl = (const float*)d_in[2];
    const float* Wg = (const float*)d_in[3];
    const int* isz = (const int*)d_in[4];
    float* out = (float*)d_out;

    bf16 *VaH, *VaL, *VbH, *VbL, *VaTh, *VaTl, *VbTh, *VbTl;
    bf16 *VbWTh, *VbWTl, *WTh, *WTl, *Eh, *El, *ETh, *ETl;
    cudaGetSymbolAddress((void**)&VaH, g_VaH);   cudaGetSymbolAddress((void**)&VaL, g_VaL);
    cudaGetSymbolAddress((void**)&VbH, g_VbH);   cudaGetSymbolAddress((void**)&VbL, g_VbL);
    cudaGetSymbolAddress((void**)&VaTh, g_VaTh); cudaGetSymbolAddress((void**)&VaTl, g_VaTl);
    cudaGetSymbolAddress((void**)&VbTh, g_VbTh); cudaGetSymbolAddress((void**)&VbTl, g_VbTl);
    cudaGetSymbolAddress((void**)&VbWTh, g_VbWTh); cudaGetSymbolAddress((void**)&VbWTl, g_VbWTl);
    cudaGetSymbolAddress((void**)&WTh, g_WTh);   cudaGetSymbolAddress((void**)&WTl, g_WTl);
    cudaGetSymbolAddress((void**)&Eh, g_Eh);     cudaGetSymbolAddress((void**)&El, g_El);
    cudaGetSymbolAddress((void**)&ETh, g_ETh);   cudaGetSymbolAddress((void**)&ETl, g_ETl);

    cudaFuncSetAttribute(k_gemm<0>, cudaFuncAttributeMaxDynamicSharedMemorySize, SMEM_NEED);
    cudaFuncSetAttribute(k_gemm<1>, cudaFuncAttributeMaxDynamicSharedMemorySize, SMEM_NEED);
    cudaFuncSetAttribute(k_gemm<2>, cudaFuncAttributeMaxDynamicSharedMemorySize, SMEM_NEED);

    const long NCA = (long)BB * CC * AA;

    // 1) pre-split + transposes
    k_split<<<(unsigned)(NCA / 2048), 256>>>(Va, VaH, VaL);
    k_split<<<(unsigned)(NCA / 2048), 256>>>(Vb, VbH, VbL);
    k_tsplit<<<dim3(AA / 32, CC / 32, BB), 256>>>(Va, VaTh, VaTl, CC, AA, (long)CC * AA);
    k_tsplit<<<dim3(AA / 32, CC / 32, BB), 256>>>(Vb, VbTh, VbTl, CC, AA, (long)CC * AA);
    k_tsplit<<<dim3(CC / 32, CC / 32, 1), 256>>>(Wl, WTh, WTl, CC, CC, 0);
    // 2) VbWT[n][c] = sum_d VbT[n][d] * WT[c][d]   (tcgen05, split-out)
    k_gemm<1><<<dim3(1, AA / 128, BB), 256, SMEM_NEED>>>(
        VbTh, VbTl, (long)AA * CC, CC,
        WTh, WTl, 0, CC,
        nullptr, VbWTh, VbWTl, (long)AA * CC, CC, CC);
    // 3) S GEMM fused: S[a][n] = sum_c VaT[a][c]*VbWT[n][c]; epilogue -> E/ET + sums
    k_gemm<2><<<dim3(AA / 256, AA / 128, BB), 256, SMEM_NEED>>>(
        VaTh, VaTl, (long)AA * CC, CC,
        VbWTh, VbWTl, (long)AA * CC, CC,
        nullptr, nullptr, nullptr, 0, 0, CC);
    k_combine<<<BB * AA / 256, 256>>>();
    // 4) Va_att_unscaled[c][n] = sum_a Vb[c][a] * ET[n][a]   -> out[0:B]
    k_gemm<0><<<dim3(AA / 256, CC / 128, BB), 256, SMEM_NEED>>>(
        VbH, VbL, (long)CC * AA, AA,
        ETh, ETl, (long)AA * AA, AA,
        out, nullptr, nullptr, 2L * CC * AA, AA, AA);
    // 5) Vb_att_unscaled[c][n] = sum_a Va[c][a] * E[n][a]    -> out[B:2B]
    k_gemm<0><<<dim3(AA / 256, CC / 128, BB), 256, SMEM_NEED>>>(
        VaH, VaL, (long)CC * AA, AA,
        Eh, El, (long)AA * AA, AA,
        out + (long)BB * 2 * CC * AA, nullptr, nullptr, 2L * CC * AA, AA, AA);
    // 6) gate: normalize + mask + concat
    k_gate<<<dim3(AA / 256, BB, 2), 256>>>(Wg, Va, Vb, out);
    // 7) optional tail
    long main_elems = 2L * BB * 2 * CC * AA;
    if ((long)out_size > main_elems) {
        long rem = (long)out_size - main_elems;
        k_tail<<<(unsigned)((rem + 255) / 256), 256>>>(out, main_elems, out_size, isz);
    }
}

// round 8
// speedup vs baseline: 5.4794x; 1.0017x over previous
#include <cuda_runtime.h>
#include <cuda_bf16.h>
#include <mma.h>
#include <math_constants.h>
#include <cstdint>

using namespace nvcuda;
typedef __nv_bfloat16 bf16;

#define BB 4
#define CC 256
#define AA 4096

#if defined(__CUDA_ARCH_FEAT_SM103_ALL) || defined(__CUDA_ARCH_FEAT_SM100_ALL) || \
    defined(__CUDA_ARCH_FEAT_SM101_ALL) || defined(__CUDA_ARCH_FEAT_SM110_ALL)
#define HAS_TC 1
#else
#define HAS_TC 0
#endif

// ---- device scratch ----
__device__ __align__(1024) bf16  g_Eh [(long)BB * AA * AA];    // exp(S-60) hi
__device__ __align__(1024) bf16  g_El [(long)BB * AA * AA];
__device__ __align__(1024) bf16  g_ETh[(long)BB * AA * AA];    // transposed
__device__ __align__(1024) bf16  g_ETl[(long)BB * AA * AA];
__device__ __align__(1024) bf16  g_VaH[(long)BB * CC * AA], g_VaL[(long)BB * CC * AA];
__device__ __align__(1024) bf16  g_VbH[(long)BB * CC * AA], g_VbL[(long)BB * CC * AA];
__device__ __align__(1024) bf16  g_VaTh[(long)BB * AA * CC], g_VaTl[(long)BB * AA * CC];
__device__ __align__(1024) bf16  g_VbTh[(long)BB * AA * CC], g_VbTl[(long)BB * AA * CC];
__device__ __align__(1024) bf16  g_VbWTh[(long)BB * AA * CC], g_VbWTl[(long)BB * AA * CC];
__device__ __align__(1024) bf16  g_WTh[CC * CC], g_WTl[CC * CC];
__device__ float g_rp[(long)BB * 16 * AA], g_cp[(long)BB * 32 * AA];
__device__ float g_irs[BB * AA], g_ics[BB * AA];

// ============================================================
// helpers
// ============================================================
__device__ __forceinline__ uint32_t smem_u32(const void* p) {
    uint32_t a;
    asm("{ .reg .u64 t; cvta.to.shared.u64 t, %1; cvt.u32.u64 %0, t; }" : "=r"(a) : "l"(p));
    return a;
}
__device__ __forceinline__ uint32_t cvt2(float lo, float hi) {
    uint32_t r;
    asm("cvt.rn.bf16x2.f32 %0, %1, %2;" : "=r"(r) : "f"(hi), "f"(lo));
    return r;
}
__device__ __forceinline__ void split8(const float* v, uint4& H, uint4& L) {
    uint32_t h[4], l[4];
#pragma unroll
    for (int i = 0; i < 4; i++) {
        float a = v[2 * i], b = v[2 * i + 1];
        h[i] = cvt2(a, b);
        float ar = a - __uint_as_float(h[i] << 16);
        float br = b - __uint_as_float(h[i] & 0xFFFF0000u);
        l[i] = cvt2(ar, br);
    }
    H = make_uint4(h[0], h[1], h[2], h[3]);
    L = make_uint4(l[0], l[1], l[2], l[3]);
}
__device__ __forceinline__ int sw128(int off) { return off ^ ((off >> 3) & 0x70); }

#if HAS_TC
__device__ __forceinline__ uint32_t elect_one() {
    uint32_t p;
    asm volatile("{ .reg .pred p; elect.sync _|p, 0xFFFFFFFF; selp.b32 %0, 1, 0, p; }" : "=r"(p));
    return p;
}
__device__ __forceinline__ void mbar_init(uint32_t m, uint32_t cnt) {
    asm volatile("mbarrier.init.shared.b64 [%0], %1;" :: "r"(m), "r"(cnt) : "memory");
}
__device__ __forceinline__ void mbar_wait(uint32_t m, uint32_t par) {
    asm volatile(
        "{\n\t.reg .pred P;\n\t"
        "W_%=:\n\t"
        "mbarrier.try_wait.parity.acquire.cta.shared::cta.b64 P, [%0], %1, 0x989680;\n\t"
        "@P bra.uni D_%=;\n\t"
        "bra.uni W_%=;\n\t"
        "D_%=:\n\t}"
        :: "r"(m), "r"(par) : "memory");
}
__device__ __forceinline__ void tmem_alloc(uint32_t dst, uint32_t ncols) {
    asm volatile("tcgen05.alloc.cta_group::1.sync.aligned.shared::cta.b32 [%0], %1;"
                 :: "r"(dst), "r"(ncols) : "memory");
}
__device__ __forceinline__ void tmem_dealloc(uint32_t t, uint32_t ncols) {
    asm volatile("tcgen05.relinquish_alloc_permit.cta_group::1.sync.aligned;");
    asm volatile("tcgen05.dealloc.cta_group::1.sync.aligned.b32 %0, %1;" :: "r"(t), "r"(ncols));
}
__device__ __forceinline__ void tc_commit(uint32_t mbar) {
    asm volatile("tcgen05.commit.cta_group::1.mbarrier::arrive::one.shared::cluster.b64 [%0];"
                 :: "r"(mbar) : "memory");
}
__device__ __forceinline__ void mma_f16_ss(uint32_t d, uint64_t ad, uint64_t bd,
                                           uint32_t idesc, bool accum) {
    uint32_t en = accum ? 1u : 0u;
    asm volatile(
        "{\n\t.reg .pred p;\n\tsetp.ne.u32 p, %4, 0;\n\t"
        "tcgen05.mma.cta_group::1.kind::f16 [%0], %1, %2, %3, {%5, %5, %5, %5}, p;\n\t}"
        :: "r"(d), "l"(ad), "l"(bd), "r"(idesc), "r"(en), "r"(0u) : "memory");
}
__device__ __forceinline__ void cp16(uint32_t dst, const void* src) {
    asm volatile("cp.async.cg.shared.global [%0], [%1], 16;" :: "r"(dst), "l"(src));
}
#define CP_COMMIT() asm volatile("cp.async.commit_group;" ::: "memory")
#define CP_WAIT1()  asm volatile("cp.async.wait_group 1;" ::: "memory")
#define CP_WAIT0()  asm volatile("cp.async.wait_group 0;" ::: "memory")
#define TC_FENCE_AFTER()  asm volatile("tcgen05.fence::after_thread_sync;" ::: "memory")
#define TC_FENCE_BEFORE() asm volatile("tcgen05.fence::before_thread_sync;" ::: "memory")
#define PROXY_FENCE()     asm volatile("fence.proxy.async.shared::cta;" ::: "memory")
#define TC_WAIT_LD()      asm volatile("tcgen05.wait::ld.sync.aligned;" ::: "memory")

#define TC_LD_X32(r, addr) \
    asm volatile("tcgen05.ld.sync.aligned.32x32b.x32.b32 " \
        "{%0,%1,%2,%3,%4,%5,%6,%7,%8,%9,%10,%11,%12,%13,%14,%15," \
        "%16,%17,%18,%19,%20,%21,%22,%23,%24,%25,%26,%27,%28,%29,%30,%31}, [%32];" \
        : "=r"((r)[0]),"=r"((r)[1]),"=r"((r)[2]),"=r"((r)[3]), \
          "=r"((r)[4]),"=r"((r)[5]),"=r"((r)[6]),"=r"((r)[7]), \
          "=r"((r)[8]),"=r"((r)[9]),"=r"((r)[10]),"=r"((r)[11]), \
          "=r"((r)[12]),"=r"((r)[13]),"=r"((r)[14]),"=r"((r)[15]), \
          "=r"((r)[16]),"=r"((r)[17]),"=r"((r)[18]),"=r"((r)[19]), \
          "=r"((r)[20]),"=r"((r)[21]),"=r"((r)[22]),"=r"((r)[23]), \
          "=r"((r)[24]),"=r"((r)[25]),"=r"((r)[26]),"=r"((r)[27]), \
          "=r"((r)[28]),"=r"((r)[29]),"=r"((r)[30]),"=r"((r)[31]) \
        : "r"(addr))
#endif

static constexpr uint64_t DESC_BASE_SW128 =
    (uint64_t(2) << 61) | (uint64_t(1) << 46) | (uint64_t(64) << 32) | (uint64_t(1) << 16);
__device__ __forceinline__ uint64_t mk_desc(uint32_t addr) {
    return DESC_BASE_SW128 | ((uint64_t)(addr >> 4) & 0x3FFF);
}

// ============================================================
// main GEMM: CTA tile 128m x 256n, K-stage 64, pure cp.async producers.
// C[m][n] = sum_k A[m][k]*B[n][k], A/B pre-split bf16 hi/lo.
// EPI 0: fp32 store to Cf (ldc)
// EPI 1: bf16 hi/lo split store to Coh/Col (ldc)
// EPI 2: exp(x-60) -> E/ET bf16 hi/lo + row/col partial sums
// ============================================================
#define OFF_MBAR 0
#define OFF_TMEM 32
#define STG_B (96 * 1024)
#define OFF_BUF(s) (1024 + (s) * STG_B)
#define SMEM_NEED (1024 + 2 * STG_B + 1024)
#define TLD 257

static constexpr uint32_t IDESC =
    (1u << 4) | (1u << 7) | (1u << 10) | ((256 / 8) << 17) | ((128 / 16) << 24);

// common EPI-2 tile epilogue: tile holds fp32 S values [128][TLD]
__device__ __forceinline__ void epi_exp(float* tile, int b, int m0, int n0,
                                        int bx, int by, int tid) {
    // phase a: exp + E store + row sums (thread t: row r=t>>1, half h=t&1)
    {
        const int r = tid >> 1, h = tid & 1;
        float* trow = tile + r * TLD + h * 128;
        float rsum = 0.f;
#pragma unroll
        for (int g = 0; g < 16; g++) {
            float e[8];
#pragma unroll
            for (int i = 0; i < 8; i++) {
                e[i] = __expf(trow[g * 8 + i] - 60.f);
                rsum += e[i];
                trow[g * 8 + i] = e[i];
            }
            uint4 H, L; split8(e, H, L);
            const long off = ((long)b * AA + m0 + r) * AA + n0 + h * 128 + g * 8;
            *(uint4*)(g_Eh + off) = H;
            *(uint4*)(g_El + off) = L;
        }
        rsum += __shfl_xor_sync(0xffffffffu, rsum, 1);
        if (h == 0) g_rp[((long)b * 16 + bx) * AA + m0 + r] = rsum;
    }
    __syncthreads();
    // phase b: ET store + col sums (thread t: column n=t)
    {
        const int n = tid;
        float csum = 0.f;
#pragma unroll
        for (int g = 0; g < 16; g++) {
            float e[8];
#pragma unroll
            for (int i = 0; i < 8; i++) {
                e[i] = tile[(g * 8 + i) * TLD + n];
                csum += e[i];
            }
            uint4 H, L; split8(e, H, L);
            const long off = ((long)b * AA + n0 + n) * AA + m0 + g * 8;
            *(uint4*)(g_ETh + off) = H;
            *(uint4*)(g_ETl + off) = L;
        }
        g_cp[((long)b * 32 + by) * AA + n0 + n] = csum;
    }
}

template<int EPI>
__global__ void __launch_bounds__(256) k_gemm(
    const bf16* __restrict__ Agh, const bf16* __restrict__ Agl, long sA, int lda,
    const bf16* __restrict__ Bgh, const bf16* __restrict__ Bgl, long sB, int ldb,
    float* __restrict__ Cf, bf16* __restrict__ Coh, bf16* __restrict__ Col,
    long sC, int ldc, int K)
{
    extern __shared__ char smraw[];
    char* sm = (char*)(((uintptr_t)smraw + 1023) & ~(uintptr_t)1023);
    float* tile = (float*)(sm + 1024);    // reuses pipeline buffers post-mainloop
    const int tid = threadIdx.x, wid = tid >> 5, lid = tid & 31;
    const int b = blockIdx.z;
    const int m0 = blockIdx.y * 128, n0 = blockIdx.x * 256;
    const bf16* Ah = Agh + (long)b * sA + (long)m0 * lda;
    const bf16* Al = Agl + (long)b * sA + (long)m0 * lda;
    const bf16* Bh = Bgh + (long)b * sB + (long)n0 * ldb;
    const bf16* Bl = Bgl + (long)b * sB + (long)n0 * ldb;

#if HAS_TC
    const uint32_t sb = smem_u32(sm);
    if (tid == 0) { mbar_init(sb + OFF_MBAR, 1); mbar_init(sb + OFF_MBAR + 8, 1); }
    if (wid == 0) tmem_alloc(sb + OFF_TMEM, 256);
    __syncthreads();
    uint32_t tmem;
    asm volatile("ld.shared.b32 %0, [%1];" : "=r"(tmem) : "r"(sb + OFF_TMEM));

    const int nst = K / 64;
    auto issue = [&](int s) {
        const uint32_t bufb = sb + OFF_BUF(s & 1);
        const int k0 = s * 64;
#pragma unroll
        for (int i = 0; i < 4; i++) {           // A: 128 rows x 8 chunks
            int idx = tid + i * 256;
            int r = idx >> 3, ch = idx & 7;
            uint32_t d = bufb + (uint32_t)sw128(r * 128 + ch * 16);
            const long so = (long)r * lda + k0 + ch * 8;
            cp16(d, Ah + so);
            cp16(d + 16 * 1024, Al + so);
        }
#pragma unroll
        for (int i = 0; i < 8; i++) {           // B: 256 rows x 8 chunks
            int idx = tid + i * 256;
            int r = idx >> 3, ch = idx & 7;
            uint32_t d = bufb + 32 * 1024 + (uint32_t)sw128(r * 128 + ch * 16);
            const long so = (long)r * ldb + k0 + ch * 8;
            cp16(d, Bh + so);
            cp16(d + 32 * 1024, Bl + so);
        }
        CP_COMMIT();
    };

    issue(0);
    issue(1);
    int ph0 = 0, ph1 = 0;
    for (int s = 0; s < nst; s++) {
        const int buf = s & 1;
        if (s + 1 < nst) CP_WAIT1(); else CP_WAIT0();
        PROXY_FENCE();
        __syncthreads();
        if (wid == 0 && elect_one()) {
            const uint32_t bufb = sb + OFF_BUF(buf);
            uint64_t adh = mk_desc(bufb);
            uint64_t adl = mk_desc(bufb + 16 * 1024);
            uint64_t bdh = mk_desc(bufb + 32 * 1024);
            uint64_t bdl = mk_desc(bufb + 64 * 1024);
#pragma unroll
            for (int k = 0; k < 4; k++) {
                mma_f16_ss(tmem, adh + k * 2, bdh + k * 2, IDESC, !(s == 0 && k == 0));
                mma_f16_ss(tmem, adh + k * 2, bdl + k * 2, IDESC, true);
                mma_f16_ss(tmem, adl + k * 2, bdh + k * 2, IDESC, true);
            }
            tc_commit(sb + OFF_MBAR + buf * 8);
        }
        if (s + 2 < nst) {
            if (buf == 0) { mbar_wait(sb + OFF_MBAR, ph0); ph0 ^= 1; }
            else          { mbar_wait(sb + OFF_MBAR + 8, ph1); ph1 ^= 1; }
            issue(s + 2);
        }
    }
    mbar_wait(sb + OFF_MBAR, ph0);
    mbar_wait(sb + OFF_MBAR + 8, ph1);
    TC_FENCE_AFTER();

    // ---- epilogue: 8 warps, warp w: rows=(w&3)*32+lid, col half=(w>>2)*128 ----
    {
        const int row = (wid & 3) * 32 + lid;
        const int half = wid >> 2;
#pragma unroll
        for (int ch = 0; ch < 4; ch++) {
            uint32_t r[32];
            TC_LD_X32(r, tmem + half * 128 + ch * 32);
            TC_WAIT_LD();
            if (EPI == 0) {
                float* dst = Cf + (long)b * sC + (long)(m0 + row) * ldc
                             + n0 + half * 128 + ch * 32;
#pragma unroll
                for (int j = 0; j < 32; j += 4) {
                    float4 o = make_float4(__uint_as_float(r[j]),   __uint_as_float(r[j+1]),
                                           __uint_as_float(r[j+2]), __uint_as_float(r[j+3]));
                    *(float4*)(dst + j) = o;
                }
            } else if (EPI == 1) {
                const long off = (long)b * sC + (long)(m0 + row) * ldc
                                 + n0 + half * 128 + ch * 32;
#pragma unroll
                for (int g = 0; g < 4; g++) {
                    float e[8];
#pragma unroll
                    for (int i = 0; i < 8; i++) e[i] = __uint_as_float(r[g * 8 + i]);
                    uint4 H, L; split8(e, H, L);
                    *(uint4*)(Coh + off + g * 8) = H;
                    *(uint4*)(Col + off + g * 8) = L;
                }
            } else {
                float* trow = tile + row * TLD + half * 128 + ch * 32;
#pragma unroll
                for (int j = 0; j < 32; j++) trow[j] = __uint_as_float(r[j]);
            }
        }
        TC_FENCE_BEFORE();
    }
    __syncthreads();
    if (wid == 0) tmem_dealloc(tmem, 256);
    if (EPI == 2) {
        __syncthreads();
        epi_exp(tile, b, m0, n0, blockIdx.x, blockIdx.y, tid);
    }

#else  // ---------- wmma fallback (insurance only) ----------
    float* scratch = tile + 128 * TLD;   // 8 warps x 256 floats
    const int wm = wid >> 1, wn = wid & 1;
    for (int nc = 0; nc < 2; nc++) {
        wmma::fragment<wmma::accumulator, 16, 16, 16, float> acc[2][4];
#pragma unroll
        for (int i = 0; i < 2; i++)
#pragma unroll
            for (int j = 0; j < 4; j++) wmma::fill_fragment(acc[i][j], 0.f);
        for (int k0 = 0; k0 < K; k0 += 16) {
            wmma::fragment<wmma::matrix_a, 16, 16, 16, bf16, wmma::row_major> ah, al;
            wmma::fragment<wmma::matrix_b, 16, 16, 16, bf16, wmma::col_major> bh, bl;
#pragma unroll
            for (int i = 0; i < 2; i++) {
                long offA = (long)(wm * 32 + i * 16) * lda + k0;
                wmma::load_matrix_sync(ah, Ah + offA, lda);
                wmma::load_matrix_sync(al, Al + offA, lda);
#pragma unroll
                for (int j = 0; j < 4; j++) {
                    long offB = (long)(nc * 128 + wn * 64 + j * 16) * ldb + k0;
                    wmma::load_matrix_sync(bh, Bh + offB, ldb);
                    wmma::load_matrix_sync(bl, Bl + offB, ldb);
                    wmma::mma_sync(acc[i][j], ah, bh, acc[i][j]);
                    wmma::mma_sync(acc[i][j], ah, bl, acc[i][j]);
                    wmma::mma_sync(acc[i][j], al, bh, acc[i][j]);
                }
            }
        }
        if (EPI == 0) {
#pragma unroll
            for (int i = 0; i < 2; i++)
#pragma unroll
                for (int j = 0; j < 4; j++)
                    wmma::store_matrix_sync(Cf + (long)b * sC
                                            + (long)(m0 + wm * 32 + i * 16) * ldc
                                            + n0 + nc * 128 + wn * 64 + j * 16,
                                            acc[i][j], ldc, wmma::mem_row_major);
        } else {
            // stage via per-warp scratch into tile
#pragma unroll
            for (int i = 0; i < 2; i++)
#pragma unroll
                for (int j = 0; j < 4; j++) {
                    wmma::store_matrix_sync(scratch + wid * 256, acc[i][j], 16,
                                            wmma::mem_row_major);
                    __syncwarp();
#pragma unroll
                    for (int e = 0; e < 8; e++) {
                        int idx = lid + e * 32;
                        int rr = idx >> 4, cc = idx & 15;
                        tile[(wm * 32 + i * 16 + rr) * TLD
                             + nc * 128 + wn * 64 + j * 16 + cc] =
                            scratch[wid * 256 + rr * 16 + cc];
                    }
                    __syncwarp();
                }
        }
    }
    if (EPI == 1) {
        __syncthreads();
        const int r = tid >> 1, h = tid & 1;
        const long off0 = (long)b * sC + (long)(m0 + r) * ldc + n0 + h * 128;
#pragma unroll
        for (int g = 0; g < 16; g++) {
            float e[8];
#pragma unroll
            for (int i = 0; i < 8; i++) e[i] = tile[r * TLD + h * 128 + g * 8 + i];
            uint4 H, L; split8(e, H, L);
            *(uint4*)(Coh + off0 + g * 8) = H;
            *(uint4*)(Col + off0 + g * 8) = L;
        }
    } else if (EPI == 2) {
        __syncthreads();
        epi_exp(tile, b, m0, n0, blockIdx.x, blockIdx.y, tid);
    }
#endif
}

// ---- combine partial sums -> inverse sums ----
__global__ void __launch_bounds__(256) k_combine() {
    const int idx = blockIdx.x * 256 + threadIdx.x;
    const int b = idx / AA, x = idx % AA;
    float rs = 0.f, cs = 0.f;
#pragma unroll
    for (int j = 0; j < 16; j++) rs += g_rp[((long)b * 16 + j) * AA + x];
#pragma unroll
    for (int j = 0; j < 32; j++) cs += g_cp[((long)b * 32 + j) * AA + x];
    g_irs[idx] = 1.f / rs;
    g_ics[idx] = 1.f / cs;
}

// ---- elementwise fp32 -> bf16 hi/lo split ----
__global__ void __launch_bounds__(256) k_split(const float* __restrict__ in,
                                               bf16* __restrict__ oh,
                                               bf16* __restrict__ ol) {
    const long i8 = (long)blockIdx.x * 256 + threadIdx.x;
    float v[8];
    *(float4*)(v)     = __ldg((const float4*)in + i8 * 2);
    *(float4*)(v + 4) = __ldg((const float4*)in + i8 * 2 + 1);
    uint4 H, L; split8(v, H, L);
    *(uint4*)(oh + i8 * 8) = H;
    *(uint4*)(ol + i8 * 8) = L;
}

// ---- generic transpose + split: src[b][r][c] ([R][Cc]) -> out[b][c][r] ----
__global__ void __launch_bounds__(256) k_tsplit(const float* __restrict__ src,
                                                bf16* __restrict__ oh,
                                                bf16* __restrict__ ol,
                                                int R, int Cc, long sbatch) {
    __shared__ float t[32][33];
    const long b = blockIdx.z;
    const int c0 = blockIdx.x * 32, r0 = blockIdx.y * 32;
    const float* s = src + b * sbatch;
    bf16* doh = oh + b * sbatch;
    bf16* dol = ol + b * sbatch;
    const int x = threadIdx.x & 31, y = threadIdx.x >> 5;
#pragma unroll
    for (int i = 0; i < 32; i += 8)
        t[y + i][x] = s[(long)(r0 + y + i) * Cc + c0 + x];
    __syncthreads();
#pragma unroll
    for (int p = 0; p < 2; p++) {
        int idx = threadIdx.x + p * 256;
        int orow = idx >> 4, cp = idx & 15;
        float v0 = t[cp * 2][orow], v1 = t[cp * 2 + 1][orow];
        uint32_t hp = cvt2(v0, v1);
        float q0 = v0 - __uint_as_float(hp << 16);
        float q1 = v1 - __uint_as_float(hp & 0xFFFF0000u);
        uint32_t lp = cvt2(q0, q1);
        long o = (long)(c0 + orow) * R + r0 + cp * 2;
        *(uint32_t*)(doh + o) = hp;
        *(uint32_t*)(dol + o) = lp;
    }
}

// ---- gate + normalize + in-place scale + concat-copy ----
__global__ void __launch_bounds__(256) k_gate(const float* __restrict__ Wg,
                                              const float* __restrict__ Va,
                                              const float* __restrict__ Vb,
                                              float* __restrict__ out) {
    const int side = blockIdx.z, b = blockIdx.y;
    const int n = blockIdx.x * 256 + threadIdx.x;
    const float* orig = (side ? Vb : Va) + (long)b * CC * AA + n;
    const float isn = (side ? g_irs : g_ics)[b * AA + n];
    float* att = out + ((long)(side * BB + b)) * (2L * CC * AA) + n;
    float dot = 0.f;
#pragma unroll 4
    for (int c = 0; c < CC; c++) dot = fmaf(att[(long)c * AA] * isn, Wg[c], dot);
    float mask = isn / (1.f + __expf(-dot));
#pragma unroll 4
    for (int c = 0; c < CC; c++) {
        att[(long)c * AA] *= mask;
        att[(long)(c + CC) * AA] = orig[(long)c * AA];
    }
}

__global__ void k_tail(float* __restrict__ out, long start, long total,
                       const int* __restrict__ isz) {
    long i = start + blockIdx.x * 256L + threadIdx.x;
    if (i < total) out[i] = (float)(*isz);
}

extern "C" void kernel_launch(void* const* d_in, const int* in_sizes, int n_in,
                              void* d_out, int out_size) {
    const float* Va = (const float*)d_in[0];
    const float* Vb = (const float*)d_in[1];
    const float* Wl = (const float*)d_in[2];
    const float* Wg = (const float*)d_in[3];
    const int* isz = (const int*)d_in[4];
    float* out = (float*)d_out;

    bf16 *VaH, *VaL, *VbH, *VbL, *VaTh, *VaTl, *VbTh, *VbTl;
    bf16 *VbWTh, *VbWTl, *WTh, *WTl, *Eh, *El, *ETh, *ETl;
    cudaGetSymbolAddress((void**)&VaH, g_VaH);   cudaGetSymbolAddress((void**)&VaL, g_VaL);
    cudaGetSymbolAddress((void**)&VbH, g_VbH);   cudaGetSymbolAddress((void**)&VbL, g_VbL);
    cudaGetSymbolAddress((void**)&VaTh, g_VaTh); cudaGetSymbolAddress((void**)&VaTl, g_VaTl);
    cudaGetSymbolAddress((void**)&VbTh, g_VbTh); cudaGetSymbolAddress((void**)&VbTl, g_VbTl);
    cudaGetSymbolAddress((void**)&VbWTh, g_VbWTh); cudaGetSymbolAddress((void**)&VbWTl, g_VbWTl);
    cudaGetSymbolAddress((void**)&WTh, g_WTh);   cudaGetSymbolAddress((void**)&WTl, g_WTl);
    cudaGetSymbolAddress((void**)&Eh, g_Eh);     cudaGetSymbolAddress((void**)&El, g_El);
    cudaGetSymbolAddress((void**)&ETh, g_ETh);   cudaGetSymbolAddress((void**)&ETl, g_ETl);

    cudaFuncSetAttribute(k_gemm<0>, cudaFuncAttributeMaxDynamicSharedMemorySize, SMEM_NEED);
    cudaFuncSetAttribute(k_gemm<1>, cudaFuncAttributeMaxDynamicSharedMemorySize, SMEM_NEED);
    cudaFuncSetAttribute(k_gemm<2>, cudaFuncAttributeMaxDynamicSharedMemorySize, SMEM_NEED);

    const long NCA = (long)BB * CC * AA;

    // 1) pre-split + transposes
    k_split<<<(unsigned)(NCA / 2048), 256>>>(Va, VaH, VaL);
    k_split<<<(unsigned)(NCA / 2048), 256>>>(Vb, VbH, VbL);
    k_tsplit<<<dim3(AA / 32, CC / 32, BB), 256>>>(Va, VaTh, VaTl, CC, AA, (long)CC * AA);
    k_tsplit<<<dim3(AA / 32, CC / 32, BB), 256>>>(Vb, VbTh, VbTl, CC, AA, (long)CC * AA);
    k_tsplit<<<dim3(CC / 32, CC / 32, 1), 256>>>(Wl, WTh, WTl, CC, CC, 0);
    // 2) VbWT[n][c] = sum_d VbT[n][d] * WT[c][d]   (tcgen05, split-out)
    k_gemm<1><<<dim3(1, AA / 128, BB), 256, SMEM_NEED>>>(
        VbTh, VbTl, (long)AA * CC, CC,
        WTh, WTl, 0, CC,
        nullptr, VbWTh, VbWTl, (long)AA * CC, CC, CC);
    // 3) S GEMM fused: S[a][n] = sum_c VaT[a][c]*VbWT[n][c]; epilogue -> E/ET + sums
    k_gemm<2><<<dim3(AA / 256, AA / 128, BB), 256, SMEM_NEED>>>(
        VaTh, VaTl, (long)AA * CC, CC,
        VbWTh, VbWTl, (long)AA * CC, CC,
        nullptr, nullptr, nullptr, 0, 0, CC);
    k_combine<<<BB * AA / 256, 256>>>();
    // 4) Va_att_unscaled[c][n] = sum_a Vb[c][a] * ET[n][a]   -> out[0:B]
    k_gemm<0><<<dim3(AA / 256, CC / 128, BB), 256, SMEM_NEED>>>(
        VbH, VbL, (long)CC * AA, AA,
        ETh, ETl, (long)AA * AA, AA,
        out, nullptr, nullptr, 2L * CC * AA, AA, AA);
    // 5) Vb_att_unscaled[c][n] = sum_a Va[c][a] * E[n][a]    -> out[B:2B]
    k_gemm<0><<<dim3(AA / 256, CC / 128, BB), 256, SMEM_NEED>>>(
        VaH, VaL, (long)CC * AA, AA,
        Eh, El, (long)AA * AA, AA,
        out + (long)BB * 2 * CC * AA, nullptr, nullptr, 2L * CC * AA, AA, AA);
    // 6) gate: normalize + mask + concat
    k_gate<<<dim3(AA / 256, BB, 2), 256>>>(Wg, Va, Vb, out);
    // 7) optional tail
    long main_elems = 2L * BB * 2 * CC * AA;
    if ((long)out_size > main_elems) {
        long rem = (long)out_size - main_elems;
        k_tail<<<(unsigned)((rem + 255) / 256), 256>>>(out, main_elems, out_size, isz);
    }
}

// round 9
// speedup vs baseline: 5.4841x; 1.0009x over previous
#include <cuda_runtime.h>
#include <cuda_bf16.h>
#include <mma.h>
#include <math_constants.h>
#include <cstdint>

using namespace nvcuda;
typedef __nv_bfloat16 bf16;

#define BB 4
#define CC 256
#define AA 4096

#if defined(__CUDA_ARCH_FEAT_SM103_ALL) || defined(__CUDA_ARCH_FEAT_SM100_ALL) || \
    defined(__CUDA_ARCH_FEAT_SM101_ALL) || defined(__CUDA_ARCH_FEAT_SM110_ALL)
#define HAS_TC 1
#else
#define HAS_TC 0
#endif

// ---- device scratch ----
__device__ __align__(1024) bf16  g_Eh [(long)BB * AA * AA];    // exp(S-60) hi
__device__ __align__(1024) bf16  g_El [(long)BB * AA * AA];
__device__ __align__(1024) bf16  g_ETh[(long)BB * AA * AA];    // transposed
__device__ __align__(1024) bf16  g_ETl[(long)BB * AA * AA];
__device__ __align__(1024) bf16  g_VaH[(long)BB * CC * AA], g_VaL[(long)BB * CC * AA];
__device__ __align__(1024) bf16  g_VbH[(long)BB * CC * AA], g_VbL[(long)BB * CC * AA];
__device__ __align__(1024) bf16  g_VaTh[(long)BB * AA * CC], g_VaTl[(long)BB * AA * CC];
__device__ __align__(1024) bf16  g_VbTh[(long)BB * AA * CC], g_VbTl[(long)BB * AA * CC];
__device__ __align__(1024) bf16  g_VbWTh[(long)BB * AA * CC], g_VbWTl[(long)BB * AA * CC];
__device__ __align__(1024) bf16  g_WTh[CC * CC], g_WTl[CC * CC];
__device__ float g_rp[(long)BB * 16 * AA], g_cp[(long)BB * 32 * AA];
__device__ float g_irs[BB * AA], g_ics[BB * AA];

// ============================================================
// helpers
// ============================================================
__device__ __forceinline__ uint32_t smem_u32(const void* p) {
    uint32_t a;
    asm("{ .reg .u64 t; cvta.to.shared.u64 t, %1; cvt.u32.u64 %0, t; }" : "=r"(a) : "l"(p));
    return a;
}
__device__ __forceinline__ uint32_t cvt2(float lo, float hi) {
    uint32_t r;
    asm("cvt.rn.bf16x2.f32 %0, %1, %2;" : "=r"(r) : "f"(hi), "f"(lo));
    return r;
}
__device__ __forceinline__ void split8(const float* v, uint4& H, uint4& L) {
    uint32_t h[4], l[4];
#pragma unroll
    for (int i = 0; i < 4; i++) {
        float a = v[2 * i], b = v[2 * i + 1];
        h[i] = cvt2(a, b);
        float ar = a - __uint_as_float(h[i] << 16);
        float br = b - __uint_as_float(h[i] & 0xFFFF0000u);
        l[i] = cvt2(ar, br);
    }
    H = make_uint4(h[0], h[1], h[2], h[3]);
    L = make_uint4(l[0], l[1], l[2], l[3]);
}
__device__ __forceinline__ int sw128(int off) { return off ^ ((off >> 3) & 0x70); }

#if HAS_TC
__device__ __forceinline__ uint32_t elect_one() {
    uint32_t p;
    asm volatile("{ .reg .pred p; elect.sync _|p, 0xFFFFFFFF; selp.b32 %0, 1, 0, p; }" : "=r"(p));
    return p;
}
__device__ __forceinline__ void mbar_init(uint32_t m, uint32_t cnt) {
    asm volatile("mbarrier.init.shared.b64 [%0], %1;" :: "r"(m), "r"(cnt) : "memory");
}
__device__ __forceinline__ void mbar_wait(uint32_t m, uint32_t par) {
    asm volatile(
        "{\n\t.reg .pred P;\n\t"
        "W_%=:\n\t"
        "mbarrier.try_wait.parity.acquire.cta.shared::cta.b64 P, [%0], %1, 0x989680;\n\t"
        "@P bra.uni D_%=;\n\t"
        "bra.uni W_%=;\n\t"
        "D_%=:\n\t}"
        :: "r"(m), "r"(par) : "memory");
}
__device__ __forceinline__ void tmem_alloc(uint32_t dst, uint32_t ncols) {
    asm volatile("tcgen05.alloc.cta_group::1.sync.aligned.shared::cta.b32 [%0], %1;"
                 :: "r"(dst), "r"(ncols) : "memory");
}
__device__ __forceinline__ void tmem_dealloc(uint32_t t, uint32_t ncols) {
    asm volatile("tcgen05.relinquish_alloc_permit.cta_group::1.sync.aligned;");
    asm volatile("tcgen05.dealloc.cta_group::1.sync.aligned.b32 %0, %1;" :: "r"(t), "r"(ncols));
}
__device__ __forceinline__ void tc_commit(uint32_t mbar) {
    asm volatile("tcgen05.commit.cta_group::1.mbarrier::arrive::one.shared::cluster.b64 [%0];"
                 :: "r"(mbar) : "memory");
}
__device__ __forceinline__ void mma_f16_ss(uint32_t d, uint64_t ad, uint64_t bd,
                                           uint32_t idesc, bool accum) {
    uint32_t en = accum ? 1u : 0u;
    asm volatile(
        "{\n\t.reg .pred p;\n\tsetp.ne.u32 p, %4, 0;\n\t"
        "tcgen05.mma.cta_group::1.kind::f16 [%0], %1, %2, %3, {%5, %5, %5, %5}, p;\n\t}"
        :: "r"(d), "l"(ad), "l"(bd), "r"(idesc), "r"(en), "r"(0u) : "memory");
}
__device__ __forceinline__ void cp16(uint32_t dst, const void* src) {
    asm volatile("cp.async.cg.shared.global [%0], [%1], 16;" :: "r"(dst), "l"(src));
}
#define CP_COMMIT() asm volatile("cp.async.commit_group;" ::: "memory")
#define CP_WAIT1()  asm volatile("cp.async.wait_group 1;" ::: "memory")
#define CP_WAIT0()  asm volatile("cp.async.wait_group 0;" ::: "memory")
#define TC_FENCE_AFTER()  asm volatile("tcgen05.fence::after_thread_sync;" ::: "memory")
#define TC_FENCE_BEFORE() asm volatile("tcgen05.fence::before_thread_sync;" ::: "memory")
#define PROXY_FENCE()     asm volatile("fence.proxy.async.shared::cta;" ::: "memory")
#define TC_WAIT_LD()      asm volatile("tcgen05.wait::ld.sync.aligned;" ::: "memory")

#define TC_LD_X32(r, addr) \
    asm volatile("tcgen05.ld.sync.aligned.32x32b.x32.b32 " \
        "{%0,%1,%2,%3,%4,%5,%6,%7,%8,%9,%10,%11,%12,%13,%14,%15," \
        "%16,%17,%18,%19,%20,%21,%22,%23,%24,%25,%26,%27,%28,%29,%30,%31}, [%32];" \
        : "=r"((r)[0]),"=r"((r)[1]),"=r"((r)[2]),"=r"((r)[3]), \
          "=r"((r)[4]),"=r"((r)[5]),"=r"((r)[6]),"=r"((r)[7]), \
          "=r"((r)[8]),"=r"((r)[9]),"=r"((r)[10]),"=r"((r)[11]), \
          "=r"((r)[12]),"=r"((r)[13]),"=r"((r)[14]),"=r"((r)[15]), \
          "=r"((r)[16]),"=r"((r)[17]),"=r"((r)[18]),"=r"((r)[19]), \
          "=r"((r)[20]),"=r"((r)[21]),"=r"((r)[22]),"=r"((r)[23]), \
          "=r"((r)[24]),"=r"((r)[25]),"=r"((r)[26]),"=r"((r)[27]), \
          "=r"((r)[28]),"=r"((r)[29]),"=r"((r)[30]),"=r"((r)[31]) \
        : "r"(addr))
#endif

static constexpr uint64_t DESC_BASE_SW128 =
    (uint64_t(2) << 61) | (uint64_t(1) << 46) | (uint64_t(64) << 32) | (uint64_t(1) << 16);
__device__ __forceinline__ uint64_t mk_desc(uint32_t addr) {
    return DESC_BASE_SW128 | ((uint64_t)(addr >> 4) & 0x3FFF);
}

// ============================================================
// main GEMM: CTA tile 128m x 256n, K-stage 64, pure cp.async producers.
// C[m][n] = sum_k A[m][k]*B[n][k], A/B pre-split bf16 hi/lo.
// EPI 0: fp32 store to Cf (ldc)
// EPI 1: bf16 hi/lo split store to Coh/Col (ldc)
// EPI 2: exp(x-60) -> E/ET bf16 hi/lo + row/col partial sums
// ============================================================
#define OFF_MBAR 0
#define OFF_TMEM 32
#define STG_B (96 * 1024)
#define OFF_BUF(s) (1024 + (s) * STG_B)
#define SMEM_NEED (1024 + 2 * STG_B + 1024)
#define TLD 257

static constexpr uint32_t IDESC =
    (1u << 4) | (1u << 7) | (1u << 10) | ((256 / 8) << 17) | ((128 / 16) << 24);

// common EPI-2 tile epilogue: tile holds fp32 S values [128][TLD]
__device__ __forceinline__ void epi_exp(float* tile, int b, int m0, int n0,
                                        int bx, int by, int tid) {
    // phase a: exp + E store + row sums (thread t: row r=t>>1, half h=t&1)
    {
        const int r = tid >> 1, h = tid & 1;
        float* trow = tile + r * TLD + h * 128;
        float rsum = 0.f;
#pragma unroll
        for (int g = 0; g < 16; g++) {
            float e[8];
#pragma unroll
            for (int i = 0; i < 8; i++) {
                e[i] = __expf(trow[g * 8 + i] - 60.f);
                rsum += e[i];
                trow[g * 8 + i] = e[i];
            }
            uint4 H, L; split8(e, H, L);
            const long off = ((long)b * AA + m0 + r) * AA + n0 + h * 128 + g * 8;
            *(uint4*)(g_Eh + off) = H;
            *(uint4*)(g_El + off) = L;
        }
        rsum += __shfl_xor_sync(0xffffffffu, rsum, 1);
        if (h == 0) g_rp[((long)b * 16 + bx) * AA + m0 + r] = rsum;
    }
    __syncthreads();
    // phase b: ET store + col sums (thread t: column n=t)
    {
        const int n = tid;
        float csum = 0.f;
#pragma unroll
        for (int g = 0; g < 16; g++) {
            float e[8];
#pragma unroll
            for (int i = 0; i < 8; i++) {
                e[i] = tile[(g * 8 + i) * TLD + n];
                csum += e[i];
            }
            uint4 H, L; split8(e, H, L);
            const long off = ((long)b * AA + n0 + n) * AA + m0 + g * 8;
            *(uint4*)(g_ETh + off) = H;
            *(uint4*)(g_ETl + off) = L;
        }
        g_cp[((long)b * 32 + by) * AA + n0 + n] = csum;
    }
}

template<int EPI>
__global__ void __launch_bounds__(256) k_gemm(
    const bf16* __restrict__ Agh, const bf16* __restrict__ Agl, long sA, int lda,
    const bf16* __restrict__ Bgh, const bf16* __restrict__ Bgl, long sB, int ldb,
    float* __restrict__ Cf, bf16* __restrict__ Coh, bf16* __restrict__ Col,
    long sC, int ldc, int K)
{
    extern __shared__ char smraw[];
    char* sm = (char*)(((uintptr_t)smraw + 1023) & ~(uintptr_t)1023);
    float* tile = (float*)(sm + 1024);    // reuses pipeline buffers post-mainloop
    const int tid = threadIdx.x, wid = tid >> 5, lid = tid & 31;
    const int b = blockIdx.z;
    const int m0 = blockIdx.y * 128, n0 = blockIdx.x * 256;
    const bf16* Ah = Agh + (long)b * sA + (long)m0 * lda;
    const bf16* Al = Agl + (long)b * sA + (long)m0 * lda;
    const bf16* Bh = Bgh + (long)b * sB + (long)n0 * ldb;
    const bf16* Bl = Bgl + (long)b * sB + (long)n0 * ldb;

#if HAS_TC
    const uint32_t sb = smem_u32(sm);
    if (tid == 0) { mbar_init(sb + OFF_MBAR, 1); mbar_init(sb + OFF_MBAR + 8, 1); }
    if (wid == 0) tmem_alloc(sb + OFF_TMEM, 256);
    __syncthreads();
    uint32_t tmem;
    asm volatile("ld.shared.b32 %0, [%1];" : "=r"(tmem) : "r"(sb + OFF_TMEM));

    const int nst = K / 64;
    auto issue = [&](int s) {
        const uint32_t bufb = sb + OFF_BUF(s & 1);
        const int k0 = s * 64;
#pragma unroll
        for (int i = 0; i < 4; i++) {           // A: 128 rows x 8 chunks
            int idx = tid + i * 256;
            int r = idx >> 3, ch = idx & 7;
            uint32_t d = bufb + (uint32_t)sw128(r * 128 + ch * 16);
            const long so = (long)r * lda + k0 + ch * 8;
            cp16(d, Ah + so);
            cp16(d + 16 * 1024, Al + so);
        }
#pragma unroll
        for (int i = 0; i < 8; i++) {           // B: 256 rows x 8 chunks
            int idx = tid + i * 256;
            int r = idx >> 3, ch = idx & 7;
            uint32_t d = bufb + 32 * 1024 + (uint32_t)sw128(r * 128 + ch * 16);
            const long so = (long)r * ldb + k0 + ch * 8;
            cp16(d, Bh + so);
            cp16(d + 32 * 1024, Bl + so);
        }
        CP_COMMIT();
    };

    issue(0);
    issue(1);
    int ph0 = 0, ph1 = 0;
    for (int s = 0; s < nst; s++) {
        const int buf = s & 1;
        if (s + 1 < nst) CP_WAIT1(); else CP_WAIT0();
        PROXY_FENCE();
        __syncthreads();
        if (wid == 0 && elect_one()) {
            const uint32_t bufb = sb + OFF_BUF(buf);
            uint64_t adh = mk_desc(bufb);
            uint64_t adl = mk_desc(bufb + 16 * 1024);
            uint64_t bdh = mk_desc(bufb + 32 * 1024);
            uint64_t bdl = mk_desc(bufb + 64 * 1024);
#pragma unroll
            for (int k = 0; k < 4; k++) {
                mma_f16_ss(tmem, adh + k * 2, bdh + k * 2, IDESC, !(s == 0 && k == 0));
                mma_f16_ss(tmem, adh + k * 2, bdl + k * 2, IDESC, true);
                mma_f16_ss(tmem, adl + k * 2, bdh + k * 2, IDESC, true);
            }
            tc_commit(sb + OFF_MBAR + buf * 8);
        }
        if (s + 2 < nst) {
            if (buf == 0) { mbar_wait(sb + OFF_MBAR, ph0); ph0 ^= 1; }
            else          { mbar_wait(sb + OFF_MBAR + 8, ph1); ph1 ^= 1; }
            issue(s + 2);
        }
    }
    mbar_wait(sb + OFF_MBAR, ph0);
    mbar_wait(sb + OFF_MBAR + 8, ph1);
    TC_FENCE_AFTER();

    // ---- epilogue: 8 warps, warp w: rows=(w&3)*32+lid, col half=(w>>2)*128 ----
    {
        const int row = (wid & 3) * 32 + lid;
        const int half = wid >> 2;
#pragma unroll
        for (int ch = 0; ch < 4; ch++) {
            uint32_t r[32];
            TC_LD_X32(r, tmem + half * 128 + ch * 32);
            TC_WAIT_LD();
            if (EPI == 0) {
                float* dst = Cf + (long)b * sC + (long)(m0 + row) * ldc
                             + n0 + half * 128 + ch * 32;
#pragma unroll
                for (int j = 0; j < 32; j += 4) {
                    float4 o = make_float4(__uint_as_float(r[j]),   __uint_as_float(r[j+1]),
                                           __uint_as_float(r[j+2]), __uint_as_float(r[j+3]));
                    *(float4*)(dst + j) = o;
                }
            } else if (EPI == 1) {
                const long off = (long)b * sC + (long)(m0 + row) * ldc
                                 + n0 + half * 128 + ch * 32;
#pragma unroll
                for (int g = 0; g < 4; g++) {
                    float e[8];
#pragma unroll
                    for (int i = 0; i < 8; i++) e[i] = __uint_as_float(r[g * 8 + i]);
                    uint4 H, L; split8(e, H, L);
                    *(uint4*)(Coh + off + g * 8) = H;
                    *(uint4*)(Col + off + g * 8) = L;
                }
            } else {
                float* trow = tile + row * TLD + half * 128 + ch * 32;
#pragma unroll
                for (int j = 0; j < 32; j++) trow[j] = __uint_as_float(r[j]);
            }
        }
        TC_FENCE_BEFORE();
    }
    __syncthreads();
    if (wid == 0) tmem_dealloc(tmem, 256);
    if (EPI == 2) {
        __syncthreads();
        epi_exp(tile, b, m0, n0, blockIdx.x, blockIdx.y, tid);
    }

#else  // ---------- wmma fallback (insurance only) ----------
    float* scratch = tile + 128 * TLD;   // 8 warps x 256 floats
    const int wm = wid >> 1, wn = wid & 1;
    for (int nc = 0; nc < 2; nc++) {
        wmma::fragment<wmma::accumulator, 16, 16, 16, float> acc[2][4];
#pragma unroll
        for (int i = 0; i < 2; i++)
#pragma unroll
            for (int j = 0; j < 4; j++) wmma::fill_fragment(acc[i][j], 0.f);
        for (int k0 = 0; k0 < K; k0 += 16) {
            wmma::fragment<wmma::matrix_a, 16, 16, 16, bf16, wmma::row_major> ah, al;
            wmma::fragment<wmma::matrix_b, 16, 16, 16, bf16, wmma::col_major> bh, bl;
#pragma unroll
            for (int i = 0; i < 2; i++) {
                long offA = (long)(wm * 32 + i * 16) * lda + k0;
                wmma::load_matrix_sync(ah, Ah + offA, lda);
                wmma::load_matrix_sync(al, Al + offA, lda);
#pragma unroll
                for (int j = 0; j < 4; j++) {
                    long offB = (long)(nc * 128 + wn * 64 + j * 16) * ldb + k0;
                    wmma::load_matrix_sync(bh, Bh + offB, ldb);
                    wmma::load_matrix_sync(bl, Bl + offB, ldb);
                    wmma::mma_sync(acc[i][j], ah, bh, acc[i][j]);
                    wmma::mma_sync(acc[i][j], ah, bl, acc[i][j]);
                    wmma::mma_sync(acc[i][j], al, bh, acc[i][j]);
                }
            }
        }
        if (EPI == 0) {
#pragma unroll
            for (int i = 0; i < 2; i++)
#pragma unroll
                for (int j = 0; j < 4; j++)
                    wmma::store_matrix_sync(Cf + (long)b * sC
                                            + (long)(m0 + wm * 32 + i * 16) * ldc
                                            + n0 + nc * 128 + wn * 64 + j * 16,
                                            acc[i][j], ldc, wmma::mem_row_major);
        } else {
            // stage via per-warp scratch into tile
#pragma unroll
            for (int i = 0; i < 2; i++)
#pragma unroll
                for (int j = 0; j < 4; j++) {
                    wmma::store_matrix_sync(scratch + wid * 256, acc[i][j], 16,
                                            wmma::mem_row_major);
                    __syncwarp();
#pragma unroll
                    for (int e = 0; e < 8; e++) {
                        int idx = lid + e * 32;
                        int rr = idx >> 4, cc = idx & 15;
                        tile[(wm * 32 + i * 16 + rr) * TLD
                             + nc * 128 + wn * 64 + j * 16 + cc] =
                            scratch[wid * 256 + rr * 16 + cc];
                    }
                    __syncwarp();
                }
        }
    }
    if (EPI == 1) {
        __syncthreads();
        const int r = tid >> 1, h = tid & 1;
        const long off0 = (long)b * sC + (long)(m0 + r) * ldc + n0 + h * 128;
#pragma unroll
        for (int g = 0; g < 16; g++) {
            float e[8];
#pragma unroll
            for (int i = 0; i < 8; i++) e[i] = tile[r * TLD + h * 128 + g * 8 + i];
            uint4 H, L; split8(e, H, L);
            *(uint4*)(Coh + off0 + g * 8) = H;
            *(uint4*)(Col + off0 + g * 8) = L;
        }
    } else if (EPI == 2) {
        __syncthreads();
        epi_exp(tile, b, m0, n0, blockIdx.x, blockIdx.y, tid);
    }
#endif
}

// ---- combine partial sums -> inverse sums ----
__global__ void __launch_bounds__(256) k_combine() {
    const int idx = blockIdx.x * 256 + threadIdx.x;
    const int b = idx / AA, x = idx % AA;
    float rs = 0.f, cs = 0.f;
#pragma unroll
    for (int j = 0; j < 16; j++) rs += g_rp[((long)b * 16 + j) * AA + x];
#pragma unroll
    for (int j = 0; j < 32; j++) cs += g_cp[((long)b * 32 + j) * AA + x];
    g_irs[idx] = 1.f / rs;
    g_ics[idx] = 1.f / cs;
}

// ---- elementwise fp32 -> bf16 hi/lo split ----
__global__ void __launch_bounds__(256) k_split(const float* __restrict__ in,
                                               bf16* __restrict__ oh,
                                               bf16* __restrict__ ol) {
    const long i8 = (long)blockIdx.x * 256 + threadIdx.x;
    float v[8];
    *(float4*)(v)     = __ldg((const float4*)in + i8 * 2);
    *(float4*)(v + 4) = __ldg((const float4*)in + i8 * 2 + 1);
    uint4 H, L; split8(v, H, L);
    *(uint4*)(oh + i8 * 8) = H;
    *(uint4*)(ol + i8 * 8) = L;
}

// ---- generic transpose + split: src[b][r][c] ([R][Cc]) -> out[b][c][r] ----
__global__ void __launch_bounds__(256) k_tsplit(const float* __restrict__ src,
                                                bf16* __restrict__ oh,
                                                bf16* __restrict__ ol,
                                                int R, int Cc, long sbatch) {
    __shared__ float t[32][33];
    const long b = blockIdx.z;
    const int c0 = blockIdx.x * 32, r0 = blockIdx.y * 32;
    const float* s = src + b * sbatch;
    bf16* doh = oh + b * sbatch;
    bf16* dol = ol + b * sbatch;
    const int x = threadIdx.x & 31, y = threadIdx.x >> 5;
#pragma unroll
    for (int i = 0; i < 32; i += 8)
        t[y + i][x] = s[(long)(r0 + y + i) * Cc + c0 + x];
    __syncthreads();
#pragma unroll
    for (int p = 0; p < 2; p++) {
        int idx = threadIdx.x + p * 256;
        int orow = idx >> 4, cp = idx & 15;
        float v0 = t[cp * 2][orow], v1 = t[cp * 2 + 1][orow];
        uint32_t hp = cvt2(v0, v1);
        float q0 = v0 - __uint_as_float(hp << 16);
        float q1 = v1 - __uint_as_float(hp & 0xFFFF0000u);
        uint32_t lp = cvt2(q0, q1);
        long o = (long)(c0 + orow) * R + r0 + cp * 2;
        *(uint32_t*)(doh + o) = hp;
        *(uint32_t*)(dol + o) = lp;
    }
}

// ---- gate + normalize + in-place scale + concat-copy ----
__global__ void __launch_bounds__(256) k_gate(const float* __restrict__ Wg,
                                              const float* __restrict__ Va,
                                              const float* __restrict__ Vb,
                                              float* __restrict__ out) {
    const int side = blockIdx.z, b = blockIdx.y;
    const int n = blockIdx.x * 256 + threadIdx.x;
    const float* orig = (side ? Vb : Va) + (long)b * CC * AA + n;
    const float isn = (side ? g_irs : g_ics)[b * AA + n];
    float* att = out + ((long)(side * BB + b)) * (2L * CC * AA) + n;
    float dot = 0.f;
#pragma unroll 4
    for (int c = 0; c < CC; c++) dot = fmaf(att[(long)c * AA] * isn, Wg[c], dot);
    float mask = isn / (1.f + __expf(-dot));
#pragma unroll 4
    for (int c = 0; c < CC; c++) {
        att[(long)c * AA] *= mask;
        att[(long)(c + CC) * AA] = orig[(long)c * AA];
    }
}

__global__ void k_tail(float* __restrict__ out, long start, long total,
                       const int* __restrict__ isz) {
    long i = start + blockIdx.x * 256L + threadIdx.x;
    if (i < total) out[i] = (float)(*isz);
}

extern "C" void kernel_launch(void* const* d_in, const int* in_sizes, int n_in,
                              void* d_out, int out_size) {
    const float* Va = (const float*)d_in[0];
    const float* Vb = (const float*)d_in[1];
    const float* Wl = (const float*)d_in[2];
    const float* Wg = (const float*)d_in[3];
    const int* isz = (const int*)d_in[4];
    float* out = (float*)d_out;

    bf16 *VaH, *VaL, *VbH, *VbL, *VaTh, *VaTl, *VbTh, *VbTl;
    bf16 *VbWTh, *VbWTl, *WTh, *WTl, *Eh, *El, *ETh, *ETl;
    cudaGetSymbolAddress((void**)&VaH, g_VaH);   cudaGetSymbolAddress((void**)&VaL, g_VaL);
    cudaGetSymbolAddress((void**)&VbH, g_VbH);   cudaGetSymbolAddress((void**)&VbL, g_VbL);
    cudaGetSymbolAddress((void**)&VaTh, g_VaTh); cudaGetSymbolAddress((void**)&VaTl, g_VaTl);
    cudaGetSymbolAddress((void**)&VbTh, g_VbTh); cudaGetSymbolAddress((void**)&VbTl, g_VbTl);
    cudaGetSymbolAddress((void**)&VbWTh, g_VbWTh); cudaGetSymbolAddress((void**)&VbWTl, g_VbWTl);
    cudaGetSymbolAddress((void**)&WTh, g_WTh);   cudaGetSymbolAddress((void**)&WTl, g_WTl);
    cudaGetSymbolAddress((void**)&Eh, g_Eh);     cudaGetSymbolAddress((void**)&El, g_El);
    cudaGetSymbolAddress((void**)&ETh, g_ETh);   cudaGetSymbolAddress((void**)&ETl, g_ETl);

    cudaFuncSetAttribute(k_gemm<0>, cudaFuncAttributeMaxDynamicSharedMemorySize, SMEM_NEED);
    cudaFuncSetAttribute(k_gemm<1>, cudaFuncAttributeMaxDynamicSharedMemorySize, SMEM_NEED);
    cudaFuncSetAttribute(k_gemm<2>, cudaFuncAttributeMaxDynamicSharedMemorySize, SMEM_NEED);

    const long NCA = (long)BB * CC * AA;

    // 1) pre-split + transposes
    k_split<<<(unsigned)(NCA / 2048), 256>>>(Va, VaH, VaL);
    k_split<<<(unsigned)(NCA / 2048), 256>>>(Vb, VbH, VbL);
    k_tsplit<<<dim3(AA / 32, CC / 32, BB), 256>>>(Va, VaTh, VaTl, CC, AA, (long)CC * AA);
    k_tsplit<<<dim3(AA / 32, CC / 32, BB), 256>>>(Vb, VbTh, VbTl, CC, AA, (long)CC * AA);
    k_tsplit<<<dim3(CC / 32, CC / 32, 1), 256>>>(Wl, WTh, WTl, CC, CC, 0);
    // 2) VbWT[n][c] = sum_d VbT[n][d] * WT[c][d]   (tcgen05, split-out)
    k_gemm<1><<<dim3(1, AA / 128, BB), 256, SMEM_NEED>>>(
        VbTh, VbTl, (long)AA * CC, CC,
        WTh, WTl, 0, CC,
        nullptr, VbWTh, VbWTl, (long)AA * CC, CC, CC);
    // 3) S GEMM fused: S[a][n] = sum_c VaT[a][c]*VbWT[n][c]; epilogue -> E/ET + sums
    k_gemm<2><<<dim3(AA / 256, AA / 128, BB), 256, SMEM_NEED>>>(
        VaTh, VaTl, (long)AA * CC, CC,
        VbWTh, VbWTl, (long)AA * CC, CC,
        nullptr, nullptr, nullptr, 0, 0, CC);
    k_combine<<<BB * AA / 256, 256>>>();
    // 4) Va_att_unscaled[c][n] = sum_a Vb[c][a] * ET[n][a]   -> out[0:B]
    k_gemm<0><<<dim3(AA / 256, CC / 128, BB), 256, SMEM_NEED>>>(
        VbH, VbL, (long)CC * AA, AA,
        ETh, ETl, (long)AA * AA, AA,
        out, nullptr, nullptr, 2L * CC * AA, AA, AA);
    // 5) Vb_att_unscaled[c][n] = sum_a Va[c][a] * E[n][a]    -> out[B:2B]
    k_gemm<0><<<dim3(AA / 256, CC / 128, BB), 256, SMEM_NEED>>>(
        VaH, VaL, (long)CC * AA, AA,
        Eh, El, (long)AA * AA, AA,
        out + (long)BB * 2 * CC * AA, nullptr, nullptr, 2L * CC * AA, AA, AA);
    // 6) gate: normalize + mask + concat
    k_gate<<<dim3(AA / 256, BB, 2), 256>>>(Wg, Va, Vb, out);
    // 7) optional tail
    long main_elems = 2L * BB * 2 * CC * AA;
    if ((long)out_size > main_elems) {
        long rem = (long)out_size - main_elems;
        k_tail<<<(unsigned)((rem + 255) / 256), 256>>>(out, main_elems, out_size, isz);
    }
}

// round 10
// speedup vs baseline: 5.5114x; 1.0050x over previous
#include <cuda_runtime.h>
#include <cuda_bf16.h>
#include <mma.h>
#include <math_constants.h>
#include <cstdint>

using namespace nvcuda;
typedef __nv_bfloat16 bf16;

#define BB 4
#define CC 256
#define AA 4096

#if defined(__CUDA_ARCH_FEAT_SM103_ALL) || defined(__CUDA_ARCH_FEAT_SM100_ALL) || \
    defined(__CUDA_ARCH_FEAT_SM101_ALL) || defined(__CUDA_ARCH_FEAT_SM110_ALL)
#define HAS_TC 1
#else
#define HAS_TC 0
#endif

// ---- device scratch ----
__device__ __align__(1024) bf16  g_Eh [(long)BB * AA * AA];    // exp(S-60) hi
__device__ __align__(1024) bf16  g_El [(long)BB * AA * AA];
__device__ __align__(1024) bf16  g_ETh[(long)BB * AA * AA];    // transposed
__device__ __align__(1024) bf16  g_ETl[(long)BB * AA * AA];
__device__ __align__(1024) bf16  g_VaH[(long)BB * CC * AA], g_VaL[(long)BB * CC * AA];
__device__ __align__(1024) bf16  g_VbH[(long)BB * CC * AA], g_VbL[(long)BB * CC * AA];
__device__ __align__(1024) bf16  g_VaTh[(long)BB * AA * CC], g_VaTl[(long)BB * AA * CC];
__device__ __align__(1024) bf16  g_VbTh[(long)BB * AA * CC], g_VbTl[(long)BB * AA * CC];
__device__ __align__(1024) bf16  g_VbWTh[(long)BB * AA * CC], g_VbWTl[(long)BB * AA * CC];
__device__ __align__(1024) bf16  g_WTh[CC * CC], g_WTl[CC * CC];
__device__ float g_rp[(long)BB * 16 * AA], g_cp[(long)BB * 32 * AA];
__device__ float g_irs[BB * AA], g_ics[BB * AA];

// ============================================================
// helpers
// ============================================================
__device__ __forceinline__ uint32_t smem_u32(const void* p) {
    uint32_t a;
    asm("{ .reg .u64 t; cvta.to.shared.u64 t, %1; cvt.u32.u64 %0, t; }" : "=r"(a) : "l"(p));
    return a;
}
__device__ __forceinline__ uint32_t cvt2(float lo, float hi) {
    uint32_t r;
    asm("cvt.rn.bf16x2.f32 %0, %1, %2;" : "=r"(r) : "f"(hi), "f"(lo));
    return r;
}
__device__ __forceinline__ void split8(const float* v, uint4& H, uint4& L) {
    uint32_t h[4], l[4];
#pragma unroll
    for (int i = 0; i < 4; i++) {
        float a = v[2 * i], b = v[2 * i + 1];
        h[i] = cvt2(a, b);
        float ar = a - __uint_as_float(h[i] << 16);
        float br = b - __uint_as_float(h[i] & 0xFFFF0000u);
        l[i] = cvt2(ar, br);
    }
    H = make_uint4(h[0], h[1], h[2], h[3]);
    L = make_uint4(l[0], l[1], l[2], l[3]);
}
__device__ __forceinline__ int sw128(int off) { return off ^ ((off >> 3) & 0x70); }

#if HAS_TC
__device__ __forceinline__ uint32_t elect_one() {
    uint32_t p;
    asm volatile("{ .reg .pred p; elect.sync _|p, 0xFFFFFFFF; selp.b32 %0, 1, 0, p; }" : "=r"(p));
    return p;
}
__device__ __forceinline__ void mbar_init(uint32_t m, uint32_t cnt) {
    asm volatile("mbarrier.init.shared.b64 [%0], %1;" :: "r"(m), "r"(cnt) : "memory");
}
__device__ __forceinline__ void mbar_wait(uint32_t m, uint32_t par) {
    asm volatile(
        "{\n\t.reg .pred P;\n\t"
        "W_%=:\n\t"
        "mbarrier.try_wait.parity.acquire.cta.shared::cta.b64 P, [%0], %1, 0x989680;\n\t"
        "@P bra.uni D_%=;\n\t"
        "bra.uni W_%=;\n\t"
        "D_%=:\n\t}"
        :: "r"(m), "r"(par) : "memory");
}
__device__ __forceinline__ void tmem_alloc(uint32_t dst, uint32_t ncols) {
    asm volatile("tcgen05.alloc.cta_group::1.sync.aligned.shared::cta.b32 [%0], %1;"
                 :: "r"(dst), "r"(ncols) : "memory");
}
__device__ __forceinline__ void tmem_dealloc(uint32_t t, uint32_t ncols) {
    asm volatile("tcgen05.relinquish_alloc_permit.cta_group::1.sync.aligned;");
    asm volatile("tcgen05.dealloc.cta_group::1.sync.aligned.b32 %0, %1;" :: "r"(t), "r"(ncols));
}
__device__ __forceinline__ void tc_commit(uint32_t mbar) {
    asm volatile("tcgen05.commit.cta_group::1.mbarrier::arrive::one.shared::cluster.b64 [%0];"
                 :: "r"(mbar) : "memory");
}
__device__ __forceinline__ void mma_f16_ss(uint32_t d, uint64_t ad, uint64_t bd,
                                           uint32_t idesc, bool accum) {
    uint32_t en = accum ? 1u : 0u;
    asm volatile(
        "{\n\t.reg .pred p;\n\tsetp.ne.u32 p, %4, 0;\n\t"
        "tcgen05.mma.cta_group::1.kind::f16 [%0], %1, %2, %3, {%5, %5, %5, %5}, p;\n\t}"
        :: "r"(d), "l"(ad), "l"(bd), "r"(idesc), "r"(en), "r"(0u) : "memory");
}
__device__ __forceinline__ void cp16(uint32_t dst, const void* src) {
    asm volatile("cp.async.cg.shared.global [%0], [%1], 16;" :: "r"(dst), "l"(src));
}
#define CP_COMMIT() asm volatile("cp.async.commit_group;" ::: "memory")
#define CP_WAIT1()  asm volatile("cp.async.wait_group 1;" ::: "memory")
#define CP_WAIT0()  asm volatile("cp.async.wait_group 0;" ::: "memory")
#define TC_FENCE_AFTER()  asm volatile("tcgen05.fence::after_thread_sync;" ::: "memory")
#define TC_FENCE_BEFORE() asm volatile("tcgen05.fence::before_thread_sync;" ::: "memory")
#define PROXY_FENCE()     asm volatile("fence.proxy.async.shared::cta;" ::: "memory")
#define TC_WAIT_LD()      asm volatile("tcgen05.wait::ld.sync.aligned;" ::: "memory")

#define TC_LD_X32(r, addr) \
    asm volatile("tcgen05.ld.sync.aligned.32x32b.x32.b32 " \
        "{%0,%1,%2,%3,%4,%5,%6,%7,%8,%9,%10,%11,%12,%13,%14,%15," \
        "%16,%17,%18,%19,%20,%21,%22,%23,%24,%25,%26,%27,%28,%29,%30,%31}, [%32];" \
        : "=r"((r)[0]),"=r"((r)[1]),"=r"((r)[2]),"=r"((r)[3]), \
          "=r"((r)[4]),"=r"((r)[5]),"=r"((r)[6]),"=r"((r)[7]), \
          "=r"((r)[8]),"=r"((r)[9]),"=r"((r)[10]),"=r"((r)[11]), \
          "=r"((r)[12]),"=r"((r)[13]),"=r"((r)[14]),"=r"((r)[15]), \
          "=r"((r)[16]),"=r"((r)[17]),"=r"((r)[18]),"=r"((r)[19]), \
          "=r"((r)[20]),"=r"((r)[21]),"=r"((r)[22]),"=r"((r)[23]), \
          "=r"((r)[24]),"=r"((r)[25]),"=r"((r)[26]),"=r"((r)[27]), \
          "=r"((r)[28]),"=r"((r)[29]),"=r"((r)[30]),"=r"((r)[31]) \
        : "r"(addr))
#endif

static constexpr uint64_t DESC_BASE_SW128 =
    (uint64_t(2) << 61) | (uint64_t(1) << 46) | (uint64_t(64) << 32) | (uint64_t(1) << 16);
__device__ __forceinline__ uint64_t mk_desc(uint32_t addr) {
    return DESC_BASE_SW128 | ((uint64_t)(addr >> 4) & 0x3FFF);
}

// ============================================================
// main GEMM: CTA tile 128m x 256n, K-stage 64, pure cp.async producers.
// C[m][n] = sum_k A[m][k]*B[n][k], A/B pre-split bf16 hi/lo.
// EPI 0: fp32 store to Cf (ldc)
// EPI 1: bf16 hi/lo split store to Coh/Col (ldc)
// EPI 2: exp(x-60) -> E/ET bf16 hi/lo + row/col partial sums
// ============================================================
#define OFF_MBAR 0
#define OFF_TMEM 32
#define STG_B (96 * 1024)
#define OFF_BUF(s) (1024 + (s) * STG_B)
#define SMEM_NEED (1024 + 2 * STG_B + 1024)
#define TLD 257

static constexpr uint32_t IDESC =
    (1u << 4) | (1u << 7) | (1u << 10) | ((256 / 8) << 17) | ((128 / 16) << 24);

// common EPI-2 tile epilogue: tile holds fp32 S values [128][TLD]
__device__ __forceinline__ void epi_exp(float* tile, int b, int m0, int n0,
                                        int bx, int by, int tid) {
    // phase a: exp + E store + row sums (thread t: row r=t>>1, half h=t&1)
    {
        const int r = tid >> 1, h = tid & 1;
        float* trow = tile + r * TLD + h * 128;
        float rsum = 0.f;
#pragma unroll
        for (int g = 0; g < 16; g++) {
            float e[8];
#pragma unroll
            for (int i = 0; i < 8; i++) {
                e[i] = __expf(trow[g * 8 + i] - 60.f);
                rsum += e[i];
                trow[g * 8 + i] = e[i];
            }
            uint4 H, L; split8(e, H, L);
            const long off = ((long)b * AA + m0 + r) * AA + n0 + h * 128 + g * 8;
            *(uint4*)(g_Eh + off) = H;
            *(uint4*)(g_El + off) = L;
        }
        rsum += __shfl_xor_sync(0xffffffffu, rsum, 1);
        if (h == 0) g_rp[((long)b * 16 + bx) * AA + m0 + r] = rsum;
    }
    __syncthreads();
    // phase b: ET store + col sums (thread t: column n=t)
    {
        const int n = tid;
        float csum = 0.f;
#pragma unroll
        for (int g = 0; g < 16; g++) {
            float e[8];
#pragma unroll
            for (int i = 0; i < 8; i++) {
                e[i] = tile[(g * 8 + i) * TLD + n];
                csum += e[i];
            }
            uint4 H, L; split8(e, H, L);
            const long off = ((long)b * AA + n0 + n) * AA + m0 + g * 8;
            *(uint4*)(g_ETh + off) = H;
            *(uint4*)(g_ETl + off) = L;
        }
        g_cp[((long)b * 32 + by) * AA + n0 + n] = csum;
    }
}

template<int EPI>
__global__ void __launch_bounds__(256) k_gemm(
    const bf16* __restrict__ Agh, const bf16* __restrict__ Agl, long sA, int lda,
    const bf16* __restrict__ Bgh, const bf16* __restrict__ Bgl, long sB, int ldb,
    float* __restrict__ Cf, bf16* __restrict__ Coh, bf16* __restrict__ Col,
    long sC, int ldc, int K)
{
    extern __shared__ char smraw[];
    char* sm = (char*)(((uintptr_t)smraw + 1023) & ~(uintptr_t)1023);
    float* tile = (float*)(sm + 1024);    // reuses pipeline buffers post-mainloop
    const int tid = threadIdx.x, wid = tid >> 5, lid = tid & 31;
    const int b = blockIdx.z;
    const int m0 = blockIdx.y * 128, n0 = blockIdx.x * 256;
    const bf16* Ah = Agh + (long)b * sA + (long)m0 * lda;
    const bf16* Al = Agl + (long)b * sA + (long)m0 * lda;
    const bf16* Bh = Bgh + (long)b * sB + (long)n0 * ldb;
    const bf16* Bl = Bgl + (long)b * sB + (long)n0 * ldb;

#if HAS_TC
    const uint32_t sb = smem_u32(sm);
    if (tid == 0) { mbar_init(sb + OFF_MBAR, 1); mbar_init(sb + OFF_MBAR + 8, 1); }
    if (wid == 0) tmem_alloc(sb + OFF_TMEM, 256);
    __syncthreads();
    uint32_t tmem;
    asm volatile("ld.shared.b32 %0, [%1];" : "=r"(tmem) : "r"(sb + OFF_TMEM));

    const int nst = K / 64;
    auto issue = [&](int s) {
        const uint32_t bufb = sb + OFF_BUF(s & 1);
        const int k0 = s * 64;
#pragma unroll
        for (int i = 0; i < 4; i++) {           // A: 128 rows x 8 chunks
            int idx = tid + i * 256;
            int r = idx >> 3, ch = idx & 7;
            uint32_t d = bufb + (uint32_t)sw128(r * 128 + ch * 16);
            const long so = (long)r * lda + k0 + ch * 8;
            cp16(d, Ah + so);
            cp16(d + 16 * 1024, Al + so);
        }
#pragma unroll
        for (int i = 0; i < 8; i++) {           // B: 256 rows x 8 chunks
            int idx = tid + i * 256;
            int r = idx >> 3, ch = idx & 7;
            uint32_t d = bufb + 32 * 1024 + (uint32_t)sw128(r * 128 + ch * 16);
            const long so = (long)r * ldb + k0 + ch * 8;
            cp16(d, Bh + so);
            cp16(d + 32 * 1024, Bl + so);
        }
        CP_COMMIT();
    };

    issue(0);
    issue(1);
    int ph0 = 0, ph1 = 0;
    for (int s = 0; s < nst; s++) {
        const int buf = s & 1;
        if (s + 1 < nst) CP_WAIT1(); else CP_WAIT0();
        PROXY_FENCE();
        __syncthreads();
        if (wid == 0 && elect_one()) {
            const uint32_t bufb = sb + OFF_BUF(buf);
            uint64_t adh = mk_desc(bufb);
            uint64_t adl = mk_desc(bufb + 16 * 1024);
            uint64_t bdh = mk_desc(bufb + 32 * 1024);
            uint64_t bdl = mk_desc(bufb + 64 * 1024);
#pragma unroll
            for (int k = 0; k < 4; k++) {
                mma_f16_ss(tmem, adh + k * 2, bdh + k * 2, IDESC, !(s == 0 && k == 0));
                mma_f16_ss(tmem, adh + k * 2, bdl + k * 2, IDESC, true);
                mma_f16_ss(tmem, adl + k * 2, bdh + k * 2, IDESC, true);
            }
            tc_commit(sb + OFF_MBAR + buf * 8);
        }
        if (s + 2 < nst) {
            if (buf == 0) { mbar_wait(sb + OFF_MBAR, ph0); ph0 ^= 1; }
            else          { mbar_wait(sb + OFF_MBAR + 8, ph1); ph1 ^= 1; }
            issue(s + 2);
        }
    }
    mbar_wait(sb + OFF_MBAR, ph0);
    mbar_wait(sb + OFF_MBAR + 8, ph1);
    TC_FENCE_AFTER();

    // ---- epilogue: 8 warps, warp w: rows=(w&3)*32+lid, col half=(w>>2)*128 ----
    {
        const int row = (wid & 3) * 32 + lid;
        const int half = wid >> 2;
#pragma unroll
        for (int ch = 0; ch < 4; ch++) {
            uint32_t r[32];
            TC_LD_X32(r, tmem + half * 128 + ch * 32);
            TC_WAIT_LD();
            if (EPI == 0) {
                float* dst = Cf + (long)b * sC + (long)(m0 + row) * ldc
                             + n0 + half * 128 + ch * 32;
#pragma unroll
                for (int j = 0; j < 32; j += 4) {
                    float4 o = make_float4(__uint_as_float(r[j]),   __uint_as_float(r[j+1]),
                                           __uint_as_float(r[j+2]), __uint_as_float(r[j+3]));
                    *(float4*)(dst + j) = o;
                }
            } else if (EPI == 1) {
                const long off = (long)b * sC + (long)(m0 + row) * ldc
                                 + n0 + half * 128 + ch * 32;
#pragma unroll
                for (int g = 0; g < 4; g++) {
                    float e[8];
#pragma unroll
                    for (int i = 0; i < 8; i++) e[i] = __uint_as_float(r[g * 8 + i]);
                    uint4 H, L; split8(e, H, L);
                    *(uint4*)(Coh + off + g * 8) = H;
                    *(uint4*)(Col + off + g * 8) = L;
                }
            } else {
                float* trow = tile + row * TLD + half * 128 + ch * 32;
#pragma unroll
                for (int j = 0; j < 32; j++) trow[j] = __uint_as_float(r[j]);
            }
        }
        TC_FENCE_BEFORE();
    }
    __syncthreads();
    if (wid == 0) tmem_dealloc(tmem, 256);
    if (EPI == 2) {
        __syncthreads();
        epi_exp(tile, b, m0, n0, blockIdx.x, blockIdx.y, tid);
    }

#else  // ---------- wmma fallback (insurance only) ----------
    float* scratch = tile + 128 * TLD;   // 8 warps x 256 floats
    const int wm = wid >> 1, wn = wid & 1;
    for (int nc = 0; nc < 2; nc++) {
        wmma::fragment<wmma::accumulator, 16, 16, 16, float> acc[2][4];
#pragma unroll
        for (int i = 0; i < 2; i++)
#pragma unroll
            for (int j = 0; j < 4; j++) wmma::fill_fragment(acc[i][j], 0.f);
        for (int k0 = 0; k0 < K; k0 += 16) {
            wmma::fragment<wmma::matrix_a, 16, 16, 16, bf16, wmma::row_major> ah, al;
            wmma::fragment<wmma::matrix_b, 16, 16, 16, bf16, wmma::col_major> bh, bl;
#pragma unroll
            for (int i = 0; i < 2; i++) {
                long offA = (long)(wm * 32 + i * 16) * lda + k0;
                wmma::load_matrix_sync(ah, Ah + offA, lda);
                wmma::load_matrix_sync(al, Al + offA, lda);
#pragma unroll
                for (int j = 0; j < 4; j++) {
                    long offB = (long)(nc * 128 + wn * 64 + j * 16) * ldb + k0;
                    wmma::load_matrix_sync(bh, Bh + offB, ldb);
                    wmma::load_matrix_sync(bl, Bl + offB, ldb);
                    wmma::mma_sync(acc[i][j], ah, bh, acc[i][j]);
                    wmma::mma_sync(acc[i][j], ah, bl, acc[i][j]);
                    wmma::mma_sync(acc[i][j], al, bh, acc[i][j]);
                }
            }
        }
        if (EPI == 0) {
#pragma unroll
            for (int i = 0; i < 2; i++)
#pragma unroll
                for (int j = 0; j < 4; j++)
                    wmma::store_matrix_sync(Cf + (long)b * sC
                                            + (long)(m0 + wm * 32 + i * 16) * ldc
                                            + n0 + nc * 128 + wn * 64 + j * 16,
                                            acc[i][j], ldc, wmma::mem_row_major);
        } else {
            // stage via per-warp scratch into tile
#pragma unroll
            for (int i = 0; i < 2; i++)
#pragma unroll
                for (int j = 0; j < 4; j++) {
                    wmma::store_matrix_sync(scratch + wid * 256, acc[i][j], 16,
                                            wmma::mem_row_major);
                    __syncwarp();
#pragma unroll
                    for (int e = 0; e < 8; e++) {
                        int idx = lid + e * 32;
                        int rr = idx >> 4, cc = idx & 15;
                        tile[(wm * 32 + i * 16 + rr) * TLD
                             + nc * 128 + wn * 64 + j * 16 + cc] =
                            scratch[wid * 256 + rr * 16 + cc];
                    }
                    __syncwarp();
                }
        }
    }
    if (EPI == 1) {
        __syncthreads();
        const int r = tid >> 1, h = tid & 1;
        const long off0 = (long)b * sC + (long)(m0 + r) * ldc + n0 + h * 128;
#pragma unroll
        for (int g = 0; g < 16; g++) {
            float e[8];
#pragma unroll
            for (int i = 0; i < 8; i++) e[i] = tile[r * TLD + h * 128 + g * 8 + i];
            uint4 H, L; split8(e, H, L);
            *(uint4*)(Coh + off0 + g * 8) = H;
            *(uint4*)(Col + off0 + g * 8) = L;
        }
    } else if (EPI == 2) {
        __syncthreads();
        epi_exp(tile, b, m0, n0, blockIdx.x, blockIdx.y, tid);
    }
#endif
}

// ---- combine partial sums -> inverse sums ----
__global__ void __launch_bounds__(256) k_combine() {
    const int idx = blockIdx.x * 256 + threadIdx.x;
    const int b = idx / AA, x = idx % AA;
    float rs = 0.f, cs = 0.f;
#pragma unroll
    for (int j = 0; j < 16; j++) rs += g_rp[((long)b * 16 + j) * AA + x];
#pragma unroll
    for (int j = 0; j < 32; j++) cs += g_cp[((long)b * 32 + j) * AA + x];
    g_irs[idx] = 1.f / rs;
    g_ics[idx] = 1.f / cs;
}

// ---- elementwise fp32 -> bf16 hi/lo split ----
__global__ void __launch_bounds__(256) k_split(const float* __restrict__ in,
                                               bf16* __restrict__ oh,
                                               bf16* __restrict__ ol) {
    const long i8 = (long)blockIdx.x * 256 + threadIdx.x;
    float v[8];
    *(float4*)(v)     = __ldg((const float4*)in + i8 * 2);
    *(float4*)(v + 4) = __ldg((const float4*)in + i8 * 2 + 1);
    uint4 H, L; split8(v, H, L);
    *(uint4*)(oh + i8 * 8) = H;
    *(uint4*)(ol + i8 * 8) = L;
}

// ---- generic transpose + split: src[b][r][c] ([R][Cc]) -> out[b][c][r] ----
__global__ void __launch_bounds__(256) k_tsplit(const float* __restrict__ src,
                                                bf16* __restrict__ oh,
                                                bf16* __restrict__ ol,
                                                int R, int Cc, long sbatch) {
    __shared__ float t[32][33];
    const long b = blockIdx.z;
    const int c0 = blockIdx.x * 32, r0 = blockIdx.y * 32;
    const float* s = src + b * sbatch;
    bf16* doh = oh + b * sbatch;
    bf16* dol = ol + b * sbatch;
    const int x = threadIdx.x & 31, y = threadIdx.x >> 5;
#pragma unroll
    for (int i = 0; i < 32; i += 8)
        t[y + i][x] = s[(long)(r0 + y + i) * Cc + c0 + x];
    __syncthreads();
#pragma unroll
    for (int p = 0; p < 2; p++) {
        int idx = threadIdx.x + p * 256;
        int orow = idx >> 4, cp = idx & 15;
        float v0 = t[cp * 2][orow], v1 = t[cp * 2 + 1][orow];
        uint32_t hp = cvt2(v0, v1);
        float q0 = v0 - __uint_as_float(hp << 16);
        float q1 = v1 - __uint_as_float(hp & 0xFFFF0000u);
        uint32_t lp = cvt2(q0, q1);
        long o = (long)(c0 + orow) * R + r0 + cp * 2;
        *(uint32_t*)(doh + o) = hp;
        *(uint32_t*)(dol + o) = lp;
    }
}

// ---- gate + normalize + in-place scale + concat-copy ----
__global__ void __launch_bounds__(256) k_gate(const float* __restrict__ Wg,
                                              const float* __restrict__ Va,
                                              const float* __restrict__ Vb,
                                              float* __restrict__ out) {
    const int side = blockIdx.z, b = blockIdx.y;
    const int n = blockIdx.x * 256 + threadIdx.x;
    const float* orig = (side ? Vb : Va) + (long)b * CC * AA + n;
    const float isn = (side ? g_irs : g_ics)[b * AA + n];
    float* att = out + ((long)(side * BB + b)) * (2L * CC * AA) + n;
    float dot = 0.f;
#pragma unroll 4
    for (int c = 0; c < CC; c++) dot = fmaf(att[(long)c * AA] * isn, Wg[c], dot);
    float mask = isn / (1.f + __expf(-dot));
#pragma unroll 4
    for (int c = 0; c < CC; c++) {
        att[(long)c * AA] *= mask;
        att[(long)(c + CC) * AA] = orig[(long)c * AA];
    }
}

__global__ void k_tail(float* __restrict__ out, long start, long total,
                       const int* __restrict__ isz) {
    long i = start + blockIdx.x * 256L + threadIdx.x;
    if (i < total) out[i] = (float)(*isz);
}

extern "C" void kernel_launch(void* const* d_in, const int* in_sizes, int n_in,
                              void* d_out, int out_size) {
    const float* Va = (const float*)d_in[0];
    const float* Vb = (const float*)d_in[1];
    const float* Wl = (const float*)d_in[2];
    const float* Wg = (const float*)d_in[3];
    const int* isz = (const int*)d_in[4];
    float* out = (float*)d_out;

    bf16 *VaH, *VaL, *VbH, *VbL, *VaTh, *VaTl, *VbTh, *VbTl;
    bf16 *VbWTh, *VbWTl, *WTh, *WTl, *Eh, *El, *ETh, *ETl;
    cudaGetSymbolAddress((void**)&VaH, g_VaH);   cudaGetSymbolAddress((void**)&VaL, g_VaL);
    cudaGetSymbolAddress((void**)&VbH, g_VbH);   cudaGetSymbolAddress((void**)&VbL, g_VbL);
    cudaGetSymbolAddress((void**)&VaTh, g_VaTh); cudaGetSymbolAddress((void**)&VaTl, g_VaTl);
    cudaGetSymbolAddress((void**)&VbTh, g_VbTh); cudaGetSymbolAddress((void**)&VbTl, g_VbTl);
    cudaGetSymbolAddress((void**)&VbWTh, g_VbWTh); cudaGetSymbolAddress((void**)&VbWTl, g_VbWTl);
    cudaGetSymbolAddress((void**)&WTh, g_WTh);   cudaGetSymbolAddress((void**)&WTl, g_WTl);
    cudaGetSymbolAddress((void**)&Eh, g_Eh);     cudaGetSymbolAddress((void**)&El, g_El);
    cudaGetSymbolAddress((void**)&ETh, g_ETh);   cudaGetSymbolAddress((void**)&ETl, g_ETl);

    cudaFuncSetAttribute(k_gemm<0>, cudaFuncAttributeMaxDynamicSharedMemorySize, SMEM_NEED);
    cudaFuncSetAttribute(k_gemm<1>, cudaFuncAttributeMaxDynamicSharedMemorySize, SMEM_NEED);
    cudaFuncSetAttribute(k_gemm<2>, cudaFuncAttributeMaxDynamicSharedMemorySize, SMEM_NEED);

    const long NCA = (long)BB * CC * AA;

    // 1) pre-split + transposes
    k_split<<<(unsigned)(NCA / 2048), 256>>>(Va, VaH, VaL);
    k_split<<<(unsigned)(NCA / 2048), 256>>>(Vb, VbH, VbL);
    k_tsplit<<<dim3(AA / 32, CC / 32, BB), 256>>>(Va, VaTh, VaTl, CC, AA, (long)CC * AA);
    k_tsplit<<<dim3(AA / 32, CC / 32, BB), 256>>>(Vb, VbTh, VbTl, CC, AA, (long)CC * AA);
    k_tsplit<<<dim3(CC / 32, CC / 32, 1), 256>>>(Wl, WTh, WTl, CC, CC, 0);
    // 2) VbWT[n][c] = sum_d VbT[n][d] * WT[c][d]   (tcgen05, split-out)
    k_gemm<1><<<dim3(1, AA / 128, BB), 256, SMEM_NEED>>>(
        VbTh, VbTl, (long)AA * CC, CC,
        WTh, WTl, 0, CC,
        nullptr, VbWTh, VbWTl, (long)AA * CC, CC, CC);
    // 3) S GEMM fused: S[a][n] = sum_c VaT[a][c]*VbWT[n][c]; epilogue -> E/ET + sums
    k_gemm<2><<<dim3(AA / 256, AA / 128, BB), 256, SMEM_NEED>>>(
        VaTh, VaTl, (long)AA * CC, CC,
        VbWTh, VbWTl, (long)AA * CC, CC,
        nullptr, nullptr, nullptr, 0, 0, CC);
    k_combine<<<BB * AA / 256, 256>>>();
    // 4) Va_att_unscaled[c][n] = sum_a Vb[c][a] * ET[n][a]   -> out[0:B]
    k_gemm<0><<<dim3(AA / 256, CC / 128, BB), 256, SMEM_NEED>>>(
        VbH, VbL, (long)CC * AA, AA,
        ETh, ETl, (long)AA * AA, AA,
        out, nullptr, nullptr, 2L * CC * AA, AA, AA);
    // 5) Vb_att_unscaled[c][n] = sum_a Va[c][a] * E[n][a]    -> out[B:2B]
    k_gemm<0><<<dim3(AA / 256, CC / 128, BB), 256, SMEM_NEED>>>(
        VaH, VaL, (long)CC * AA, AA,
        Eh, El, (long)AA * AA, AA,
        out + (long)BB * 2 * CC * AA, nullptr, nullptr, 2L * CC * AA, AA, AA);
    // 6) gate: normalize + mask + concat
    k_gate<<<dim3(AA / 256, BB, 2), 256>>>(Wg, Va, Vb, out);
    // 7) optional tail
    long main_elems = 2L * BB * 2 * CC * AA;
    if ((long)out_size > main_elems) {
        long rem = (long)out_size - main_elems;
        k_tail<<<(unsigned)((rem + 255) / 256), 256>>>(out, main_elems, out_size, isz);
    }
}